// round 4
// baseline (speedup 1.0000x reference)
#include <cuda_runtime.h>
#include <math.h>

// Problem constants
// B=4, C=64, H=W=256, N_SPLIT=4 (T=16), RED_FC=32, OUT_NC=32, K=3, FMN1=FMN2=2048
// wsize = 32*64*9 = 18432, wb row = 18464

typedef unsigned long long ull;

// ---------------- scratch (device globals; no runtime allocation) ----------
__device__ float g_h[4*64*256*256];       // conv1 output (leaky-relu'd)
__device__ float g_adap[4*256*256];       // tanh(conv2)
__device__ float g_gram[64*1024];         // pooled grams
__device__ float g_fc1[64*2048];
__device__ float g_fc2[64*2048];
__device__ float g_wb[64*18464];          // dynamic weights + bias
__device__ float g_part[9453568];         // split-K partials (max: 8 x 64 x 18464)

// ---------------- f32x2 helpers (sm_103a packed fp32 FMA) ------------------
__device__ __forceinline__ ull pack2(float lo, float hi) {
    ull d;
    asm("mov.b64 %0, {%1, %2};" : "=l"(d) : "f"(lo), "f"(hi));
    return d;
}
__device__ __forceinline__ void unpack2(ull d, float& lo, float& hi) {
    asm("mov.b64 {%0, %1}, %2;" : "=f"(lo), "=f"(hi) : "l"(d));
}
__device__ __forceinline__ ull fma2(ull a, ull b, ull c) {
    ull d;
    asm("fma.rn.f32x2 %0, %1, %2, %3;" : "=l"(d) : "l"(a), "l"(b), "l"(c));
    return d;
}

// ---------------- patch pipeline helpers -----------------------------------
// 34x34 halo patch, 256 threads, 5 elements per thread.
__device__ __forceinline__ void ldpatch(const float* __restrict__ fp,
                                        int y0, int x0, int tid, float* pre)
{
#pragma unroll
    for (int r = 0; r < 5; r++) {
        int i = tid + 256*r;
        float v = 0.f;
        if (i < 1156) {
            int py = i / 34, px = i - py*34;
            int gy = y0 - 1 + py, gx = x0 - 1 + px;
            if ((unsigned)gy < 256u && (unsigned)gx < 256u) v = __ldg(&fp[gy*256 + gx]);
        }
        pre[r] = v;
    }
}
__device__ __forceinline__ void stpatch(float (*buf)[35], int tid, const float* pre)
{
#pragma unroll
    for (int r = 0; r < 5; r++) {
        int i = tid + 256*r;
        if (i < 1156) buf[i / 34][i - (i/34)*34] = pre[r];
    }
}

// ---------------- conv1: 64->64 3x3 pad1 + leaky relu ----------------------
// grid (8,8,32): x-tile, y-tile, z = b*8 + ocg (8 output chans per block)
// block (32,8): each thread computes 4 pixels. Double-buffered patch, 1 bar/ic.
__global__ __launch_bounds__(256) void conv1_kernel(
    const float* __restrict__ feat,
    const float* __restrict__ rw1,
    const float* __restrict__ rb1)
{
    __shared__ ull wsm[8*64*9];          // splatted (w,w) pairs, 36 KB
    __shared__ float patch[2][34][35];

    int b = blockIdx.z >> 3, ocg = blockIdx.z & 7;
    int x0 = blockIdx.x * 32, y0 = blockIdx.y * 32;
    int tx = threadIdx.x, ty = threadIdx.y;
    int tid = ty * 32 + tx;

    const float* wbase = rw1 + ocg * (8*64*9);
    for (int i = tid; i < 8*64*9; i += 256) {
        float w = wbase[i];
        wsm[i] = pack2(w, w);
    }

    const float* fbase = feat + (size_t)(b*64) * 65536;
    float pre[5];
    ldpatch(fbase, y0, x0, tid, pre);
    stpatch(patch[0], tid, pre);

    ull accA[8], accB[8];
#pragma unroll
    for (int o = 0; o < 8; o++) { accA[o] = 0ull; accB[o] = 0ull; }

    __syncthreads();

    for (int ic = 0; ic < 64; ic++) {
        int p = ic & 1;
        if (ic < 63) ldpatch(fbase + (size_t)(ic+1)*65536, y0, x0, tid, pre);

        ull PA[9], PB[9];
#pragma unroll
        for (int dy = 0; dy < 3; dy++)
#pragma unroll
            for (int dx = 0; dx < 3; dx++) {
                int k = dy*3 + dx;
                PA[k] = pack2(patch[p][ty + dy][tx + dx],      patch[p][ty + 8  + dy][tx + dx]);
                PB[k] = pack2(patch[p][ty + 16 + dy][tx + dx], patch[p][ty + 24 + dy][tx + dx]);
            }
#pragma unroll
        for (int o = 0; o < 8; o++) {
            const ull* w = &wsm[(o*64 + ic) * 9];
#pragma unroll
            for (int k = 0; k < 9; k++) {
                ull w2 = w[k];
                accA[o] = fma2(PA[k], w2, accA[o]);
                accB[o] = fma2(PB[k], w2, accB[o]);
            }
        }
        if (ic < 63) stpatch(patch[p ^ 1], tid, pre);
        __syncthreads();
    }

#pragma unroll
    for (int o = 0; o < 8; o++) {
        int oc = ocg*8 + o;
        float bias = rb1[oc];
        float v0, v1, v2, v3;
        unpack2(accA[o], v0, v1);
        unpack2(accB[o], v2, v3);
        float vv[4] = {v0, v1, v2, v3};
        size_t base = (size_t)(b*64 + oc) * 65536;
#pragma unroll
        for (int k = 0; k < 4; k++) {
            float v = vv[k] + bias;
            v = (v >= 0.f) ? v : 0.2f * v;
            g_h[base + (size_t)(y0 + ty + 8*k) * 256 + x0 + tx] = v;
        }
    }
}

// ---------------- conv2: 64->1 3x3 pad1 + tanh -----------------------------
__global__ __launch_bounds__(256) void conv2_kernel(
    const float* __restrict__ rw2, const float* __restrict__ rb2)
{
    __shared__ float wsm[576];
    __shared__ float patch[2][34][35];
    int b = blockIdx.z;
    int x0 = blockIdx.x * 32, y0 = blockIdx.y * 32;
    int tx = threadIdx.x, ty = threadIdx.y;
    int tid = ty * 32 + tx;
    for (int i = tid; i < 576; i += 256) wsm[i] = rw2[i];
    float acc[4] = {0.f, 0.f, 0.f, 0.f};

    const float* fbase = g_h + (size_t)(b*64) * 65536;
    float pre[5];
    ldpatch(fbase, y0, x0, tid, pre);
    stpatch(patch[0], tid, pre);
    __syncthreads();

    for (int ic = 0; ic < 64; ic++) {
        int p = ic & 1;
        if (ic < 63) ldpatch(fbase + (size_t)(ic+1)*65536, y0, x0, tid, pre);
#pragma unroll
        for (int k = 0; k < 4; k++) {
            float s = acc[k];
#pragma unroll
            for (int dy = 0; dy < 3; dy++)
#pragma unroll
                for (int dx = 0; dx < 3; dx++)
                    s += patch[p][ty + 8*k + dy][tx + dx] * wsm[ic*9 + dy*3 + dx];
            acc[k] = s;
        }
        if (ic < 63) stpatch(patch[p ^ 1], tid, pre);
        __syncthreads();
    }
    float bias = rb2[0];
#pragma unroll
    for (int k = 0; k < 4; k++)
        g_adap[((size_t)b*256 + y0 + ty + 8*k) * 256 + x0 + tx] = tanhf(acc[k] + bias);
}

// ---------------- adaptive pool per tile -> gram ---------------------------
__global__ void pool_kernel()
{
    __shared__ float win[66][67];
    int r = blockIdx.x;
    int b = r >> 4, t = r & 15;
    int ti = t >> 2, tj = t & 3;
    int tid = threadIdx.x;
    for (int i = tid; i < 66*66; i += 256) {
        int h = i / 66, w = i % 66;
        int gy = ti*64 - 1 + h, gx = tj*64 - 1 + w;
        float v = 0.f;
        if ((unsigned)gy < 256u && (unsigned)gx < 256u)
            v = g_adap[((size_t)b*256 + gy) * 256 + gx];
        win[h][w] = v;
    }
    __syncthreads();
    for (int i = tid; i < 1024; i += 256) {
        int p = i >> 5, q = i & 31;
        int sp = (p*66) >> 5, ep = ((p+1)*66 + 31) >> 5;
        int sq = (q*66) >> 5, eq = ((q+1)*66 + 31) >> 5;
        float s = 0.f;
        for (int h = sp; h < ep; h++)
            for (int w = sq; w < eq; w++)
                s += win[h][w];
        g_gram[r*1024 + i] = s / (float)((ep - sp) * (eq - sq));
    }
}

// ---------------- split-K GEMM: part[s] = A(64xKC chunk) @ B ---------------
// grid (ceil(N/64), nsplit), block 128. Thread tile: 4 M-rows x 8 N-cols.
__global__ __launch_bounds__(128) void gemm_sk_kernel(
    const float* __restrict__ Bm, int K, int N, int KC, int stage)
{
    const float* __restrict__ A = (stage == 0) ? g_gram : (stage == 1) ? g_fc1 : g_fc2;

    __shared__ float  As[16][65];
    __shared__ float4 Bs[16][16];

    int n0 = blockIdx.x * 64;
    int k0 = blockIdx.y * KC;
    int tid = threadIdx.x;
    int tx = tid & 7;        // 8 col groups of 8
    int ty = tid >> 3;       // 16 row groups of 4

    ull acc[4][4];
#pragma unroll
    for (int u = 0; u < 4; u++)
#pragma unroll
        for (int v = 0; v < 4; v++) acc[u][v] = 0ull;

    for (int kc = 0; kc < KC; kc += 16) {
        int kb = k0 + kc;
        __syncthreads();
#pragma unroll
        for (int r = 0; r < 2; r++) {
            int i = tid * 2 + r;
            int m  = i >> 2;
            int kg = (i & 3) * 4;
            float4 v = *(const float4*)&A[(size_t)m * K + kb + kg];
            As[kg+0][m] = v.x; As[kg+1][m] = v.y;
            As[kg+2][m] = v.z; As[kg+3][m] = v.w;
        }
#pragma unroll
        for (int r = 0; r < 2; r++) {
            int i = tid * 2 + r;
            int kk = i >> 4;
            int f  = i & 15;
            int col = n0 + f * 4;
            float4 v = make_float4(0.f, 0.f, 0.f, 0.f);
            if (col < N) v = *(const float4*)&Bm[(size_t)(kb + kk) * N + col];
            Bs[kk][f] = v;
        }
        __syncthreads();

#pragma unroll
        for (int kk = 0; kk < 16; kk++) {
            ull a2[4];
#pragma unroll
            for (int u = 0; u < 4; u++) {
                float a = As[kk][ty*4 + u];
                a2[u] = pack2(a, a);
            }
            const ull* bp = (const ull*)&Bs[kk][tx*2];
            ull b2[4];
#pragma unroll
            for (int v = 0; v < 4; v++) b2[v] = bp[v];
#pragma unroll
            for (int u = 0; u < 4; u++)
#pragma unroll
                for (int v = 0; v < 4; v++)
                    acc[u][v] = fma2(b2[v], a2[u], acc[u][v]);
        }
    }

    int s = blockIdx.y;
#pragma unroll
    for (int u = 0; u < 4; u++) {
        int row = ty*4 + u;
#pragma unroll
        for (int v = 0; v < 4; v++) {
            int col = n0 + tx*8 + v*2;
            if (col < N) {
                float lo, hi;
                unpack2(acc[u][v], lo, hi);
                float* p = &g_part[((size_t)(s*64 + row)) * N + col];
                p[0] = lo; p[1] = hi;
            }
        }
    }
}

// ---------------- split-K reduce + bias + activation -----------------------
__global__ void gemm_reduce_kernel(const float* __restrict__ bias,
                                   int N, int nsplit, int relu, int stage)
{
    float* out = (stage == 0) ? g_fc1 : (stage == 1) ? g_fc2 : g_wb;
    int nv = N >> 2;
    int idx = blockIdx.x * 256 + threadIdx.x;
    if (idx >= 64 * nv) return;
    int m = idx / nv, f = idx - m * nv;
    float4 s = make_float4(0.f, 0.f, 0.f, 0.f);
    for (int sp = 0; sp < nsplit; sp++) {
        const float4* p = (const float4*)&g_part[(size_t)(sp*64 + m) * N];
        float4 v = p[f];
        s.x += v.x; s.y += v.y; s.z += v.z; s.w += v.w;
    }
    float4 bv = ((const float4*)bias)[f];
    s.x += bv.x; s.y += bv.y; s.z += bv.z; s.w += bv.w;
    if (relu) {
        s.x = fmaxf(s.x, 0.f); s.y = fmaxf(s.y, 0.f);
        s.z = fmaxf(s.z, 0.f); s.w = fmaxf(s.w, 0.f);
    }
    ((float4*)out)[(size_t)m * nv + f] = s;
}

// ---------------- dynamic per-tile conv (64->32, VALID on 66x66 window) ----
__global__ __launch_bounds__(256) void dynconv_kernel(
    const float* __restrict__ feat, float* __restrict__ out)
{
    __shared__ ull wsm[8*64*9];
    __shared__ float patch[2][34][35];

    int idx = blockIdx.z;
    int ocg = idx & 3;
    int r = idx >> 2;                       // b*16 + t
    int b = r >> 4, t = r & 15;
    int ti = t >> 2, tj = t & 3;
    int gy0 = ti*64 + blockIdx.y * 32;
    int gx0 = tj*64 + blockIdx.x * 32;
    int tx = threadIdx.x, ty = threadIdx.y;
    int tid = ty * 32 + tx;

    const float* wrow = g_wb + (size_t)r * 18464 + ocg * (8*576);
    for (int i = tid; i < 4608; i += 256) {
        float w = wrow[i];
        wsm[i] = pack2(w, w);
    }

    const float* fbase = feat + (size_t)(b*64) * 65536;
    float pre[5];
    ldpatch(fbase, gy0, gx0, tid, pre);
    stpatch(patch[0], tid, pre);

    ull accA[8], accB[8];
#pragma unroll
    for (int o = 0; o < 8; o++) { accA[o] = 0ull; accB[o] = 0ull; }

    __syncthreads();

    for (int ic = 0; ic < 64; ic++) {
        int p = ic & 1;
        if (ic < 63) ldpatch(fbase + (size_t)(ic+1)*65536, gy0, gx0, tid, pre);

        ull PA[9], PB[9];
#pragma unroll
        for (int dy = 0; dy < 3; dy++)
#pragma unroll
            for (int dx = 0; dx < 3; dx++) {
                int k = dy*3 + dx;
                PA[k] = pack2(patch[p][ty + dy][tx + dx],      patch[p][ty + 8  + dy][tx + dx]);
                PB[k] = pack2(patch[p][ty + 16 + dy][tx + dx], patch[p][ty + 24 + dy][tx + dx]);
            }
#pragma unroll
        for (int o = 0; o < 8; o++) {
            const ull* w = &wsm[(o*64 + ic) * 9];
#pragma unroll
            for (int k = 0; k < 9; k++) {
                ull w2 = w[k];
                accA[o] = fma2(PA[k], w2, accA[o]);
                accB[o] = fma2(PB[k], w2, accB[o]);
            }
        }
        if (ic < 63) stpatch(patch[p ^ 1], tid, pre);
        __syncthreads();
    }

#pragma unroll
    for (int o = 0; o < 8; o++) {
        int oc = ocg*8 + o;
        float bias = g_wb[(size_t)r * 18464 + 18432 + oc];
        float v0, v1, v2, v3;
        unpack2(accA[o], v0, v1);
        unpack2(accB[o], v2, v3);
        float vv[4] = {v0, v1, v2, v3};
        size_t base = (size_t)(b*96 + 64 + oc) * 65536;
#pragma unroll
        for (int k = 0; k < 4; k++)
            out[base + (size_t)(gy0 + ty + 8*k) * 256 + gx0 + tx] = vv[k] + bias;
    }
}

// ---------------- passthrough copy: out[:, 0:64] = feature -----------------
__global__ void copy_feat_kernel(const float4* __restrict__ f, float4* __restrict__ out)
{
    int i = blockIdx.x * 256 + threadIdx.x;    // 4,194,304 float4 total
    if (i < 4194304) {
        int b = i >> 20;
        int rem = i & ((1 << 20) - 1);
        out[(size_t)b * 1572864 + rem] = f[i];
    }
}

// ---------------- launch ---------------------------------------------------
extern "C" void kernel_launch(void* const* d_in, const int* in_sizes, int n_in,
                              void* d_out, int out_size)
{
    const float* feature = (const float*)d_in[0];
    const float* rw1 = (const float*)d_in[1];
    const float* rb1 = (const float*)d_in[2];
    const float* rw2 = (const float*)d_in[3];
    const float* rb2 = (const float*)d_in[4];
    const float* fw1 = (const float*)d_in[5];
    const float* fb1 = (const float*)d_in[6];
    const float* fw2 = (const float*)d_in[7];
    const float* fb2 = (const float*)d_in[8];
    const float* fw3 = (const float*)d_in[9];
    const float* fb3 = (const float*)d_in[10];
    float* out = (float*)d_out;

    conv1_kernel<<<dim3(8, 8, 32), dim3(32, 8)>>>(feature, rw1, rb1);
    conv2_kernel<<<dim3(8, 8, 4),  dim3(32, 8)>>>(rw2, rb2);
    pool_kernel<<<64, 256>>>();

    // FC1: 64x1024 @ 1024x2048, split-K 16
    gemm_sk_kernel<<<dim3(32, 16), 128>>>(fw1, 1024, 2048, 64, 0);
    gemm_reduce_kernel<<<(64*512 + 255)/256, 256>>>(fb1, 2048, 16, 1, 0);
    // FC2: 64x2048 @ 2048x2048, split-K 16
    gemm_sk_kernel<<<dim3(32, 16), 128>>>(fw2, 2048, 2048, 128, 1);
    gemm_reduce_kernel<<<(64*512 + 255)/256, 256>>>(fb2, 2048, 16, 1, 1);
    // FC3: 64x2048 @ 2048x18464, split-K 8
    gemm_sk_kernel<<<dim3(289, 8), 128>>>(fw3, 2048, 18464, 256, 2);
    gemm_reduce_kernel<<<(64*4616 + 255)/256, 256>>>(fb3, 18464, 8, 0, 2);

    dynconv_kernel<<<dim3(2, 2, 256), dim3(32, 8)>>>(feature, out);
    copy_feat_kernel<<<16384, 256>>>((const float4*)feature, (float4*)out);
}

// round 6
// speedup vs baseline: 1.2849x; 1.2849x over previous
#include <cuda_runtime.h>
#include <cuda_bf16.h>
#include <cstdint>
#include <math.h>

// Problem constants
// B=4, C=64, H=W=256, N_SPLIT=4 (T=16), RED_FC=32, OUT_NC=32, K=3, FMN1=FMN2=2048
// wsize = 32*64*9 = 18432, wb row = 18464

typedef unsigned long long ull;

// ---------------- scratch (device globals; no runtime allocation) ----------
__device__ float g_h[4*256*256*64];            // conv1 output, NHWC fp32
__device__ float g_adap[4*256*256];            // tanh(conv2)
__device__ float g_gram[64*1024];              // pooled grams
__device__ float g_fc1[64*2048];
__device__ float g_fc2[64*2048];
__device__ float g_wb[64*18464];               // dynamic weights + bias
__device__ float g_part[9453568];              // split-K partials
__device__ __nv_bfloat16 g_fh[4*256*256*64];   // feature NHWC bf16 hi
__device__ __nv_bfloat16 g_fl[4*256*256*64];   // feature NHWC bf16 lo
__device__ __nv_bfloat16 g_w1h[9*64*64];       // rw1 [tap][oc][ic] hi
__device__ __nv_bfloat16 g_w1l[9*64*64];       // rw1 [tap][oc][ic] lo

// ---------------- f32x2 helpers (sm_103a packed fp32 FMA) ------------------
__device__ __forceinline__ ull pack2(float lo, float hi) {
    ull d; asm("mov.b64 %0, {%1, %2};" : "=l"(d) : "f"(lo), "f"(hi)); return d;
}
__device__ __forceinline__ void unpack2(ull d, float& lo, float& hi) {
    asm("mov.b64 {%0, %1}, %2;" : "=f"(lo), "=f"(hi) : "l"(d));
}
__device__ __forceinline__ ull fma2(ull a, ull b, ull c) {
    ull d; asm("fma.rn.f32x2 %0, %1, %2, %3;" : "=l"(d) : "l"(a), "l"(b), "l"(c)); return d;
}

// ---------------- mma.sync helpers (sm_80+ path, works on plain sm_103) ----
__device__ __forceinline__ uint32_t smem_u32(const void* p) {
    uint32_t a;
    asm("{ .reg .u64 t; cvta.to.shared.u64 t, %1; cvt.u32.u64 %0, t; }" : "=r"(a) : "l"(p));
    return a;
}
__device__ __forceinline__ void ldm_x4(uint32_t* r, uint32_t addr) {
    asm volatile("ldmatrix.sync.aligned.m8n8.x4.shared.b16 {%0,%1,%2,%3}, [%4];"
        : "=r"(r[0]), "=r"(r[1]), "=r"(r[2]), "=r"(r[3]) : "r"(addr));
}
__device__ __forceinline__ void ldm_x2(uint32_t* r, uint32_t addr) {
    asm volatile("ldmatrix.sync.aligned.m8n8.x2.shared.b16 {%0,%1}, [%2];"
        : "=r"(r[0]), "=r"(r[1]) : "r"(addr));
}
__device__ __forceinline__ void mma_bf16(float* d, const uint32_t* a, const uint32_t* b) {
    asm volatile(
        "mma.sync.aligned.m16n8k16.row.col.f32.bf16.bf16.f32 "
        "{%0,%1,%2,%3}, {%4,%5,%6,%7}, {%8,%9}, {%0,%1,%2,%3};"
        : "+f"(d[0]), "+f"(d[1]), "+f"(d[2]), "+f"(d[3])
        : "r"(a[0]), "r"(a[1]), "r"(a[2]), "r"(a[3]), "r"(b[0]), "r"(b[1]));
}

// ---------------- NCHW fp32 -> NHWC bf16 hi/lo -----------------------------
__global__ __launch_bounds__(256) void tohwc_kernel(const float* __restrict__ feat)
{
    __shared__ float s[64][65];
    int bx = blockIdx.x;
    int b = bx >> 10, grp = bx & 1023;
    int pix0 = grp * 64;
    int tid = threadIdx.x;
#pragma unroll
    for (int i = 0; i < 16; i++) {
        int idx = i * 256 + tid;
        int ic = idx >> 6, px = idx & 63;
        s[ic][px] = feat[(((size_t)(b*64 + ic)) << 16) + pix0 + px];
    }
    __syncthreads();
#pragma unroll
    for (int i = 0; i < 16; i++) {
        int idx = i * 256 + tid;
        int px = idx >> 6, ic = idx & 63;
        float v = s[ic][px];
        __nv_bfloat16 hi = __float2bfloat16_rn(v);
        __nv_bfloat16 lo = __float2bfloat16_rn(v - __bfloat162float(hi));
        size_t o = ((size_t)b*65536 + pix0 + px) * 64 + ic;
        g_fh[o] = hi; g_fl[o] = lo;
    }
}

// ---------------- rw1 -> [tap][oc][ic] bf16 hi/lo --------------------------
__global__ void wprep_kernel(const float* __restrict__ rw1)
{
    int idx = blockIdx.x * 256 + threadIdx.x;
    if (idx >= 9*64*64) return;
    int tap = idx >> 12, rem = idx & 4095;
    int oc = rem >> 6, ic = rem & 63;
    float v = rw1[(oc*64 + ic)*9 + tap];
    __nv_bfloat16 hi = __float2bfloat16_rn(v);
    __nv_bfloat16 lo = __float2bfloat16_rn(v - __bfloat162float(hi));
    g_w1h[idx] = hi; g_w1l[idx] = lo;
}

// ---------------- conv1 via mma.sync: 9 tap GEMMs, bf16 hi/lo split --------
// grid (8,32,4): x-tile (32 px), y-tile (8 rows), batch. block 256 (8 warps).
// Block tile: 8 rows x 32 cols x 64 oc. Warp w -> row w, 2 m16-tiles x 8 n8.
// Dyn smem: Ah[256][72] @0, Al @36864, Wh[64][72] @73728, Wl @82944, bias @92160.
__global__ __launch_bounds__(256) void conv1_hmma_kernel(const float* __restrict__ rb1)
{
    extern __shared__ char smem[];
    const uint32_t AH = 0, AL = 36864, WH = 73728, WL = 82944, BS = 92160;
    uint32_t sb = smem_u32(smem);
    int b = blockIdx.z;
    int y0 = blockIdx.y * 8, x0 = blockIdx.x * 32;
    int tid = threadIdx.x, w = tid >> 5, lane = tid & 31;

    if (tid < 64) *(float*)(smem + BS + tid*4) = rb1[tid];

    float acc[2][8][4];
#pragma unroll
    for (int mt = 0; mt < 2; mt++)
#pragma unroll
        for (int nt = 0; nt < 8; nt++)
#pragma unroll
            for (int e = 0; e < 4; e++) acc[mt][nt][e] = 0.f;

    // per-lane ldmatrix address components
    uint32_t a_row = lane & 15, a_k16 = (lane >> 4) * 16;
    uint32_t w_row = lane & 7,  w_k16 = ((lane >> 3) & 1) * 16;

    for (int tap = 0; tap < 9; tap++) {
        int dy = tap / 3 - 1, dx = tap % 3 - 1;
        __syncthreads();
        // build A (hi/lo): 256 px x 64 ic, rows padded to 72 bf16 (144 B)
#pragma unroll
        for (int j = 0; j < 8; j++) {
            int i = j * 256 + tid;          // 0..2047 uint4 slots
            int px = i >> 3, ch8 = i & 7;
            int gy = y0 + (px >> 5) + dy, gx = x0 + (px & 31) + dx;
            uint4 vh = {0,0,0,0}, vl = {0,0,0,0};
            if ((unsigned)gy < 256u && (unsigned)gx < 256u) {
                size_t g = ((size_t)(b*256 + gy)*256 + gx)*64 + ch8*8;
                vh = *(const uint4*)(g_fh + g);
                vl = *(const uint4*)(g_fl + g);
            }
            uint32_t off = (uint32_t)px*144 + ch8*16;
            *(uint4*)(smem + AH + off) = vh;
            *(uint4*)(smem + AL + off) = vl;
        }
        // build W (hi/lo): 64 oc x 64 ic
#pragma unroll
        for (int j = 0; j < 2; j++) {
            int i = j * 256 + tid;          // 0..511 uint4 slots
            int row = i >> 3, ch8 = i & 7;
            size_t g = ((size_t)tap*64 + row)*64 + ch8*8;
            uint4 vh = *(const uint4*)(g_w1h + g);
            uint4 vl = *(const uint4*)(g_w1l + g);
            uint32_t off = (uint32_t)row*144 + ch8*16;
            *(uint4*)(smem + WH + off) = vh;
            *(uint4*)(smem + WL + off) = vl;
        }
        __syncthreads();

#pragma unroll
        for (int ks = 0; ks < 4; ks++) {
            uint32_t ah[2][4], al[2][4];
#pragma unroll
            for (int mt = 0; mt < 2; mt++) {
                uint32_t aoff = (uint32_t)(w*32 + mt*16 + a_row)*144 + ks*32 + a_k16;
                ldm_x4(ah[mt], sb + AH + aoff);
                ldm_x4(al[mt], sb + AL + aoff);
            }
#pragma unroll
            for (int nt = 0; nt < 8; nt++) {
                uint32_t wh[2], wl[2];
                uint32_t woff = (uint32_t)(nt*8 + w_row)*144 + ks*32 + w_k16;
                ldm_x2(wh, sb + WH + woff);
                ldm_x2(wl, sb + WL + woff);
                mma_bf16(acc[0][nt], ah[0], wh);
                mma_bf16(acc[1][nt], ah[1], wh);
                mma_bf16(acc[0][nt], al[0], wh);
                mma_bf16(acc[1][nt], al[1], wh);
                mma_bf16(acc[0][nt], ah[0], wl);
                mma_bf16(acc[1][nt], ah[1], wl);
            }
        }
    }
    __syncthreads();

    // epilogue: bias + leaky relu, NHWC stores
    const float* bs = (const float*)(smem + BS);
    int g = lane >> 2, c0 = (lane & 3) * 2;
    int y = y0 + w;
#pragma unroll
    for (int mt = 0; mt < 2; mt++) {
#pragma unroll
        for (int half = 0; half < 2; half++) {
            int x = x0 + mt*16 + g + half*8;
            float* dst = g_h + ((size_t)(b*256 + y)*256 + x)*64;
#pragma unroll
            for (int nt = 0; nt < 8; nt++) {
                int oc = nt*8 + c0;
                float v0 = acc[mt][nt][half*2 + 0] + bs[oc];
                float v1 = acc[mt][nt][half*2 + 1] + bs[oc + 1];
                v0 = (v0 >= 0.f) ? v0 : 0.2f * v0;
                v1 = (v1 >= 0.f) ? v1 : 0.2f * v1;
                float2 o = {v0, v1};
                *(float2*)(dst + oc) = o;
            }
        }
    }
}

// ---------------- conv2 (NHWC in): 64->1 3x3 pad1 + tanh -------------------
__global__ __launch_bounds__(256) void conv2_kernel(
    const float* __restrict__ rw2, const float* __restrict__ rb2)
{
    __shared__ float ws[576];
    int tid = threadIdx.x;
    for (int i = tid; i < 576; i += 256) {
        int tap = i >> 6, ic = i & 63;
        ws[i] = rw2[ic*9 + tap];
    }
    __syncthreads();
    int P = blockIdx.x * 256 + tid;        // 0..262143
    int b = P >> 16, pix = P & 65535;
    int y = pix >> 8, x = pix & 255;
    float acc = 0.f;
#pragma unroll
    for (int tap = 0; tap < 9; tap++) {
        int yy = y + tap/3 - 1, xx = x + tap%3 - 1;
        if ((unsigned)yy < 256u && (unsigned)xx < 256u) {
            const float4* hp = (const float4*)(g_h + ((size_t)(b*256 + yy)*256 + xx)*64);
            const float4* wp = (const float4*)(ws + tap*64);
#pragma unroll
            for (int v = 0; v < 16; v++) {
                float4 h4 = hp[v], w4 = wp[v];
                acc += h4.x*w4.x + h4.y*w4.y + h4.z*w4.z + h4.w*w4.w;
            }
        }
    }
    g_adap[(size_t)b*65536 + pix] = tanhf(acc + rb2[0]);
}

// ---------------- adaptive pool per tile -> gram ---------------------------
__global__ void pool_kernel()
{
    __shared__ float win[66][67];
    int r = blockIdx.x;
    int b = r >> 4, t = r & 15;
    int ti = t >> 2, tj = t & 3;
    int tid = threadIdx.x;
    for (int i = tid; i < 66*66; i += 256) {
        int h = i / 66, w = i % 66;
        int gy = ti*64 - 1 + h, gx = tj*64 - 1 + w;
        float v = 0.f;
        if ((unsigned)gy < 256u && (unsigned)gx < 256u)
            v = g_adap[((size_t)b*256 + gy) * 256 + gx];
        win[h][w] = v;
    }
    __syncthreads();
    for (int i = tid; i < 1024; i += 256) {
        int p = i >> 5, q = i & 31;
        int sp = (p*66) >> 5, ep = ((p+1)*66 + 31) >> 5;
        int sq = (q*66) >> 5, eq = ((q+1)*66 + 31) >> 5;
        float s = 0.f;
        for (int h = sp; h < ep; h++)
            for (int w = sq; w < eq; w++)
                s += win[h][w];
        g_gram[r*1024 + i] = s / (float)((ep - sp) * (eq - sq));
    }
}

// ---------------- split-K GEMM: part[s] = A(64xKC chunk) @ B ---------------
__global__ __launch_bounds__(128) void gemm_sk_kernel(
    const float* __restrict__ Bm, int K, int N, int KC, int stage)
{
    const float* __restrict__ A = (stage == 0) ? g_gram : (stage == 1) ? g_fc1 : g_fc2;

    __shared__ float  As[16][65];
    __shared__ float4 Bs[16][16];

    int n0 = blockIdx.x * 64;
    int k0 = blockIdx.y * KC;
    int tid = threadIdx.x;
    int tx = tid & 7;
    int ty = tid >> 3;

    ull acc[4][4];
#pragma unroll
    for (int u = 0; u < 4; u++)
#pragma unroll
        for (int v = 0; v < 4; v++) acc[u][v] = 0ull;

    for (int kc = 0; kc < KC; kc += 16) {
        int kb = k0 + kc;
        __syncthreads();
#pragma unroll
        for (int r = 0; r < 2; r++) {
            int i = tid * 2 + r;
            int m  = i >> 2;
            int kg = (i & 3) * 4;
            float4 v = *(const float4*)&A[(size_t)m * K + kb + kg];
            As[kg+0][m] = v.x; As[kg+1][m] = v.y;
            As[kg+2][m] = v.z; As[kg+3][m] = v.w;
        }
#pragma unroll
        for (int r = 0; r < 2; r++) {
            int i = tid * 2 + r;
            int kk = i >> 4;
            int f  = i & 15;
            int col = n0 + f * 4;
            float4 v = make_float4(0.f, 0.f, 0.f, 0.f);
            if (col < N) v = *(const float4*)&Bm[(size_t)(kb + kk) * N + col];
            Bs[kk][f] = v;
        }
        __syncthreads();

#pragma unroll
        for (int kk = 0; kk < 16; kk++) {
            ull a2[4];
#pragma unroll
            for (int u = 0; u < 4; u++) {
                float a = As[kk][ty*4 + u];
                a2[u] = pack2(a, a);
            }
            const ull* bp = (const ull*)&Bs[kk][tx*2];
            ull b2[4];
#pragma unroll
            for (int v = 0; v < 4; v++) b2[v] = bp[v];
#pragma unroll
            for (int u = 0; u < 4; u++)
#pragma unroll
                for (int v = 0; v < 4; v++)
                    acc[u][v] = fma2(b2[v], a2[u], acc[u][v]);
        }
    }

    int s = blockIdx.y;
#pragma unroll
    for (int u = 0; u < 4; u++) {
        int row = ty*4 + u;
#pragma unroll
        for (int v = 0; v < 4; v++) {
            int col = n0 + tx*8 + v*2;
            if (col < N) {
                float lo, hi;
                unpack2(acc[u][v], lo, hi);
                float* p = &g_part[((size_t)(s*64 + row)) * N + col];
                p[0] = lo; p[1] = hi;
            }
        }
    }
}

// ---------------- split-K reduce + bias + activation -----------------------
__global__ void gemm_reduce_kernel(const float* __restrict__ bias,
                                   int N, int nsplit, int relu, int stage)
{
    float* out = (stage == 0) ? g_fc1 : (stage == 1) ? g_fc2 : g_wb;
    int nv = N >> 2;
    int idx = blockIdx.x * 256 + threadIdx.x;
    if (idx >= 64 * nv) return;
    int m = idx / nv, f = idx - m * nv;
    float4 s = make_float4(0.f, 0.f, 0.f, 0.f);
    for (int sp = 0; sp < nsplit; sp++) {
        const float4* p = (const float4*)&g_part[(size_t)(sp*64 + m) * N];
        float4 v = p[f];
        s.x += v.x; s.y += v.y; s.z += v.z; s.w += v.w;
    }
    float4 bv = ((const float4*)bias)[f];
    s.x += bv.x; s.y += bv.y; s.z += bv.z; s.w += bv.w;
    if (relu) {
        s.x = fmaxf(s.x, 0.f); s.y = fmaxf(s.y, 0.f);
        s.z = fmaxf(s.z, 0.f); s.w = fmaxf(s.w, 0.f);
    }
    ((float4*)out)[(size_t)m * nv + f] = s;
}

// ---------------- patch pipeline helpers (for dynconv) ---------------------
__device__ __forceinline__ void ldpatch(const float* __restrict__ fp,
                                        int y0, int x0, int tid, float* pre)
{
#pragma unroll
    for (int r = 0; r < 5; r++) {
        int i = tid + 256*r;
        float v = 0.f;
        if (i < 1156) {
            int py = i / 34, px = i - py*34;
            int gy = y0 - 1 + py, gx = x0 - 1 + px;
            if ((unsigned)gy < 256u && (unsigned)gx < 256u) v = __ldg(&fp[gy*256 + gx]);
        }
        pre[r] = v;
    }
}
__device__ __forceinline__ void stpatch(float (*buf)[35], int tid, const float* pre)
{
#pragma unroll
    for (int r = 0; r < 5; r++) {
        int i = tid + 256*r;
        if (i < 1156) buf[i / 34][i - (i/34)*34] = pre[r];
    }
}

// ---------------- dynamic per-tile conv (64->32, VALID on 66x66 window) ----
__global__ __launch_bounds__(256) void dynconv_kernel(
    const float* __restrict__ feat, float* __restrict__ out)
{
    __shared__ ull wsm[8*64*9];
    __shared__ float patch[2][34][35];

    int idx = blockIdx.z;
    int ocg = idx & 3;
    int r = idx >> 2;
    int b = r >> 4, t = r & 15;
    int ti = t >> 2, tj = t & 3;
    int gy0 = ti*64 + blockIdx.y * 32;
    int gx0 = tj*64 + blockIdx.x * 32;
    int tx = threadIdx.x, ty = threadIdx.y;
    int tid = ty * 32 + tx;

    const float* wrow = g_wb + (size_t)r * 18464 + ocg * (8*576);
    for (int i = tid; i < 4608; i += 256) {
        float w = wrow[i];
        wsm[i] = pack2(w, w);
    }

    const float* fbase = feat + (size_t)(b*64) * 65536;
    float pre[5];
    ldpatch(fbase, gy0, gx0, tid, pre);
    stpatch(patch[0], tid, pre);

    ull accA[8], accB[8];
#pragma unroll
    for (int o = 0; o < 8; o++) { accA[o] = 0ull; accB[o] = 0ull; }

    __syncthreads();

    for (int ic = 0; ic < 64; ic++) {
        int p = ic & 1;
        if (ic < 63) ldpatch(fbase + (size_t)(ic+1)*65536, gy0, gx0, tid, pre);

        ull PA[9], PB[9];
#pragma unroll
        for (int dy = 0; dy < 3; dy++)
#pragma unroll
            for (int dx = 0; dx < 3; dx++) {
                int k = dy*3 + dx;
                PA[k] = pack2(patch[p][ty + dy][tx + dx],      patch[p][ty + 8  + dy][tx + dx]);
                PB[k] = pack2(patch[p][ty + 16 + dy][tx + dx], patch[p][ty + 24 + dy][tx + dx]);
            }
#pragma unroll
        for (int o = 0; o < 8; o++) {
            const ull* w = &wsm[(o*64 + ic) * 9];
#pragma unroll
            for (int k = 0; k < 9; k++) {
                ull w2 = w[k];
                accA[o] = fma2(PA[k], w2, accA[o]);
                accB[o] = fma2(PB[k], w2, accB[o]);
            }
        }
        if (ic < 63) stpatch(patch[p ^ 1], tid, pre);
        __syncthreads();
    }

#pragma unroll
    for (int o = 0; o < 8; o++) {
        int oc = ocg*8 + o;
        float bias = g_wb[(size_t)r * 18464 + 18432 + oc];
        float v0, v1, v2, v3;
        unpack2(accA[o], v0, v1);
        unpack2(accB[o], v2, v3);
        float vv[4] = {v0, v1, v2, v3};
        size_t base = (size_t)(b*96 + 64 + oc) * 65536;
#pragma unroll
        for (int k = 0; k < 4; k++)
            out[base + (size_t)(gy0 + ty + 8*k) * 256 + gx0 + tx] = vv[k] + bias;
    }
}

// ---------------- passthrough copy: out[:, 0:64] = feature -----------------
__global__ void copy_feat_kernel(const float4* __restrict__ f, float4* __restrict__ out)
{
    int i = blockIdx.x * 256 + threadIdx.x;
    if (i < 4194304) {
        int b = i >> 20;
        int rem = i & ((1 << 20) - 1);
        out[(size_t)b * 1572864 + rem] = f[i];
    }
}

// ---------------- launch ---------------------------------------------------
extern "C" void kernel_launch(void* const* d_in, const int* in_sizes, int n_in,
                              void* d_out, int out_size)
{
    const float* feature = (const float*)d_in[0];
    const float* rw1 = (const float*)d_in[1];
    const float* rb1 = (const float*)d_in[2];
    const float* rw2 = (const float*)d_in[3];
    const float* rb2 = (const float*)d_in[4];
    const float* fw1 = (const float*)d_in[5];
    const float* fb1 = (const float*)d_in[6];
    const float* fw2 = (const float*)d_in[7];
    const float* fb2 = (const float*)d_in[8];
    const float* fw3 = (const float*)d_in[9];
    const float* fb3 = (const float*)d_in[10];
    float* out = (float*)d_out;

    const int CONV1_SMEM = 92416;
    cudaFuncSetAttribute(conv1_hmma_kernel,
                         cudaFuncAttributeMaxDynamicSharedMemorySize, CONV1_SMEM);

    tohwc_kernel<<<4096, 256>>>(feature);
    wprep_kernel<<<144, 256>>>(rw1);
    conv1_hmma_kernel<<<dim3(8, 32, 4), 256, CONV1_SMEM>>>(rb1);
    conv2_kernel<<<1024, 256>>>(rw2, rb2);
    pool_kernel<<<64, 256>>>();

    // FC1: 64x1024 @ 1024x2048, split-K 16
    gemm_sk_kernel<<<dim3(32, 16), 128>>>(fw1, 1024, 2048, 64, 0);
    gemm_reduce_kernel<<<(64*512 + 255)/256, 256>>>(fb1, 2048, 16, 1, 0);
    // FC2: 64x2048 @ 2048x2048, split-K 16
    gemm_sk_kernel<<<dim3(32, 16), 128>>>(fw2, 2048, 2048, 128, 1);
    gemm_reduce_kernel<<<(64*512 + 255)/256, 256>>>(fb2, 2048, 16, 1, 1);
    // FC3: 64x2048 @ 2048x18464, split-K 8
    gemm_sk_kernel<<<dim3(289, 8), 128>>>(fw3, 2048, 18464, 256, 2);
    gemm_reduce_kernel<<<(64*4616 + 255)/256, 256>>>(fb3, 18464, 8, 0, 2);

    dynconv_kernel<<<dim3(2, 2, 256), dim3(32, 8)>>>(feature, out);
    copy_feat_kernel<<<16384, 256>>>((const float4*)feature, (float4*)out);
}

// round 7
// speedup vs baseline: 1.8698x; 1.4552x over previous
#include <cuda_runtime.h>
#include <cuda_bf16.h>
#include <cstdint>
#include <math.h>

// Problem constants
// B=4, C=64, H=W=256, N_SPLIT=4 (T=16), RED_FC=32, OUT_NC=32, K=3, FMN1=FMN2=2048
// wsize = 32*64*9 = 18432, wb row = 18464

typedef unsigned long long ull;

// ---------------- scratch (device globals; no runtime allocation) ----------
__device__ float g_u[9*4*65536];               // conv2 tap projections
__device__ float g_adap[4*256*256];            // tanh(conv2)
__device__ float g_gram[64*1024];              // pooled grams
__device__ float g_fc1[64*2048];
__device__ float g_fc2[64*2048];
__device__ float g_wb[64*18464];               // dynamic weights + bias
__device__ float g_part[9453568];              // split-K partials
__device__ __nv_bfloat16 g_fh[4*256*256*64];   // feature NHWC bf16 hi
__device__ __nv_bfloat16 g_fl[4*256*256*64];   // feature NHWC bf16 lo
__device__ __nv_bfloat16 g_w1h[9*64*64];       // rw1 [tap][oc][ic] hi
__device__ __nv_bfloat16 g_w1l[9*64*64];       // rw1 [tap][oc][ic] lo

// ---------------- f32x2 helpers (sm_103a packed fp32 FMA) ------------------
__device__ __forceinline__ ull pack2(float lo, float hi) {
    ull d; asm("mov.b64 %0, {%1, %2};" : "=l"(d) : "f"(lo), "f"(hi)); return d;
}
__device__ __forceinline__ void unpack2(ull d, float& lo, float& hi) {
    asm("mov.b64 {%0, %1}, %2;" : "=f"(lo), "=f"(hi) : "l"(d));
}
__device__ __forceinline__ ull fma2(ull a, ull b, ull c) {
    ull d; asm("fma.rn.f32x2 %0, %1, %2, %3;" : "=l"(d) : "l"(a), "l"(b), "l"(c)); return d;
}

// ---------------- mma.sync helpers (sm_80+ path, works on plain sm_103) ----
__device__ __forceinline__ uint32_t smem_u32(const void* p) {
    uint32_t a;
    asm("{ .reg .u64 t; cvta.to.shared.u64 t, %1; cvt.u32.u64 %0, t; }" : "=r"(a) : "l"(p));
    return a;
}
__device__ __forceinline__ void ldm_x4(uint32_t* r, uint32_t addr) {
    asm volatile("ldmatrix.sync.aligned.m8n8.x4.shared.b16 {%0,%1,%2,%3}, [%4];"
        : "=r"(r[0]), "=r"(r[1]), "=r"(r[2]), "=r"(r[3]) : "r"(addr));
}
__device__ __forceinline__ void ldm_x2(uint32_t* r, uint32_t addr) {
    asm volatile("ldmatrix.sync.aligned.m8n8.x2.shared.b16 {%0,%1}, [%2];"
        : "=r"(r[0]), "=r"(r[1]) : "r"(addr));
}
__device__ __forceinline__ void mma_bf16(float* d, const uint32_t* a, const uint32_t* b) {
    asm volatile(
        "mma.sync.aligned.m16n8k16.row.col.f32.bf16.bf16.f32 "
        "{%0,%1,%2,%3}, {%4,%5,%6,%7}, {%8,%9}, {%0,%1,%2,%3};"
        : "+f"(d[0]), "+f"(d[1]), "+f"(d[2]), "+f"(d[3])
        : "r"(a[0]), "r"(a[1]), "r"(a[2]), "r"(a[3]), "r"(b[0]), "r"(b[1]));
}

// ---------------- NCHW fp32 -> NHWC bf16 hi/lo -----------------------------
__global__ __launch_bounds__(256) void tohwc_kernel(const float* __restrict__ feat)
{
    __shared__ float s[64][65];
    int bx = blockIdx.x;
    int b = bx >> 10, grp = bx & 1023;
    int pix0 = grp * 64;
    int tid = threadIdx.x;
#pragma unroll
    for (int i = 0; i < 16; i++) {
        int idx = i * 256 + tid;
        int ic = idx >> 6, px = idx & 63;
        s[ic][px] = feat[(((size_t)(b*64 + ic)) << 16) + pix0 + px];
    }
    __syncthreads();
#pragma unroll
    for (int i = 0; i < 16; i++) {
        int idx = i * 256 + tid;
        int px = idx >> 6, ic = idx & 63;
        float v = s[ic][px];
        __nv_bfloat16 hi = __float2bfloat16_rn(v);
        __nv_bfloat16 lo = __float2bfloat16_rn(v - __bfloat162float(hi));
        size_t o = ((size_t)b*65536 + pix0 + px) * 64 + ic;
        g_fh[o] = hi; g_fl[o] = lo;
    }
}

// ---------------- rw1 -> [tap][oc][ic] bf16 hi/lo --------------------------
__global__ void wprep_kernel(const float* __restrict__ rw1)
{
    int idx = blockIdx.x * 256 + threadIdx.x;
    if (idx >= 9*64*64) return;
    int tap = idx >> 12, rem = idx & 4095;
    int oc = rem >> 6, ic = rem & 63;
    float v = rw1[(oc*64 + ic)*9 + tap];
    __nv_bfloat16 hi = __float2bfloat16_rn(v);
    __nv_bfloat16 lo = __float2bfloat16_rn(v - __bfloat162float(hi));
    g_w1h[idx] = hi; g_w1l[idx] = lo;
}

// ---------------- conv1 via mma.sync + fused conv2 tap projection ----------
// grid (8,32,4): x-tile (32 px), y-tile (8 rows), batch. block 256 (8 warps).
// Epilogue computes u[tap][pix] = dot(leaky(conv1(pix)), w2[:,tap]) directly;
// g_h is never materialized.
// Dyn smem: Ah[256][72] @0, Al @36864, Wh[64][72] @73728, Wl @82944,
//           bias @92160 (256 B), w2 @92416 (9*64*4 = 2304 B).
__global__ __launch_bounds__(256) void conv1_hmma_kernel(
    const float* __restrict__ rb1, const float* __restrict__ rw2)
{
    extern __shared__ char smem[];
    const uint32_t AH = 0, AL = 36864, WH = 73728, WL = 82944, BS = 92160, W2 = 92416;
    uint32_t sb = smem_u32(smem);
    int b = blockIdx.z;
    int y0 = blockIdx.y * 8, x0 = blockIdx.x * 32;
    int tid = threadIdx.x, w = tid >> 5, lane = tid & 31;

    if (tid < 64) *(float*)(smem + BS + tid*4) = rb1[tid];
    // w2 smem layout [tap][ic]
    if (tid >= 64 && tid < 64 + 144) {
        int i = (tid - 64) * 4;
#pragma unroll
        for (int j = 0; j < 4; j++) {
            int idx = i + j;
            int ic = idx >> 3;          // wrong stride guard below
        }
    }
    for (int i = tid; i < 576; i += 256) {
        int tap = i >> 6, ic = i & 63;
        *(float*)(smem + W2 + i*4) = rw2[ic*9 + tap];
    }

    float acc[2][8][4];
#pragma unroll
    for (int mt = 0; mt < 2; mt++)
#pragma unroll
        for (int nt = 0; nt < 8; nt++)
#pragma unroll
            for (int e = 0; e < 4; e++) acc[mt][nt][e] = 0.f;

    uint32_t a_row = lane & 15, a_k16 = (lane >> 4) * 16;
    uint32_t w_row = lane & 7,  w_k16 = ((lane >> 3) & 1) * 16;

    for (int tap = 0; tap < 9; tap++) {
        int dy = tap / 3 - 1, dx = tap % 3 - 1;
        __syncthreads();
#pragma unroll
        for (int j = 0; j < 8; j++) {
            int i = j * 256 + tid;
            int px = i >> 3, ch8 = i & 7;
            int gy = y0 + (px >> 5) + dy, gx = x0 + (px & 31) + dx;
            uint4 vh = {0,0,0,0}, vl = {0,0,0,0};
            if ((unsigned)gy < 256u && (unsigned)gx < 256u) {
                size_t g = ((size_t)(b*256 + gy)*256 + gx)*64 + ch8*8;
                vh = *(const uint4*)(g_fh + g);
                vl = *(const uint4*)(g_fl + g);
            }
            uint32_t off = (uint32_t)px*144 + ch8*16;
            *(uint4*)(smem + AH + off) = vh;
            *(uint4*)(smem + AL + off) = vl;
        }
#pragma unroll
        for (int j = 0; j < 2; j++) {
            int i = j * 256 + tid;
            int row = i >> 3, ch8 = i & 7;
            size_t g = ((size_t)tap*64 + row)*64 + ch8*8;
            uint4 vh = *(const uint4*)(g_w1h + g);
            uint4 vl = *(const uint4*)(g_w1l + g);
            uint32_t off = (uint32_t)row*144 + ch8*16;
            *(uint4*)(smem + WH + off) = vh;
            *(uint4*)(smem + WL + off) = vl;
        }
        __syncthreads();

#pragma unroll
        for (int ks = 0; ks < 4; ks++) {
            uint32_t ah[2][4], al[2][4];
#pragma unroll
            for (int mt = 0; mt < 2; mt++) {
                uint32_t aoff = (uint32_t)(w*32 + mt*16 + a_row)*144 + ks*32 + a_k16;
                ldm_x4(ah[mt], sb + AH + aoff);
                ldm_x4(al[mt], sb + AL + aoff);
            }
#pragma unroll
            for (int nt = 0; nt < 8; nt++) {
                uint32_t wh[2], wl[2];
                uint32_t woff = (uint32_t)(nt*8 + w_row)*144 + ks*32 + w_k16;
                ldm_x2(wh, sb + WH + woff);
                ldm_x2(wl, sb + WL + woff);
                mma_bf16(acc[0][nt], ah[0], wh);
                mma_bf16(acc[1][nt], ah[1], wh);
                mma_bf16(acc[0][nt], al[0], wh);
                mma_bf16(acc[1][nt], al[1], wh);
                mma_bf16(acc[0][nt], ah[0], wl);
                mma_bf16(acc[1][nt], ah[1], wl);
            }
        }
    }
    __syncthreads();

    // epilogue: bias + leaky relu, then 9 tap-dot projections (quad reduce)
    const float* bs = (const float*)(smem + BS);
    const float* w2 = (const float*)(smem + W2);
    int g = lane >> 2, c0 = (lane & 3) * 2;
    int y = y0 + w;
#pragma unroll
    for (int mt = 0; mt < 2; mt++) {
#pragma unroll
        for (int half = 0; half < 2; half++) {
            int x = x0 + mt*16 + g + half*8;
            float part[9];
#pragma unroll
            for (int t = 0; t < 9; t++) part[t] = 0.f;
#pragma unroll
            for (int nt = 0; nt < 8; nt++) {
                int oc = nt*8 + c0;
                float v0 = acc[mt][nt][half*2 + 0] + bs[oc];
                float v1 = acc[mt][nt][half*2 + 1] + bs[oc + 1];
                v0 = (v0 >= 0.f) ? v0 : 0.2f * v0;
                v1 = (v1 >= 0.f) ? v1 : 0.2f * v1;
#pragma unroll
                for (int t = 0; t < 9; t++)
                    part[t] += v0 * w2[t*64 + oc] + v1 * w2[t*64 + oc + 1];
            }
#pragma unroll
            for (int t = 0; t < 9; t++) {
                part[t] += __shfl_xor_sync(0xFFFFFFFFu, part[t], 1);
                part[t] += __shfl_xor_sync(0xFFFFFFFFu, part[t], 2);
            }
            if ((lane & 3) == 0) {
                int pix = y*256 + x;
#pragma unroll
                for (int t = 0; t < 9; t++)
                    g_u[t*262144 + b*65536 + pix] = part[t];
            }
        }
    }
}

// ---------------- conv2 sum: adap = tanh(sum of shifted taps + bias) -------
__global__ __launch_bounds__(256) void conv2_sum_kernel(const float* __restrict__ rb2)
{
    int P = blockIdx.x * 256 + threadIdx.x;   // 0..262143
    int b = P >> 16, pix = P & 65535;
    int y = pix >> 8, x = pix & 255;
    float s = 0.f;
#pragma unroll
    for (int t = 0; t < 9; t++) {
        int yy = y + t/3 - 1, xx = x + t%3 - 1;
        if ((unsigned)yy < 256u && (unsigned)xx < 256u)
            s += g_u[t*262144 + b*65536 + yy*256 + xx];
    }
    g_adap[(size_t)b*65536 + pix] = tanhf(s + rb2[0]);
}

// ---------------- adaptive pool per tile -> gram ---------------------------
__global__ void pool_kernel()
{
    __shared__ float win[66][67];
    int r = blockIdx.x;
    int b = r >> 4, t = r & 15;
    int ti = t >> 2, tj = t & 3;
    int tid = threadIdx.x;
    for (int i = tid; i < 66*66; i += 256) {
        int h = i / 66, w = i % 66;
        int gy = ti*64 - 1 + h, gx = tj*64 - 1 + w;
        float v = 0.f;
        if ((unsigned)gy < 256u && (unsigned)gx < 256u)
            v = g_adap[((size_t)b*256 + gy) * 256 + gx];
        win[h][w] = v;
    }
    __syncthreads();
    for (int i = tid; i < 1024; i += 256) {
        int p = i >> 5, q = i & 31;
        int sp = (p*66) >> 5, ep = ((p+1)*66 + 31) >> 5;
        int sq = (q*66) >> 5, eq = ((q+1)*66 + 31) >> 5;
        float s = 0.f;
        for (int h = sp; h < ep; h++)
            for (int w = sq; w < eq; w++)
                s += win[h][w];
        g_gram[r*1024 + i] = s / (float)((ep - sp) * (eq - sq));
    }
}

// ---------------- split-K GEMM: part[s] = A(64xKC chunk) @ B ---------------
__global__ __launch_bounds__(128) void gemm_sk_kernel(
    const float* __restrict__ Bm, int K, int N, int KC, int stage)
{
    const float* __restrict__ A = (stage == 0) ? g_gram : (stage == 1) ? g_fc1 : g_fc2;

    __shared__ float  As[16][65];
    __shared__ float4 Bs[16][16];

    int n0 = blockIdx.x * 64;
    int k0 = blockIdx.y * KC;
    int tid = threadIdx.x;
    int tx = tid & 7;
    int ty = tid >> 3;

    ull acc[4][4];
#pragma unroll
    for (int u = 0; u < 4; u++)
#pragma unroll
        for (int v = 0; v < 4; v++) acc[u][v] = 0ull;

    for (int kc = 0; kc < KC; kc += 16) {
        int kb = k0 + kc;
        __syncthreads();
#pragma unroll
        for (int r = 0; r < 2; r++) {
            int i = tid * 2 + r;
            int m  = i >> 2;
            int kg = (i & 3) * 4;
            float4 v = *(const float4*)&A[(size_t)m * K + kb + kg];
            As[kg+0][m] = v.x; As[kg+1][m] = v.y;
            As[kg+2][m] = v.z; As[kg+3][m] = v.w;
        }
#pragma unroll
        for (int r = 0; r < 2; r++) {
            int i = tid * 2 + r;
            int kk = i >> 4;
            int f  = i & 15;
            int col = n0 + f * 4;
            float4 v = make_float4(0.f, 0.f, 0.f, 0.f);
            if (col < N) v = *(const float4*)&Bm[(size_t)(kb + kk) * N + col];
            Bs[kk][f] = v;
        }
        __syncthreads();

#pragma unroll
        for (int kk = 0; kk < 16; kk++) {
            ull a2[4];
#pragma unroll
            for (int u = 0; u < 4; u++) {
                float a = As[kk][ty*4 + u];
                a2[u] = pack2(a, a);
            }
            const ull* bp = (const ull*)&Bs[kk][tx*2];
            ull b2[4];
#pragma unroll
            for (int v = 0; v < 4; v++) b2[v] = bp[v];
#pragma unroll
            for (int u = 0; u < 4; u++)
#pragma unroll
                for (int v = 0; v < 4; v++)
                    acc[u][v] = fma2(b2[v], a2[u], acc[u][v]);
        }
    }

    int s = blockIdx.y;
#pragma unroll
    for (int u = 0; u < 4; u++) {
        int row = ty*4 + u;
#pragma unroll
        for (int v = 0; v < 4; v++) {
            int col = n0 + tx*8 + v*2;
            if (col < N) {
                float lo, hi;
                unpack2(acc[u][v], lo, hi);
                float* p = &g_part[((size_t)(s*64 + row)) * N + col];
                p[0] = lo; p[1] = hi;
            }
        }
    }
}

// ---------------- split-K reduce + bias + activation -----------------------
__global__ void gemm_reduce_kernel(const float* __restrict__ bias,
                                   int N, int nsplit, int relu, int stage)
{
    float* out = (stage == 0) ? g_fc1 : (stage == 1) ? g_fc2 : g_wb;
    int nv = N >> 2;
    int idx = blockIdx.x * 256 + threadIdx.x;
    if (idx >= 64 * nv) return;
    int m = idx / nv, f = idx - m * nv;
    float4 s = make_float4(0.f, 0.f, 0.f, 0.f);
    for (int sp = 0; sp < nsplit; sp++) {
        const float4* p = (const float4*)&g_part[(size_t)(sp*64 + m) * N];
        float4 v = p[f];
        s.x += v.x; s.y += v.y; s.z += v.z; s.w += v.w;
    }
    float4 bv = ((const float4*)bias)[f];
    s.x += bv.x; s.y += bv.y; s.z += bv.z; s.w += bv.w;
    if (relu) {
        s.x = fmaxf(s.x, 0.f); s.y = fmaxf(s.y, 0.f);
        s.z = fmaxf(s.z, 0.f); s.w = fmaxf(s.w, 0.f);
    }
    ((float4*)out)[(size_t)m * nv + f] = s;
}

// ---------------- dynamic per-tile conv via mma.sync (64->32) --------------
// grid (2,8,64): bx x-half of tile, by row-group, bz = r = b*16+t.
// block 256 (8 warps); warp w -> row y0+w; 2 m16 x 4 n8 tiles.
// Dyn smem: Ah @0 (36864), Al @36864, Wh @73728 (4608), Wl @78336, bias @82944.
__global__ __launch_bounds__(256) void dynconv_hmma_kernel(float* __restrict__ out)
{
    extern __shared__ char smem[];
    const uint32_t AH = 0, AL = 36864, WH = 73728, WL = 78336, BS = 82944;
    uint32_t sb = smem_u32(smem);
    int r = blockIdx.z;
    int b = r >> 4, t = r & 15;
    int ti = t >> 2, tj = t & 3;
    int y0 = ti*64 + blockIdx.y * 8;
    int x0 = tj*64 + blockIdx.x * 32;
    int tid = threadIdx.x, w = tid >> 5, lane = tid & 31;

    const float* wrow = g_wb + (size_t)r * 18464;
    if (tid < 32) *(float*)(smem + BS + tid*4) = wrow[18432 + tid];

    float acc[2][4][4];
#pragma unroll
    for (int mt = 0; mt < 2; mt++)
#pragma unroll
        for (int nt = 0; nt < 4; nt++)
#pragma unroll
            for (int e = 0; e < 4; e++) acc[mt][nt][e] = 0.f;

    uint32_t a_row = lane & 15, a_k16 = (lane >> 4) * 16;
    uint32_t w_row = lane & 7,  w_k16 = ((lane >> 3) & 1) * 16;

    for (int tap = 0; tap < 9; tap++) {
        int dy = tap / 3 - 1, dx = tap % 3 - 1;
        __syncthreads();
        // A: 256 px x 64 ic, bf16 hi/lo from precomputed NHWC
#pragma unroll
        for (int j = 0; j < 8; j++) {
            int i = j * 256 + tid;
            int px = i >> 3, ch8 = i & 7;
            int gy = y0 + (px >> 5) + dy, gx = x0 + (px & 31) + dx;
            uint4 vh = {0,0,0,0}, vl = {0,0,0,0};
            if ((unsigned)gy < 256u && (unsigned)gx < 256u) {
                size_t g = ((size_t)(b*256 + gy)*256 + gx)*64 + ch8*8;
                vh = *(const uint4*)(g_fh + g);
                vl = *(const uint4*)(g_fl + g);
            }
            uint32_t off = (uint32_t)px*144 + ch8*16;
            *(uint4*)(smem + AH + off) = vh;
            *(uint4*)(smem + AL + off) = vl;
        }
        // W: 32 oc x 64 ic from g_wb fp32, convert to hi/lo
#pragma unroll
        for (int j = 0; j < 8; j++) {
            int i = j * 256 + tid;          // 0..2047
            int oc = i >> 6, ic = i & 63;
            float v = wrow[(oc*64 + ic)*9 + tap];
            __nv_bfloat16 hi = __float2bfloat16_rn(v);
            __nv_bfloat16 lo = __float2bfloat16_rn(v - __bfloat162float(hi));
            uint32_t off = (uint32_t)oc*144 + ic*2;
            *(__nv_bfloat16*)(smem + WH + off) = hi;
            *(__nv_bfloat16*)(smem + WL + off) = lo;
        }
        __syncthreads();

#pragma unroll
        for (int ks = 0; ks < 4; ks++) {
            uint32_t ah[2][4], al[2][4];
#pragma unroll
            for (int mt = 0; mt < 2; mt++) {
                uint32_t aoff = (uint32_t)(w*32 + mt*16 + a_row)*144 + ks*32 + a_k16;
                ldm_x4(ah[mt], sb + AH + aoff);
                ldm_x4(al[mt], sb + AL + aoff);
            }
#pragma unroll
            for (int nt = 0; nt < 4; nt++) {
                uint32_t wh[2], wl[2];
                uint32_t woff = (uint32_t)(nt*8 + w_row)*144 + ks*32 + w_k16;
                ldm_x2(wh, sb + WH + woff);
                ldm_x2(wl, sb + WL + woff);
                mma_bf16(acc[0][nt], ah[0], wh);
                mma_bf16(acc[1][nt], ah[1], wh);
                mma_bf16(acc[0][nt], al[0], wh);
                mma_bf16(acc[1][nt], al[1], wh);
                mma_bf16(acc[0][nt], ah[0], wl);
                mma_bf16(acc[1][nt], ah[1], wl);
            }
        }
    }
    __syncthreads();

    // epilogue: bias, NCHW scatter to out channels [64, 96)
    const float* bsm = (const float*)(smem + BS);
    int g = lane >> 2, c0 = (lane & 3) * 2;
    int y = y0 + w;
#pragma unroll
    for (int mt = 0; mt < 2; mt++) {
#pragma unroll
        for (int half = 0; half < 2; half++) {
            int x = x0 + mt*16 + g + half*8;
            int pix = y*256 + x;
#pragma unroll
            for (int nt = 0; nt < 4; nt++) {
                int oc = nt*8 + c0;
                float v0 = acc[mt][nt][half*2 + 0] + bsm[oc];
                float v1 = acc[mt][nt][half*2 + 1] + bsm[oc + 1];
                out[(((size_t)(b*96 + 64 + oc)) << 16) + pix] = v0;
                out[(((size_t)(b*96 + 64 + oc + 1)) << 16) + pix] = v1;
            }
        }
    }
}

// ---------------- passthrough copy: out[:, 0:64] = feature -----------------
__global__ void copy_feat_kernel(const float4* __restrict__ f, float4* __restrict__ out)
{
    int i = blockIdx.x * 256 + threadIdx.x;
    if (i < 4194304) {
        int b = i >> 20;
        int rem = i & ((1 << 20) - 1);
        out[(size_t)b * 1572864 + rem] = f[i];
    }
}

// ---------------- launch ---------------------------------------------------
extern "C" void kernel_launch(void* const* d_in, const int* in_sizes, int n_in,
                              void* d_out, int out_size)
{
    const float* feature = (const float*)d_in[0];
    const float* rw1 = (const float*)d_in[1];
    const float* rb1 = (const float*)d_in[2];
    const float* rw2 = (const float*)d_in[3];
    const float* rb2 = (const float*)d_in[4];
    const float* fw1 = (const float*)d_in[5];
    const float* fb1 = (const float*)d_in[6];
    const float* fw2 = (const float*)d_in[7];
    const float* fb2 = (const float*)d_in[8];
    const float* fw3 = (const float*)d_in[9];
    const float* fb3 = (const float*)d_in[10];
    float* out = (float*)d_out;

    const int CONV1_SMEM = 92416 + 2304;
    const int DYN_SMEM = 83072;
    cudaFuncSetAttribute(conv1_hmma_kernel,
                         cudaFuncAttributeMaxDynamicSharedMemorySize, CONV1_SMEM);
    cudaFuncSetAttribute(dynconv_hmma_kernel,
                         cudaFuncAttributeMaxDynamicSharedMemorySize, DYN_SMEM);

    tohwc_kernel<<<4096, 256>>>(feature);
    wprep_kernel<<<144, 256>>>(rw1);
    conv1_hmma_kernel<<<dim3(8, 32, 4), 256, CONV1_SMEM>>>(rb1, rw2);
    conv2_sum_kernel<<<1024, 256>>>(rb2);
    pool_kernel<<<64, 256>>>();

    // FC1: 64x1024 @ 1024x2048, split-K 16
    gemm_sk_kernel<<<dim3(32, 16), 128>>>(fw1, 1024, 2048, 64, 0);
    gemm_reduce_kernel<<<(64*512 + 255)/256, 256>>>(fb1, 2048, 16, 1, 0);
    // FC2: 64x2048 @ 2048x2048, split-K 16
    gemm_sk_kernel<<<dim3(32, 16), 128>>>(fw2, 2048, 2048, 128, 1);
    gemm_reduce_kernel<<<(64*512 + 255)/256, 256>>>(fb2, 2048, 16, 1, 1);
    // FC3: 64x2048 @ 2048x18464, split-K 8
    gemm_sk_kernel<<<dim3(289, 8), 128>>>(fw3, 2048, 18464, 256, 2);
    gemm_reduce_kernel<<<(64*4616 + 255)/256, 256>>>(fb3, 18464, 8, 0, 2);

    dynconv_hmma_kernel<<<dim3(2, 8, 64), 256, DYN_SMEM>>>(out);
    copy_feat_kernel<<<16384, 256>>>((const float4*)feature, (float4*)out);
}

// round 8
// speedup vs baseline: 2.1153x; 1.1313x over previous
#include <cuda_runtime.h>
#include <cuda_bf16.h>
#include <cstdint>
#include <math.h>

// Problem constants
// B=4, C=64, H=W=256, N_SPLIT=4 (T=16), RED_FC=32, OUT_NC=32, K=3, FMN1=FMN2=2048
// wsize = 32*64*9 = 18432, wb row = 18464

typedef unsigned long long ull;

// ---------------- scratch (device globals; no runtime allocation) ----------
__device__ float g_u[9*4*65536];               // conv2 tap projections
__device__ float g_adap[4*256*256];            // tanh(conv2)
__device__ float g_gram[64*1024];              // pooled grams
__device__ float g_fc1[64*2048];
__device__ float g_fc2[64*2048];
__device__ float g_wb[64*18464];               // dynamic weights + bias
__device__ float g_part[9453568];              // split-K partials
__device__ __nv_bfloat16 g_fh[4*256*256*64];   // feature NHWC bf16 hi
__device__ __nv_bfloat16 g_fl[4*256*256*64];   // feature NHWC bf16 lo
__device__ __nv_bfloat16 g_w1h[9*64*64];       // rw1 [tap][oc][ic] hi
__device__ __nv_bfloat16 g_w1l[9*64*64];       // rw1 [tap][oc][ic] lo

// ---------------- mma.sync helpers (sm_80+ path, works on plain sm_103) ----
__device__ __forceinline__ uint32_t smem_u32(const void* p) {
    uint32_t a;
    asm("{ .reg .u64 t; cvta.to.shared.u64 t, %1; cvt.u32.u64 %0, t; }" : "=r"(a) : "l"(p));
    return a;
}
__device__ __forceinline__ void ldm_x4(uint32_t* r, uint32_t addr) {
    asm volatile("ldmatrix.sync.aligned.m8n8.x4.shared.b16 {%0,%1,%2,%3}, [%4];"
        : "=r"(r[0]), "=r"(r[1]), "=r"(r[2]), "=r"(r[3]) : "r"(addr));
}
__device__ __forceinline__ void ldm_x2(uint32_t* r, uint32_t addr) {
    asm volatile("ldmatrix.sync.aligned.m8n8.x2.shared.b16 {%0,%1}, [%2];"
        : "=r"(r[0]), "=r"(r[1]) : "r"(addr));
}
__device__ __forceinline__ void mma_bf16(float* d, const uint32_t* a, const uint32_t* b) {
    asm volatile(
        "mma.sync.aligned.m16n8k16.row.col.f32.bf16.bf16.f32 "
        "{%0,%1,%2,%3}, {%4,%5,%6,%7}, {%8,%9}, {%0,%1,%2,%3};"
        : "+f"(d[0]), "+f"(d[1]), "+f"(d[2]), "+f"(d[3])
        : "r"(a[0]), "r"(a[1]), "r"(a[2]), "r"(a[3]), "r"(b[0]), "r"(b[1]));
}
__device__ __forceinline__ void split_bf16(float v, __nv_bfloat16& hi, __nv_bfloat16& lo) {
    hi = __float2bfloat16_rn(v);
    lo = __float2bfloat16_rn(v - __bfloat162float(hi));
}

// ---------------- NCHW fp32 -> NHWC bf16 hi/lo -----------------------------
__global__ __launch_bounds__(256) void tohwc_kernel(const float* __restrict__ feat)
{
    __shared__ float s[64][65];
    int bx = blockIdx.x;
    int b = bx >> 10, grp = bx & 1023;
    int pix0 = grp * 64;
    int tid = threadIdx.x;
#pragma unroll
    for (int i = 0; i < 16; i++) {
        int idx = i * 256 + tid;
        int ic = idx >> 6, px = idx & 63;
        s[ic][px] = feat[(((size_t)(b*64 + ic)) << 16) + pix0 + px];
    }
    __syncthreads();
#pragma unroll
    for (int i = 0; i < 16; i++) {
        int idx = i * 256 + tid;
        int px = idx >> 6, ic = idx & 63;
        __nv_bfloat16 hi, lo;
        split_bf16(s[ic][px], hi, lo);
        size_t o = ((size_t)b*65536 + pix0 + px) * 64 + ic;
        g_fh[o] = hi; g_fl[o] = lo;
    }
}

// ---------------- rw1 -> [tap][oc][ic] bf16 hi/lo --------------------------
__global__ void wprep_kernel(const float* __restrict__ rw1)
{
    int idx = blockIdx.x * 256 + threadIdx.x;
    if (idx >= 9*64*64) return;
    int tap = idx >> 12, rem = idx & 4095;
    int oc = rem >> 6, ic = rem & 63;
    __nv_bfloat16 hi, lo;
    split_bf16(rw1[(oc*64 + ic)*9 + tap], hi, lo);
    g_w1h[idx] = hi; g_w1l[idx] = lo;
}

// ---------------- conv1 via mma.sync + fused conv2 tap projection ----------
// grid (8,32,4): x-tile (32 px), y-tile (8 rows), batch. block 256 (8 warps).
// Dyn smem: Ah[256][72] @0, Al @36864, Wh[64][72] @73728, Wl @82944,
//           bias @92160 (256 B), w2 @92416 (2304 B).
__global__ __launch_bounds__(256) void conv1_hmma_kernel(
    const float* __restrict__ rb1, const float* __restrict__ rw2)
{
    extern __shared__ char smem[];
    const uint32_t AH = 0, AL = 36864, WH = 73728, WL = 82944, BS = 92160, W2 = 92416;
    uint32_t sb = smem_u32(smem);
    int b = blockIdx.z;
    int y0 = blockIdx.y * 8, x0 = blockIdx.x * 32;
    int tid = threadIdx.x, w = tid >> 5, lane = tid & 31;

    if (tid < 64) *(float*)(smem + BS + tid*4) = rb1[tid];
    for (int i = tid; i < 576; i += 256) {
        int tap = i >> 6, ic = i & 63;
        *(float*)(smem + W2 + i*4) = rw2[ic*9 + tap];
    }

    float acc[2][8][4];
#pragma unroll
    for (int mt = 0; mt < 2; mt++)
#pragma unroll
        for (int nt = 0; nt < 8; nt++)
#pragma unroll
            for (int e = 0; e < 4; e++) acc[mt][nt][e] = 0.f;

    uint32_t a_row = lane & 15, a_k16 = (lane >> 4) * 16;
    uint32_t w_row = lane & 7,  w_k16 = ((lane >> 3) & 1) * 16;

    for (int tap = 0; tap < 9; tap++) {
        int dy = tap / 3 - 1, dx = tap % 3 - 1;
        __syncthreads();
#pragma unroll
        for (int j = 0; j < 8; j++) {
            int i = j * 256 + tid;
            int px = i >> 3, ch8 = i & 7;
            int gy = y0 + (px >> 5) + dy, gx = x0 + (px & 31) + dx;
            uint4 vh = {0,0,0,0}, vl = {0,0,0,0};
            if ((unsigned)gy < 256u && (unsigned)gx < 256u) {
                size_t g = ((size_t)(b*256 + gy)*256 + gx)*64 + ch8*8;
                vh = *(const uint4*)(g_fh + g);
                vl = *(const uint4*)(g_fl + g);
            }
            uint32_t off = (uint32_t)px*144 + ch8*16;
            *(uint4*)(smem + AH + off) = vh;
            *(uint4*)(smem + AL + off) = vl;
        }
#pragma unroll
        for (int j = 0; j < 2; j++) {
            int i = j * 256 + tid;
            int row = i >> 3, ch8 = i & 7;
            size_t g = ((size_t)tap*64 + row)*64 + ch8*8;
            uint4 vh = *(const uint4*)(g_w1h + g);
            uint4 vl = *(const uint4*)(g_w1l + g);
            uint32_t off = (uint32_t)row*144 + ch8*16;
            *(uint4*)(smem + WH + off) = vh;
            *(uint4*)(smem + WL + off) = vl;
        }
        __syncthreads();

#pragma unroll
        for (int ks = 0; ks < 4; ks++) {
            uint32_t ah[2][4], al[2][4];
#pragma unroll
            for (int mt = 0; mt < 2; mt++) {
                uint32_t aoff = (uint32_t)(w*32 + mt*16 + a_row)*144 + ks*32 + a_k16;
                ldm_x4(ah[mt], sb + AH + aoff);
                ldm_x4(al[mt], sb + AL + aoff);
            }
#pragma unroll
            for (int nt = 0; nt < 8; nt++) {
                uint32_t wh[2], wl[2];
                uint32_t woff = (uint32_t)(nt*8 + w_row)*144 + ks*32 + w_k16;
                ldm_x2(wh, sb + WH + woff);
                ldm_x2(wl, sb + WL + woff);
                mma_bf16(acc[0][nt], ah[0], wh);
                mma_bf16(acc[1][nt], ah[1], wh);
                mma_bf16(acc[0][nt], al[0], wh);
                mma_bf16(acc[1][nt], al[1], wh);
                mma_bf16(acc[0][nt], ah[0], wl);
                mma_bf16(acc[1][nt], ah[1], wl);
            }
        }
    }
    __syncthreads();

    // epilogue: bias + leaky relu, then 9 tap-dot projections (quad reduce)
    const float* bs = (const float*)(smem + BS);
    const float* w2 = (const float*)(smem + W2);
    int g = lane >> 2, c0 = (lane & 3) * 2;
    int y = y0 + w;
#pragma unroll
    for (int mt = 0; mt < 2; mt++) {
#pragma unroll
        for (int half = 0; half < 2; half++) {
            int x = x0 + mt*16 + g + half*8;
            float part[9];
#pragma unroll
            for (int t = 0; t < 9; t++) part[t] = 0.f;
#pragma unroll
            for (int nt = 0; nt < 8; nt++) {
                int oc = nt*8 + c0;
                float v0 = acc[mt][nt][half*2 + 0] + bs[oc];
                float v1 = acc[mt][nt][half*2 + 1] + bs[oc + 1];
                v0 = (v0 >= 0.f) ? v0 : 0.2f * v0;
                v1 = (v1 >= 0.f) ? v1 : 0.2f * v1;
#pragma unroll
                for (int t = 0; t < 9; t++)
                    part[t] += v0 * w2[t*64 + oc] + v1 * w2[t*64 + oc + 1];
            }
#pragma unroll
            for (int t = 0; t < 9; t++) {
                part[t] += __shfl_xor_sync(0xFFFFFFFFu, part[t], 1);
                part[t] += __shfl_xor_sync(0xFFFFFFFFu, part[t], 2);
            }
            if ((lane & 3) == 0) {
                int pix = y*256 + x;
#pragma unroll
                for (int t = 0; t < 9; t++)
                    g_u[t*262144 + b*65536 + pix] = part[t];
            }
        }
    }
}

// ---------------- conv2 sum: adap = tanh(sum of shifted taps + bias) -------
__global__ __launch_bounds__(256) void conv2_sum_kernel(const float* __restrict__ rb2)
{
    int P = blockIdx.x * 256 + threadIdx.x;
    int b = P >> 16, pix = P & 65535;
    int y = pix >> 8, x = pix & 255;
    float s = 0.f;
#pragma unroll
    for (int t = 0; t < 9; t++) {
        int yy = y + t/3 - 1, xx = x + t%3 - 1;
        if ((unsigned)yy < 256u && (unsigned)xx < 256u)
            s += g_u[t*262144 + b*65536 + yy*256 + xx];
    }
    g_adap[(size_t)b*65536 + pix] = tanhf(s + rb2[0]);
}

// ---------------- adaptive pool per tile -> gram ---------------------------
__global__ void pool_kernel()
{
    __shared__ float win[66][67];
    int r = blockIdx.x;
    int b = r >> 4, t = r & 15;
    int ti = t >> 2, tj = t & 3;
    int tid = threadIdx.x;
    for (int i = tid; i < 66*66; i += 256) {
        int h = i / 66, w = i % 66;
        int gy = ti*64 - 1 + h, gx = tj*64 - 1 + w;
        float v = 0.f;
        if ((unsigned)gy < 256u && (unsigned)gx < 256u)
            v = g_adap[((size_t)b*256 + gy) * 256 + gx];
        win[h][w] = v;
    }
    __syncthreads();
    for (int i = tid; i < 1024; i += 256) {
        int p = i >> 5, q = i & 31;
        int sp = (p*66) >> 5, ep = ((p+1)*66 + 31) >> 5;
        int sq = (q*66) >> 5, eq = ((q+1)*66 + 31) >> 5;
        float s = 0.f;
        for (int h = sp; h < ep; h++)
            for (int w = sq; w < eq; w++)
                s += win[h][w];
        g_gram[r*1024 + i] = s / (float)((ep - sp) * (eq - sq));
    }
}

// ---------------- HMMA split-K FC GEMM: part[s] = A(64xKC) @ B(KCxN64) -----
// grid (ceil(N/64), nsplit), block 256 (8 warps).
// Warp w: m16-tile mt = w>>1, n-half (w&1)*32. In-kernel fp32->bf16 hi/lo.
__global__ __launch_bounds__(256) void gemm_hmma_kernel(
    const float* __restrict__ Bm, int K, int N, int KC, int stage)
{
    const float* __restrict__ A = (stage == 0) ? g_gram : (stage == 1) ? g_fc1 : g_fc2;

    __shared__ __nv_bfloat16 Ah[64*24], Al[64*24];   // [m][k16] stride 24
    __shared__ __nv_bfloat16 Bh[64*24], Bl[64*24];   // [n][k16] stride 24 (transposed)

    int n0 = blockIdx.x * 64;
    int k0 = blockIdx.y * KC;
    int tid = threadIdx.x, w = tid >> 5, lane = tid & 31;
    int mt = w >> 1;                 // 0..3
    int nh = (w & 1) * 4;            // n8-tile base: 0 or 4

    float acc[4][4];
#pragma unroll
    for (int nt = 0; nt < 4; nt++)
#pragma unroll
        for (int e = 0; e < 4; e++) acc[nt][e] = 0.f;

    uint32_t a_row = lane & 15, a_k16 = (lane >> 4) * 16;   // bytes
    uint32_t w_row = lane & 7,  w_k16 = ((lane >> 3) & 1) * 16;
    uint32_t sAh = smem_u32(Ah), sAl = smem_u32(Al);
    uint32_t sBh = smem_u32(Bh), sBl = smem_u32(Bl);

    // per-thread load coords
    int am = tid >> 2, ak = (tid & 3) * 4;          // A: 64 x 16
    int bk = tid >> 4, bn = (tid & 15) * 4;         // B: 16 x 64

    for (int kc = 0; kc < KC; kc += 16) {
        int kb = k0 + kc;
        __syncthreads();
        {
            float4 va = *(const float4*)&A[(size_t)am * K + kb + ak];
            __nv_bfloat16 h, l;
            const float* vp = (const float*)&va;
#pragma unroll
            for (int j = 0; j < 4; j++) {
                split_bf16(vp[j], h, l);
                Ah[am*24 + ak + j] = h;
                Al[am*24 + ak + j] = l;
            }
        }
        {
            int col = n0 + bn;
            float4 vb = make_float4(0.f, 0.f, 0.f, 0.f);
            if (col < N) vb = *(const float4*)&Bm[(size_t)(kb + bk) * N + col];
            __nv_bfloat16 h, l;
            const float* vp = (const float*)&vb;
#pragma unroll
            for (int j = 0; j < 4; j++) {
                split_bf16(vp[j], h, l);
                Bh[(bn + j)*24 + bk] = h;
                Bl[(bn + j)*24 + bk] = l;
            }
        }
        __syncthreads();

        uint32_t ah[4], al[4];
        uint32_t aoff = (uint32_t)(mt*16 + a_row)*48 + a_k16;
        ldm_x4(ah, sAh + aoff);
        ldm_x4(al, sAl + aoff);
#pragma unroll
        for (int nt = 0; nt < 4; nt++) {
            uint32_t bhf[2], blf[2];
            uint32_t woff = (uint32_t)((nh + nt)*8 + w_row)*48 + w_k16;
            ldm_x2(bhf, sBh + woff);
            ldm_x2(blf, sBl + woff);
            mma_bf16(acc[nt], ah, bhf);
            mma_bf16(acc[nt], al, bhf);
            mma_bf16(acc[nt], ah, blf);
        }
    }

    int s = blockIdx.y;
    int g = lane >> 2, c0 = (lane & 3) * 2;
#pragma unroll
    for (int nt = 0; nt < 4; nt++) {
#pragma unroll
        for (int half = 0; half < 2; half++) {
            int row = mt*16 + g + half*8;
            int col = n0 + (nh + nt)*8 + c0;
            if (col < N) {
                float* p = &g_part[((size_t)(s*64 + row)) * N + col];
                p[0] = acc[nt][half*2 + 0];
                p[1] = acc[nt][half*2 + 1];
            }
        }
    }
}

// ---------------- split-K reduce + bias + activation -----------------------
__global__ void gemm_reduce_kernel(const float* __restrict__ bias,
                                   int N, int nsplit, int relu, int stage)
{
    float* out = (stage == 0) ? g_fc1 : (stage == 1) ? g_fc2 : g_wb;
    int nv = N >> 2;
    int idx = blockIdx.x * 256 + threadIdx.x;
    if (idx >= 64 * nv) return;
    int m = idx / nv, f = idx - m * nv;
    float4 s = make_float4(0.f, 0.f, 0.f, 0.f);
    for (int sp = 0; sp < nsplit; sp++) {
        const float4* p = (const float4*)&g_part[(size_t)(sp*64 + m) * N];
        float4 v = p[f];
        s.x += v.x; s.y += v.y; s.z += v.z; s.w += v.w;
    }
    float4 bv = ((const float4*)bias)[f];
    s.x += bv.x; s.y += bv.y; s.z += bv.z; s.w += bv.w;
    if (relu) {
        s.x = fmaxf(s.x, 0.f); s.y = fmaxf(s.y, 0.f);
        s.z = fmaxf(s.z, 0.f); s.w = fmaxf(s.w, 0.f);
    }
    ((float4*)out)[(size_t)m * nv + f] = s;
}

// ---------------- dynamic per-tile conv via mma.sync (64->32) --------------
// grid (2,8,64): bx x-half, by row-group, bz = r = b*16+t. block 256.
__global__ __launch_bounds__(256) void dynconv_hmma_kernel(float* __restrict__ out)
{
    extern __shared__ char smem[];
    const uint32_t AH = 0, AL = 36864, WH = 73728, WL = 78336, BS = 82944;
    uint32_t sb = smem_u32(smem);
    int r = blockIdx.z;
    int b = r >> 4, t = r & 15;
    int ti = t >> 2, tj = t & 3;
    int y0 = ti*64 + blockIdx.y * 8;
    int x0 = tj*64 + blockIdx.x * 32;
    int tid = threadIdx.x, w = tid >> 5, lane = tid & 31;

    const float* wrow = g_wb + (size_t)r * 18464;
    if (tid < 32) *(float*)(smem + BS + tid*4) = wrow[18432 + tid];

    float acc[2][4][4];
#pragma unroll
    for (int mt = 0; mt < 2; mt++)
#pragma unroll
        for (int nt = 0; nt < 4; nt++)
#pragma unroll
            for (int e = 0; e < 4; e++) acc[mt][nt][e] = 0.f;

    uint32_t a_row = lane & 15, a_k16 = (lane >> 4) * 16;
    uint32_t w_row = lane & 7,  w_k16 = ((lane >> 3) & 1) * 16;

    for (int tap = 0; tap < 9; tap++) {
        int dy = tap / 3 - 1, dx = tap % 3 - 1;
        __syncthreads();
#pragma unroll
        for (int j = 0; j < 8; j++) {
            int i = j * 256 + tid;
            int px = i >> 3, ch8 = i & 7;
            int gy = y0 + (px >> 5) + dy, gx = x0 + (px & 31) + dx;
            uint4 vh = {0,0,0,0}, vl = {0,0,0,0};
            if ((unsigned)gy < 256u && (unsigned)gx < 256u) {
                size_t g = ((size_t)(b*256 + gy)*256 + gx)*64 + ch8*8;
                vh = *(const uint4*)(g_fh + g);
                vl = *(const uint4*)(g_fl + g);
            }
            uint32_t off = (uint32_t)px*144 + ch8*16;
            *(uint4*)(smem + AH + off) = vh;
            *(uint4*)(smem + AL + off) = vl;
        }
#pragma unroll
        for (int j = 0; j < 8; j++) {
            int i = j * 256 + tid;
            int oc = i >> 6, ic = i & 63;
            __nv_bfloat16 hi, lo;
            split_bf16(wrow[(oc*64 + ic)*9 + tap], hi, lo);
            uint32_t off = (uint32_t)oc*144 + ic*2;
            *(__nv_bfloat16*)(smem + WH + off) = hi;
            *(__nv_bfloat16*)(smem + WL + off) = lo;
        }
        __syncthreads();

#pragma unroll
        for (int ks = 0; ks < 4; ks++) {
            uint32_t ah[2][4], al[2][4];
#pragma unroll
            for (int mt = 0; mt < 2; mt++) {
                uint32_t aoff = (uint32_t)(w*32 + mt*16 + a_row)*144 + ks*32 + a_k16;
                ldm_x4(ah[mt], sb + AH + aoff);
                ldm_x4(al[mt], sb + AL + aoff);
            }
#pragma unroll
            for (int nt = 0; nt < 4; nt++) {
                uint32_t wh[2], wl[2];
                uint32_t woff = (uint32_t)(nt*8 + w_row)*144 + ks*32 + w_k16;
                ldm_x2(wh, sb + WH + woff);
                ldm_x2(wl, sb + WL + woff);
                mma_bf16(acc[0][nt], ah[0], wh);
                mma_bf16(acc[1][nt], ah[1], wh);
                mma_bf16(acc[0][nt], al[0], wh);
                mma_bf16(acc[1][nt], al[1], wh);
                mma_bf16(acc[0][nt], ah[0], wl);
                mma_bf16(acc[1][nt], ah[1], wl);
            }
        }
    }
    __syncthreads();

    const float* bsm = (const float*)(smem + BS);
    int g = lane >> 2, c0 = (lane & 3) * 2;
    int y = y0 + w;
#pragma unroll
    for (int mt = 0; mt < 2; mt++) {
#pragma unroll
        for (int half = 0; half < 2; half++) {
            int x = x0 + mt*16 + g + half*8;
            int pix = y*256 + x;
#pragma unroll
            for (int nt = 0; nt < 4; nt++) {
                int oc = nt*8 + c0;
                float v0 = acc[mt][nt][half*2 + 0] + bsm[oc];
                float v1 = acc[mt][nt][half*2 + 1] + bsm[oc + 1];
                out[(((size_t)(b*96 + 64 + oc)) << 16) + pix] = v0;
                out[(((size_t)(b*96 + 64 + oc + 1)) << 16) + pix] = v1;
            }
        }
    }
}

// ---------------- passthrough copy: out[:, 0:64] = feature -----------------
__global__ void copy_feat_kernel(const float4* __restrict__ f, float4* __restrict__ out)
{
    int i = blockIdx.x * 256 + threadIdx.x;
    if (i < 4194304) {
        int b = i >> 20;
        int rem = i & ((1 << 20) - 1);
        out[(size_t)b * 1572864 + rem] = f[i];
    }
}

// ---------------- launch ---------------------------------------------------
extern "C" void kernel_launch(void* const* d_in, const int* in_sizes, int n_in,
                              void* d_out, int out_size)
{
    const float* feature = (const float*)d_in[0];
    const float* rw1 = (const float*)d_in[1];
    const float* rb1 = (const float*)d_in[2];
    const float* rw2 = (const float*)d_in[3];
    const float* rb2 = (const float*)d_in[4];
    const float* fw1 = (const float*)d_in[5];
    const float* fb1 = (const float*)d_in[6];
    const float* fw2 = (const float*)d_in[7];
    const float* fb2 = (const float*)d_in[8];
    const float* fw3 = (const float*)d_in[9];
    const float* fb3 = (const float*)d_in[10];
    float* out = (float*)d_out;

    const int CONV1_SMEM = 92416 + 2304;
    const int DYN_SMEM = 83072;
    cudaFuncSetAttribute(conv1_hmma_kernel,
                         cudaFuncAttributeMaxDynamicSharedMemorySize, CONV1_SMEM);
    cudaFuncSetAttribute(dynconv_hmma_kernel,
                         cudaFuncAttributeMaxDynamicSharedMemorySize, DYN_SMEM);

    tohwc_kernel<<<4096, 256>>>(feature);
    wprep_kernel<<<144, 256>>>(rw1);
    conv1_hmma_kernel<<<dim3(8, 32, 4), 256, CONV1_SMEM>>>(rb1, rw2);
    conv2_sum_kernel<<<1024, 256>>>(rb2);
    pool_kernel<<<64, 256>>>();

    // FC1: 64x1024 @ 1024x2048, split-K 16 (HMMA)
    gemm_hmma_kernel<<<dim3(32, 16), 256>>>(fw1, 1024, 2048, 64, 0);
    gemm_reduce_kernel<<<(64*512 + 255)/256, 256>>>(fb1, 2048, 16, 1, 0);
    // FC2: 64x2048 @ 2048x2048, split-K 16 (HMMA)
    gemm_hmma_kernel<<<dim3(32, 16), 256>>>(fw2, 2048, 2048, 128, 1);
    gemm_reduce_kernel<<<(64*512 + 255)/256, 256>>>(fb2, 2048, 16, 1, 1);
    // FC3: 64x2048 @ 2048x18464, split-K 8 (HMMA)
    gemm_hmma_kernel<<<dim3(289, 8), 256>>>(fw3, 2048, 18464, 256, 2);
    gemm_reduce_kernel<<<(64*4616 + 255)/256, 256>>>(fb3, 18464, 8, 0, 2);

    dynconv_hmma_kernel<<<dim3(2, 8, 64), 256, DYN_SMEM>>>(out);
    copy_feat_kernel<<<16384, 256>>>((const float4*)feature, (float4*)out);
}

// round 9
// speedup vs baseline: 2.2462x; 1.0619x over previous
#include <cuda_runtime.h>
#include <cuda_bf16.h>
#include <cstdint>
#include <math.h>

// Problem constants
// B=4, C=64, H=W=256, N_SPLIT=4 (T=16), RED_FC=32, OUT_NC=32, K=3, FMN1=FMN2=2048
// wsize = 32*64*9 = 18432, wb row = 18464

typedef unsigned long long ull;

// ---------------- scratch (device globals; no runtime allocation) ----------
__device__ float g_u[9*4*65536];               // conv2 tap projections
__device__ float g_adap[4*256*256];            // tanh(conv2)
__device__ float g_gram[64*1024];              // pooled grams
__device__ float g_fc1[64*2048];
__device__ float g_fc2[64*2048];
__device__ float g_wb[64*18464];               // dynamic weights + bias
__device__ float g_part[9453568];              // split-K partials
__device__ __nv_bfloat16 g_fh[4*256*256*64];   // feature NHWC bf16 hi
__device__ __nv_bfloat16 g_fl[4*256*256*64];   // feature NHWC bf16 lo
__device__ __nv_bfloat16 g_w1h[9*64*64];       // rw1 [tap][oc][ic] hi
__device__ __nv_bfloat16 g_w1l[9*64*64];       // rw1 [tap][oc][ic] lo

// ---------------- mma.sync helpers (sm_80+ path, works on plain sm_103) ----
__device__ __forceinline__ uint32_t smem_u32(const void* p) {
    uint32_t a;
    asm("{ .reg .u64 t; cvta.to.shared.u64 t, %1; cvt.u32.u64 %0, t; }" : "=r"(a) : "l"(p));
    return a;
}
__device__ __forceinline__ void ldm_x4(uint32_t* r, uint32_t addr) {
    asm volatile("ldmatrix.sync.aligned.m8n8.x4.shared.b16 {%0,%1,%2,%3}, [%4];"
        : "=r"(r[0]), "=r"(r[1]), "=r"(r[2]), "=r"(r[3]) : "r"(addr));
}
__device__ __forceinline__ void ldm_x2(uint32_t* r, uint32_t addr) {
    asm volatile("ldmatrix.sync.aligned.m8n8.x2.shared.b16 {%0,%1}, [%2];"
        : "=r"(r[0]), "=r"(r[1]) : "r"(addr));
}
__device__ __forceinline__ void mma_bf16(float* d, const uint32_t* a, const uint32_t* b) {
    asm volatile(
        "mma.sync.aligned.m16n8k16.row.col.f32.bf16.bf16.f32 "
        "{%0,%1,%2,%3}, {%4,%5,%6,%7}, {%8,%9}, {%0,%1,%2,%3};"
        : "+f"(d[0]), "+f"(d[1]), "+f"(d[2]), "+f"(d[3])
        : "r"(a[0]), "r"(a[1]), "r"(a[2]), "r"(a[3]), "r"(b[0]), "r"(b[1]));
}
__device__ __forceinline__ void split_bf16(float v, __nv_bfloat16& hi, __nv_bfloat16& lo) {
    hi = __float2bfloat16_rn(v);
    lo = __float2bfloat16_rn(v - __bfloat162float(hi));
}

// ---------------- NCHW fp32 -> NHWC bf16 hi/lo -----------------------------
__global__ __launch_bounds__(256) void tohwc_kernel(const float* __restrict__ feat)
{
    __shared__ float s[64][65];
    int bx = blockIdx.x;
    int b = bx >> 10, grp = bx & 1023;
    int pix0 = grp * 64;
    int tid = threadIdx.x;
#pragma unroll
    for (int i = 0; i < 16; i++) {
        int idx = i * 256 + tid;
        int ic = idx >> 6, px = idx & 63;
        s[ic][px] = feat[(((size_t)(b*64 + ic)) << 16) + pix0 + px];
    }
    __syncthreads();
#pragma unroll
    for (int i = 0; i < 16; i++) {
        int idx = i * 256 + tid;
        int px = idx >> 6, ic = idx & 63;
        __nv_bfloat16 hi, lo;
        split_bf16(s[ic][px], hi, lo);
        size_t o = ((size_t)b*65536 + pix0 + px) * 64 + ic;
        g_fh[o] = hi; g_fl[o] = lo;
    }
}

// ---------------- rw1 -> [tap][oc][ic] bf16 hi/lo --------------------------
__global__ void wprep_kernel(const float* __restrict__ rw1)
{
    int idx = blockIdx.x * 256 + threadIdx.x;
    if (idx >= 9*64*64) return;
    int tap = idx >> 12, rem = idx & 4095;
    int oc = rem >> 6, ic = rem & 63;
    __nv_bfloat16 hi, lo;
    split_bf16(rw1[(oc*64 + ic)*9 + tap], hi, lo);
    g_w1h[idx] = hi; g_w1l[idx] = lo;
}

// ---------------- conv1 via mma.sync, halo-A + fused conv2 projection ------
// grid (8,32,4): x-tile (32 px), y-tile (8 rows), batch. block 256 (8 warps).
// Halo A tile (10x34 px, 64 ic, hi+lo) built ONCE; taps = row offsets.
// Dyn smem: AH @0 (48960), AL @48960, W bufs @97920 (2 x (9216 hi + 9216 lo)),
//           bias @134784 (256), w2 @135040 (2304). Total 137344.
__global__ __launch_bounds__(256) void conv1_hmma_kernel(
    const float* __restrict__ rb1, const float* __restrict__ rw2)
{
    extern __shared__ char smem[];
    const uint32_t AH = 0, AL = 48960, WB = 97920, BS = 134784, W2 = 135040;
    uint32_t sb = smem_u32(smem);
    int b = blockIdx.z;
    int y0 = blockIdx.y * 8, x0 = blockIdx.x * 32;
    int tid = threadIdx.x, w = tid >> 5, lane = tid & 31;

    if (tid < 64) *(float*)(smem + BS + tid*4) = rb1[tid];
    for (int i = tid; i < 576; i += 256) {
        int tap = i >> 6, ic = i & 63;
        *(float*)(smem + W2 + i*4) = rw2[ic*9 + tap];
    }

    // build halo A once: 340 rows (10x34 px) x 64 ic, hi+lo
    for (int i = tid; i < 2720; i += 256) {
        int hp = i >> 3, ch8 = i & 7;
        int hy = hp / 34, hx = hp - hy*34;
        int gy = y0 - 1 + hy, gx = x0 - 1 + hx;
        uint4 vh = {0,0,0,0}, vl = {0,0,0,0};
        if ((unsigned)gy < 256u && (unsigned)gx < 256u) {
            size_t g = ((size_t)(b*256 + gy)*256 + gx)*64 + ch8*8;
            vh = *(const uint4*)(g_fh + g);
            vl = *(const uint4*)(g_fl + g);
        }
        uint32_t off = (uint32_t)hp*144 + ch8*16;
        *(uint4*)(smem + AH + off) = vh;
        *(uint4*)(smem + AL + off) = vl;
    }
    // preload W tap 0 into buf 0
    {
        int row = tid >> 3, ch8 = tid & 7;        // 0..511 -> 64 rows x 8
        int i2 = 256 + tid;
        int row2 = i2 >> 3, ch82 = i2 & 7;
        size_t g1 = (size_t)row*64 + ch8*8;
        size_t g2 = (size_t)row2*64 + ch82*8;
        uint4 h1 = *(const uint4*)(g_w1h + g1);
        uint4 l1 = *(const uint4*)(g_w1l + g1);
        uint4 h2 = *(const uint4*)(g_w1h + g2);
        uint4 l2 = *(const uint4*)(g_w1l + g2);
        *(uint4*)(smem + WB + row*144 + ch8*16) = h1;
        *(uint4*)(smem + WB + 9216 + row*144 + ch8*16) = l1;
        *(uint4*)(smem + WB + row2*144 + ch82*16) = h2;
        *(uint4*)(smem + WB + 9216 + row2*144 + ch82*16) = l2;
    }
    __syncthreads();

    float acc[2][8][4];
#pragma unroll
    for (int mt = 0; mt < 2; mt++)
#pragma unroll
        for (int nt = 0; nt < 8; nt++)
#pragma unroll
            for (int e = 0; e < 4; e++) acc[mt][nt][e] = 0.f;

    uint32_t a_row = lane & 15, a_k16 = (lane >> 4) * 16;
    uint32_t w_row = lane & 7,  w_k16 = ((lane >> 3) & 1) * 16;
    int pr_row1 = tid >> 3, pr_ch1 = tid & 7;
    int pr_row2 = (256 + tid) >> 3, pr_ch2 = (256 + tid) & 7;

    for (int tap = 0; tap < 9; tap++) {
        int dy = tap / 3 - 1, dx = tap % 3 - 1;
        int buf = tap & 1;
        uint32_t wbase = WB + buf*18432;

        // prefetch next tap's W into regs
        uint4 ph1, pl1, ph2, pl2;
        if (tap < 8) {
            size_t gb = (size_t)(tap + 1)*4096;
            ph1 = *(const uint4*)(g_w1h + gb + pr_row1*64 + pr_ch1*8);
            pl1 = *(const uint4*)(g_w1l + gb + pr_row1*64 + pr_ch1*8);
            ph2 = *(const uint4*)(g_w1h + gb + pr_row2*64 + pr_ch2*8);
            pl2 = *(const uint4*)(g_w1l + gb + pr_row2*64 + pr_ch2*8);
        }

        int rb = (w + dy + 1)*34 + dx + 1;    // halo row base for this warp/tap
#pragma unroll
        for (int ks = 0; ks < 4; ks++) {
            uint32_t ah[2][4], al[2][4];
#pragma unroll
            for (int mt = 0; mt < 2; mt++) {
                uint32_t aoff = (uint32_t)(rb + mt*16 + a_row)*144 + ks*32 + a_k16;
                ldm_x4(ah[mt], sb + AH + aoff);
                ldm_x4(al[mt], sb + AL + aoff);
            }
#pragma unroll
            for (int nt = 0; nt < 8; nt++) {
                uint32_t wh[2], wl[2];
                uint32_t woff = (uint32_t)(nt*8 + w_row)*144 + ks*32 + w_k16;
                ldm_x2(wh, sb + wbase + woff);
                ldm_x2(wl, sb + wbase + 9216 + woff);
                mma_bf16(acc[0][nt], ah[0], wh);
                mma_bf16(acc[1][nt], ah[1], wh);
                mma_bf16(acc[0][nt], al[0], wh);
                mma_bf16(acc[1][nt], al[1], wh);
                mma_bf16(acc[0][nt], ah[0], wl);
                mma_bf16(acc[1][nt], ah[1], wl);
            }
        }

        if (tap < 8) {
            uint32_t nb = WB + (buf ^ 1)*18432;
            *(uint4*)(smem + nb + pr_row1*144 + pr_ch1*16) = ph1;
            *(uint4*)(smem + nb + 9216 + pr_row1*144 + pr_ch1*16) = pl1;
            *(uint4*)(smem + nb + pr_row2*144 + pr_ch2*16) = ph2;
            *(uint4*)(smem + nb + 9216 + pr_row2*144 + pr_ch2*16) = pl2;
        }
        __syncthreads();
    }

    // epilogue: bias + leaky relu, then 9 tap-dot projections (quad reduce)
    const float* bs = (const float*)(smem + BS);
    const float* w2 = (const float*)(smem + W2);
    int g = lane >> 2, c0 = (lane & 3) * 2;
    int y = y0 + w;
#pragma unroll
    for (int mt = 0; mt < 2; mt++) {
#pragma unroll
        for (int half = 0; half < 2; half++) {
            int x = x0 + mt*16 + g + half*8;
            float part[9];
#pragma unroll
            for (int t = 0; t < 9; t++) part[t] = 0.f;
#pragma unroll
            for (int nt = 0; nt < 8; nt++) {
                int oc = nt*8 + c0;
                float v0 = acc[mt][nt][half*2 + 0] + bs[oc];
                float v1 = acc[mt][nt][half*2 + 1] + bs[oc + 1];
                v0 = (v0 >= 0.f) ? v0 : 0.2f * v0;
                v1 = (v1 >= 0.f) ? v1 : 0.2f * v1;
#pragma unroll
                for (int t = 0; t < 9; t++)
                    part[t] += v0 * w2[t*64 + oc] + v1 * w2[t*64 + oc + 1];
            }
#pragma unroll
            for (int t = 0; t < 9; t++) {
                part[t] += __shfl_xor_sync(0xFFFFFFFFu, part[t], 1);
                part[t] += __shfl_xor_sync(0xFFFFFFFFu, part[t], 2);
            }
            if ((lane & 3) == 0) {
                int pix = y*256 + x;
#pragma unroll
                for (int t = 0; t < 9; t++)
                    g_u[t*262144 + b*65536 + pix] = part[t];
            }
        }
    }
}

// ---------------- conv2 sum: adap = tanh(sum of shifted taps + bias) -------
__global__ __launch_bounds__(256) void conv2_sum_kernel(const float* __restrict__ rb2)
{
    int P = blockIdx.x * 256 + threadIdx.x;
    int b = P >> 16, pix = P & 65535;
    int y = pix >> 8, x = pix & 255;
    float s = 0.f;
#pragma unroll
    for (int t = 0; t < 9; t++) {
        int yy = y + t/3 - 1, xx = x + t%3 - 1;
        if ((unsigned)yy < 256u && (unsigned)xx < 256u)
            s += g_u[t*262144 + b*65536 + yy*256 + xx];
    }
    g_adap[(size_t)b*65536 + pix] = tanhf(s + rb2[0]);
}

// ---------------- adaptive pool per tile -> gram ---------------------------
__global__ void pool_kernel()
{
    __shared__ float win[66][67];
    int r = blockIdx.x;
    int b = r >> 4, t = r & 15;
    int ti = t >> 2, tj = t & 3;
    int tid = threadIdx.x;
    for (int i = tid; i < 66*66; i += 256) {
        int h = i / 66, w = i % 66;
        int gy = ti*64 - 1 + h, gx = tj*64 - 1 + w;
        float v = 0.f;
        if ((unsigned)gy < 256u && (unsigned)gx < 256u)
            v = g_adap[((size_t)b*256 + gy) * 256 + gx];
        win[h][w] = v;
    }
    __syncthreads();
    for (int i = tid; i < 1024; i += 256) {
        int p = i >> 5, q = i & 31;
        int sp = (p*66) >> 5, ep = ((p+1)*66 + 31) >> 5;
        int sq = (q*66) >> 5, eq = ((q+1)*66 + 31) >> 5;
        float s = 0.f;
        for (int h = sp; h < ep; h++)
            for (int w = sq; w < eq; w++)
                s += win[h][w];
        g_gram[r*1024 + i] = s / (float)((ep - sp) * (eq - sq));
    }
}

// ---------------- HMMA split-K FC GEMM: part[s] = A(64xKC) @ B(KCxN64) -----
__global__ __launch_bounds__(256) void gemm_hmma_kernel(
    const float* __restrict__ Bm, int K, int N, int KC, int stage)
{
    const float* __restrict__ A = (stage == 0) ? g_gram : (stage == 1) ? g_fc1 : g_fc2;

    __shared__ __nv_bfloat16 Ah[64*24], Al[64*24];
    __shared__ __nv_bfloat16 Bh[64*24], Bl[64*24];

    int n0 = blockIdx.x * 64;
    int k0 = blockIdx.y * KC;
    int tid = threadIdx.x, w = tid >> 5, lane = tid & 31;
    int mt = w >> 1;
    int nh = (w & 1) * 4;

    float acc[4][4];
#pragma unroll
    for (int nt = 0; nt < 4; nt++)
#pragma unroll
        for (int e = 0; e < 4; e++) acc[nt][e] = 0.f;

    uint32_t a_row = lane & 15, a_k16 = (lane >> 4) * 16;
    uint32_t w_row = lane & 7,  w_k16 = ((lane >> 3) & 1) * 16;
    uint32_t sAh = smem_u32(Ah), sAl = smem_u32(Al);
    uint32_t sBh = smem_u32(Bh), sBl = smem_u32(Bl);

    int am = tid >> 2, ak = (tid & 3) * 4;
    int bk = tid >> 4, bn = (tid & 15) * 4;

    for (int kc = 0; kc < KC; kc += 16) {
        int kb = k0 + kc;
        __syncthreads();
        {
            float4 va = *(const float4*)&A[(size_t)am * K + kb + ak];
            __nv_bfloat16 h, l;
            const float* vp = (const float*)&va;
#pragma unroll
            for (int j = 0; j < 4; j++) {
                split_bf16(vp[j], h, l);
                Ah[am*24 + ak + j] = h;
                Al[am*24 + ak + j] = l;
            }
        }
        {
            int col = n0 + bn;
            float4 vb = make_float4(0.f, 0.f, 0.f, 0.f);
            if (col < N) vb = *(const float4*)&Bm[(size_t)(kb + bk) * N + col];
            __nv_bfloat16 h, l;
            const float* vp = (const float*)&vb;
#pragma unroll
            for (int j = 0; j < 4; j++) {
                split_bf16(vp[j], h, l);
                Bh[(bn + j)*24 + bk] = h;
                Bl[(bn + j)*24 + bk] = l;
            }
        }
        __syncthreads();

        uint32_t ah[4], al[4];
        uint32_t aoff = (uint32_t)(mt*16 + a_row)*48 + a_k16;
        ldm_x4(ah, sAh + aoff);
        ldm_x4(al, sAl + aoff);
#pragma unroll
        for (int nt = 0; nt < 4; nt++) {
            uint32_t bhf[2], blf[2];
            uint32_t woff = (uint32_t)((nh + nt)*8 + w_row)*48 + w_k16;
            ldm_x2(bhf, sBh + woff);
            ldm_x2(blf, sBl + woff);
            mma_bf16(acc[nt], ah, bhf);
            mma_bf16(acc[nt], al, bhf);
            mma_bf16(acc[nt], ah, blf);
        }
    }

    int s = blockIdx.y;
    int g = lane >> 2, c0 = (lane & 3) * 2;
#pragma unroll
    for (int nt = 0; nt < 4; nt++) {
#pragma unroll
        for (int half = 0; half < 2; half++) {
            int row = mt*16 + g + half*8;
            int col = n0 + (nh + nt)*8 + c0;
            if (col < N) {
                float* p = &g_part[((size_t)(s*64 + row)) * N + col];
                p[0] = acc[nt][half*2 + 0];
                p[1] = acc[nt][half*2 + 1];
            }
        }
    }
}

// ---------------- split-K reduce + bias + activation -----------------------
__global__ void gemm_reduce_kernel(const float* __restrict__ bias,
                                   int N, int nsplit, int relu, int stage)
{
    float* out = (stage == 0) ? g_fc1 : (stage == 1) ? g_fc2 : g_wb;
    int nv = N >> 2;
    int idx = blockIdx.x * 256 + threadIdx.x;
    if (idx >= 64 * nv) return;
    int m = idx / nv, f = idx - m * nv;
    float4 s = make_float4(0.f, 0.f, 0.f, 0.f);
    for (int sp = 0; sp < nsplit; sp++) {
        const float4* p = (const float4*)&g_part[(size_t)(sp*64 + m) * N];
        float4 v = p[f];
        s.x += v.x; s.y += v.y; s.z += v.z; s.w += v.w;
    }
    float4 bv = ((const float4*)bias)[f];
    s.x += bv.x; s.y += bv.y; s.z += bv.z; s.w += bv.w;
    if (relu) {
        s.x = fmaxf(s.x, 0.f); s.y = fmaxf(s.y, 0.f);
        s.z = fmaxf(s.z, 0.f); s.w = fmaxf(s.w, 0.f);
    }
    ((float4*)out)[(size_t)m * nv + f] = s;
}

// ---------------- dynamic per-tile conv via mma.sync, halo-A ---------------
// grid (2,8,64): bx x-half, by row-group, bz = r = b*16+t. block 256.
// Dyn smem: AH @0 (48960), AL @48960, W bufs @97920 (2 x (4608 hi + 4608 lo)),
//           bias @116352 (128). Total 116480.
__global__ __launch_bounds__(256) void dynconv_hmma_kernel(float* __restrict__ out)
{
    extern __shared__ char smem[];
    const uint32_t AH = 0, AL = 48960, WB = 97920, BS = 116352;
    uint32_t sb = smem_u32(smem);
    int r = blockIdx.z;
    int b = r >> 4, t = r & 15;
    int ti = t >> 2, tj = t & 3;
    int y0 = ti*64 + blockIdx.y * 8;
    int x0 = tj*64 + blockIdx.x * 32;
    int tid = threadIdx.x, w = tid >> 5, lane = tid & 31;

    const float* wrow = g_wb + (size_t)r * 18464;
    if (tid < 32) *(float*)(smem + BS + tid*4) = wrow[18432 + tid];

    // build halo A once
    for (int i = tid; i < 2720; i += 256) {
        int hp = i >> 3, ch8 = i & 7;
        int hy = hp / 34, hx = hp - hy*34;
        int gy = y0 - 1 + hy, gx = x0 - 1 + hx;
        uint4 vh = {0,0,0,0}, vl = {0,0,0,0};
        if ((unsigned)gy < 256u && (unsigned)gx < 256u) {
            size_t g = ((size_t)(b*256 + gy)*256 + gx)*64 + ch8*8;
            vh = *(const uint4*)(g_fh + g);
            vl = *(const uint4*)(g_fl + g);
        }
        uint32_t off = (uint32_t)hp*144 + ch8*16;
        *(uint4*)(smem + AH + off) = vh;
        *(uint4*)(smem + AL + off) = vl;
    }
    // preload W tap 0 into buf 0: 32 oc x 64 ic, 8 scalars per thread
    {
        int oc = tid >> 3, icg = (tid & 7) * 8;
#pragma unroll
        for (int j = 0; j < 8; j++) {
            __nv_bfloat16 hi, lo;
            split_bf16(wrow[(oc*64 + icg + j)*9 + 0], hi, lo);
            uint32_t off = (uint32_t)oc*144 + (icg + j)*2;
            *(__nv_bfloat16*)(smem + WB + off) = hi;
            *(__nv_bfloat16*)(smem + WB + 4608 + off) = lo;
        }
    }
    __syncthreads();

    float acc[2][4][4];
#pragma unroll
    for (int mt = 0; mt < 2; mt++)
#pragma unroll
        for (int nt = 0; nt < 4; nt++)
#pragma unroll
            for (int e = 0; e < 4; e++) acc[mt][nt][e] = 0.f;

    uint32_t a_row = lane & 15, a_k16 = (lane >> 4) * 16;
    uint32_t w_row = lane & 7,  w_k16 = ((lane >> 3) & 1) * 16;
    int pr_oc = tid >> 3, pr_icg = (tid & 7) * 8;

    for (int tap = 0; tap < 9; tap++) {
        int dy = tap / 3 - 1, dx = tap % 3 - 1;
        int buf = tap & 1;
        uint32_t wbase = WB + buf*9216;

        float pre[8];
        if (tap < 8) {
#pragma unroll
            for (int j = 0; j < 8; j++)
                pre[j] = wrow[(pr_oc*64 + pr_icg + j)*9 + tap + 1];
        }

        int rb = (w + dy + 1)*34 + dx + 1;
#pragma unroll
        for (int ks = 0; ks < 4; ks++) {
            uint32_t ah[2][4], al[2][4];
#pragma unroll
            for (int mt = 0; mt < 2; mt++) {
                uint32_t aoff = (uint32_t)(rb + mt*16 + a_row)*144 + ks*32 + a_k16;
                ldm_x4(ah[mt], sb + AH + aoff);
                ldm_x4(al[mt], sb + AL + aoff);
            }
#pragma unroll
            for (int nt = 0; nt < 4; nt++) {
                uint32_t wh[2], wl[2];
                uint32_t woff = (uint32_t)(nt*8 + w_row)*144 + ks*32 + w_k16;
                ldm_x2(wh, sb + wbase + woff);
                ldm_x2(wl, sb + wbase + 4608 + woff);
                mma_bf16(acc[0][nt], ah[0], wh);
                mma_bf16(acc[1][nt], ah[1], wh);
                mma_bf16(acc[0][nt], al[0], wh);
                mma_bf16(acc[1][nt], al[1], wh);
                mma_bf16(acc[0][nt], ah[0], wl);
                mma_bf16(acc[1][nt], ah[1], wl);
            }
        }

        if (tap < 8) {
            uint32_t nb = WB + (buf ^ 1)*9216;
#pragma unroll
            for (int j = 0; j < 8; j++) {
                __nv_bfloat16 hi, lo;
                split_bf16(pre[j], hi, lo);
                uint32_t off = (uint32_t)pr_oc*144 + (pr_icg + j)*2;
                *(__nv_bfloat16*)(smem + nb + off) = hi;
                *(__nv_bfloat16*)(smem + nb + 4608 + off) = lo;
            }
        }
        __syncthreads();
    }

    const float* bsm = (const float*)(smem + BS);
    int g = lane >> 2, c0 = (lane & 3) * 2;
    int y = y0 + w;
#pragma unroll
    for (int mt = 0; mt < 2; mt++) {
#pragma unroll
        for (int half = 0; half < 2; half++) {
            int x = x0 + mt*16 + g + half*8;
            int pix = y*256 + x;
#pragma unroll
            for (int nt = 0; nt < 4; nt++) {
                int oc = nt*8 + c0;
                float v0 = acc[mt][nt][half*2 + 0] + bsm[oc];
                float v1 = acc[mt][nt][half*2 + 1] + bsm[oc + 1];
                out[(((size_t)(b*96 + 64 + oc)) << 16) + pix] = v0;
                out[(((size_t)(b*96 + 64 + oc + 1)) << 16) + pix] = v1;
            }
        }
    }
}

// ---------------- passthrough copy: out[:, 0:64] = feature -----------------
__global__ void copy_feat_kernel(const float4* __restrict__ f, float4* __restrict__ out)
{
    int i = blockIdx.x * 256 + threadIdx.x;
    if (i < 4194304) {
        int b = i >> 20;
        int rem = i & ((1 << 20) - 1);
        out[(size_t)b * 1572864 + rem] = f[i];
    }
}

// ---------------- launch ---------------------------------------------------
extern "C" void kernel_launch(void* const* d_in, const int* in_sizes, int n_in,
                              void* d_out, int out_size)
{
    const float* feature = (const float*)d_in[0];
    const float* rw1 = (const float*)d_in[1];
    const float* rb1 = (const float*)d_in[2];
    const float* rw2 = (const float*)d_in[3];
    const float* rb2 = (const float*)d_in[4];
    const float* fw1 = (const float*)d_in[5];
    const float* fb1 = (const float*)d_in[6];
    const float* fw2 = (const float*)d_in[7];
    const float* fb2 = (const float*)d_in[8];
    const float* fw3 = (const float*)d_in[9];
    const float* fb3 = (const float*)d_in[10];
    float* out = (float*)d_out;

    const int CONV1_SMEM = 137344;
    const int DYN_SMEM = 116480;
    cudaFuncSetAttribute(conv1_hmma_kernel,
                         cudaFuncAttributeMaxDynamicSharedMemorySize, CONV1_SMEM);
    cudaFuncSetAttribute(dynconv_hmma_kernel,
                         cudaFuncAttributeMaxDynamicSharedMemorySize, DYN_SMEM);

    tohwc_kernel<<<4096, 256>>>(feature);
    wprep_kernel<<<144, 256>>>(rw1);
    conv1_hmma_kernel<<<dim3(8, 32, 4), 256, CONV1_SMEM>>>(rb1, rw2);
    conv2_sum_kernel<<<1024, 256>>>(rb2);
    pool_kernel<<<64, 256>>>();

    // FC1: 64x1024 @ 1024x2048, split-K 16 (HMMA)
    gemm_hmma_kernel<<<dim3(32, 16), 256>>>(fw1, 1024, 2048, 64, 0);
    gemm_reduce_kernel<<<(64*512 + 255)/256, 256>>>(fb1, 2048, 16, 1, 0);
    // FC2: 64x2048 @ 2048x2048, split-K 16 (HMMA)
    gemm_hmma_kernel<<<dim3(32, 16), 256>>>(fw2, 2048, 2048, 128, 1);
    gemm_reduce_kernel<<<(64*512 + 255)/256, 256>>>(fb2, 2048, 16, 1, 1);
    // FC3: 64x2048 @ 2048x18464, split-K 8 (HMMA)
    gemm_hmma_kernel<<<dim3(289, 8), 256>>>(fw3, 2048, 18464, 256, 2);
    gemm_reduce_kernel<<<(64*4616 + 255)/256, 256>>>(fb3, 18464, 8, 0, 2);

    dynconv_hmma_kernel<<<dim3(2, 8, 64), 256, DYN_SMEM>>>(out);
    copy_feat_kernel<<<16384, 256>>>((const float4*)feature, (float4*)out);
}

// round 10
// speedup vs baseline: 2.4079x; 1.0720x over previous
#include <cuda_runtime.h>
#include <cuda_bf16.h>
#include <cstdint>
#include <math.h>

// Problem constants
// B=4, C=64, H=W=256, N_SPLIT=4 (T=16), RED_FC=32, OUT_NC=32, K=3, FMN1=FMN2=2048
// wsize = 32*64*9 = 18432, wb row = 18464

typedef unsigned long long ull;

// ---------------- scratch (device globals; no runtime allocation) ----------
__device__ float g_u[9*4*65536];               // conv2 tap projections
__device__ float g_gram[64*1024];              // pooled grams
__device__ float g_fc1[64*2048];
__device__ float g_fc2[64*2048];
__device__ float g_wb[64*18464];               // dynamic weights + bias
__device__ float g_part[9453568];              // split-K partials
__device__ __nv_bfloat16 g_fh[4*256*256*64];   // feature NHWC bf16 hi
__device__ __nv_bfloat16 g_fl[4*256*256*64];   // feature NHWC bf16 lo
__device__ __nv_bfloat16 g_w1h[9*64*64];       // rw1 [tap][oc][ic] hi
__device__ __nv_bfloat16 g_w1l[9*64*64];       // rw1 [tap][oc][ic] lo

// row-major 128B rows with XOR-16B swizzle (bank-conflict-free ldmatrix)
#define SWZ(row, chunk) ((uint32_t)(row)*128u + (((uint32_t)((chunk) ^ ((row) & 7))) * 16u))

// ---------------- mma.sync helpers (sm_80+ path, works on plain sm_103) ----
__device__ __forceinline__ uint32_t smem_u32(const void* p) {
    uint32_t a;
    asm("{ .reg .u64 t; cvta.to.shared.u64 t, %1; cvt.u32.u64 %0, t; }" : "=r"(a) : "l"(p));
    return a;
}
__device__ __forceinline__ void ldm_x4(uint32_t* r, uint32_t addr) {
    asm volatile("ldmatrix.sync.aligned.m8n8.x4.shared.b16 {%0,%1,%2,%3}, [%4];"
        : "=r"(r[0]), "=r"(r[1]), "=r"(r[2]), "=r"(r[3]) : "r"(addr));
}
__device__ __forceinline__ void ldm_x2(uint32_t* r, uint32_t addr) {
    asm volatile("ldmatrix.sync.aligned.m8n8.x2.shared.b16 {%0,%1}, [%2];"
        : "=r"(r[0]), "=r"(r[1]) : "r"(addr));
}
__device__ __forceinline__ void mma_bf16(float* d, const uint32_t* a, const uint32_t* b) {
    asm volatile(
        "mma.sync.aligned.m16n8k16.row.col.f32.bf16.bf16.f32 "
        "{%0,%1,%2,%3}, {%4,%5,%6,%7}, {%8,%9}, {%0,%1,%2,%3};"
        : "+f"(d[0]), "+f"(d[1]), "+f"(d[2]), "+f"(d[3])
        : "r"(a[0]), "r"(a[1]), "r"(a[2]), "r"(a[3]), "r"(b[0]), "r"(b[1]));
}
__device__ __forceinline__ void split_bf16(float v, __nv_bfloat16& hi, __nv_bfloat16& lo) {
    hi = __float2bfloat16_rn(v);
    lo = __float2bfloat16_rn(v - __bfloat162float(hi));
}

// ---------------- NCHW fp32 -> NHWC bf16 hi/lo  (+ fused feature copy) -----
__global__ __launch_bounds__(256) void tohwc_kernel(const float* __restrict__ feat,
                                                    float* __restrict__ out)
{
    __shared__ float s[64][65];
    int bx = blockIdx.x;
    int b = bx >> 10, grp = bx & 1023;
    int pix0 = grp * 64;
    int tid = threadIdx.x;
#pragma unroll
    for (int i = 0; i < 16; i++) {
        int idx = i * 256 + tid;
        int ic = idx >> 6, px = idx & 63;
        float v = feat[(((size_t)(b*64 + ic)) << 16) + pix0 + px];
        s[ic][px] = v;
        out[(((size_t)(b*96 + ic)) << 16) + pix0 + px] = v;   // fused passthrough
    }
    __syncthreads();
#pragma unroll
    for (int i = 0; i < 16; i++) {
        int idx = i * 256 + tid;
        int px = idx >> 6, ic = idx & 63;
        __nv_bfloat16 hi, lo;
        split_bf16(s[ic][px], hi, lo);
        size_t o = ((size_t)b*65536 + pix0 + px) * 64 + ic;
        g_fh[o] = hi; g_fl[o] = lo;
    }
}

// ---------------- rw1 -> [tap][oc][ic] bf16 hi/lo --------------------------
__global__ void wprep_kernel(const float* __restrict__ rw1)
{
    int idx = blockIdx.x * 256 + threadIdx.x;
    if (idx >= 9*64*64) return;
    int tap = idx >> 12, rem = idx & 4095;
    int oc = rem >> 6, ic = rem & 63;
    __nv_bfloat16 hi, lo;
    split_bf16(rw1[(oc*64 + ic)*9 + tap], hi, lo);
    g_w1h[idx] = hi; g_w1l[idx] = lo;
}

// ---------------- conv1 via mma.sync, swizzled halo-A + fused conv2 proj ---
// grid (8,32,4). block 256 (8 warps), 2 blocks/SM.
// smem: AH @0 (43520), AL @43520, WH @87040 (8192), WL @95232 (8192),
//       bias @103424 (256), w2 @103680 (2304). Total 105984.
__global__ __launch_bounds__(256, 2) void conv1_hmma_kernel(
    const float* __restrict__ rb1, const float* __restrict__ rw2)
{
    extern __shared__ char smem[];
    const uint32_t AH = 0, AL = 43520, WH = 87040, WL = 95232, BS = 103424, W2 = 103680;
    uint32_t sb = smem_u32(smem);
    int b = blockIdx.z;
    int y0 = blockIdx.y * 8, x0 = blockIdx.x * 32;
    int tid = threadIdx.x, w = tid >> 5, lane = tid & 31;

    if (tid < 64) *(float*)(smem + BS + tid*4) = rb1[tid];
    for (int i = tid; i < 576; i += 256) {
        int tap = i >> 6, ic = i & 63;
        *(float*)(smem + W2 + i*4) = rw2[ic*9 + tap];
    }

    // build swizzled halo A once: 340 rows (10x34 px) x 64 ic, hi+lo
    for (int i = tid; i < 2720; i += 256) {
        int hp = i >> 3, ch8 = i & 7;
        int hy = hp / 34, hx = hp - hy*34;
        int gy = y0 - 1 + hy, gx = x0 - 1 + hx;
        uint4 vh = {0,0,0,0}, vl = {0,0,0,0};
        if ((unsigned)gy < 256u && (unsigned)gx < 256u) {
            size_t g = ((size_t)(b*256 + gy)*256 + gx)*64 + ch8*8;
            vh = *(const uint4*)(g_fh + g);
            vl = *(const uint4*)(g_fl + g);
        }
        uint32_t off = SWZ(hp, ch8);
        *(uint4*)(smem + AH + off) = vh;
        *(uint4*)(smem + AL + off) = vl;
    }
    // preload W tap 0
    int wr1 = tid >> 3, wc1 = tid & 7;
    int wr2 = (256 + tid) >> 3, wc2 = (256 + tid) & 7;
    {
        uint4 h1 = *(const uint4*)(g_w1h + wr1*64 + wc1*8);
        uint4 l1 = *(const uint4*)(g_w1l + wr1*64 + wc1*8);
        uint4 h2 = *(const uint4*)(g_w1h + wr2*64 + wc2*8);
        uint4 l2 = *(const uint4*)(g_w1l + wr2*64 + wc2*8);
        *(uint4*)(smem + WH + SWZ(wr1, wc1)) = h1;
        *(uint4*)(smem + WL + SWZ(wr1, wc1)) = l1;
        *(uint4*)(smem + WH + SWZ(wr2, wc2)) = h2;
        *(uint4*)(smem + WL + SWZ(wr2, wc2)) = l2;
    }
    __syncthreads();

    float acc[2][8][4];
#pragma unroll
    for (int mt = 0; mt < 2; mt++)
#pragma unroll
        for (int nt = 0; nt < 8; nt++)
#pragma unroll
            for (int e = 0; e < 4; e++) acc[mt][nt][e] = 0.f;

    int a_row = lane & 15, a_cs = lane >> 4;
    int w_row = lane & 7,  w_cs = (lane >> 3) & 1;

    for (int tap = 0; tap < 9; tap++) {
        int dy = tap / 3 - 1, dx = tap % 3 - 1;

        // prefetch next tap's W into regs (hidden under this tap's mma)
        uint4 ph1, pl1, ph2, pl2;
        if (tap < 8) {
            size_t gb = (size_t)(tap + 1)*4096;
            ph1 = *(const uint4*)(g_w1h + gb + wr1*64 + wc1*8);
            pl1 = *(const uint4*)(g_w1l + gb + wr1*64 + wc1*8);
            ph2 = *(const uint4*)(g_w1h + gb + wr2*64 + wc2*8);
            pl2 = *(const uint4*)(g_w1l + gb + wr2*64 + wc2*8);
        }

        int rb = (w + dy + 1)*34 + dx + 1;
#pragma unroll
        for (int ks = 0; ks < 4; ks++) {
            uint32_t ah[2][4], al[2][4];
#pragma unroll
            for (int mt = 0; mt < 2; mt++) {
                int ar = rb + mt*16 + a_row;
                uint32_t aoff = SWZ(ar, ks*2 + a_cs);
                ldm_x4(ah[mt], sb + AH + aoff);
                ldm_x4(al[mt], sb + AL + aoff);
            }
#pragma unroll
            for (int nt = 0; nt < 8; nt++) {
                uint32_t wh[2], wl[2];
                uint32_t woff = SWZ(nt*8 + w_row, ks*2 + w_cs);
                ldm_x2(wh, sb + WH + woff);
                ldm_x2(wl, sb + WL + woff);
                mma_bf16(acc[0][nt], ah[0], wh);
                mma_bf16(acc[1][nt], ah[1], wh);
                mma_bf16(acc[0][nt], al[0], wh);
                mma_bf16(acc[1][nt], al[1], wh);
                mma_bf16(acc[0][nt], ah[0], wl);
                mma_bf16(acc[1][nt], ah[1], wl);
            }
        }
        __syncthreads();                  // everyone done reading W(tap)
        if (tap < 8) {
            *(uint4*)(smem + WH + SWZ(wr1, wc1)) = ph1;
            *(uint4*)(smem + WL + SWZ(wr1, wc1)) = pl1;
            *(uint4*)(smem + WH + SWZ(wr2, wc2)) = ph2;
            *(uint4*)(smem + WL + SWZ(wr2, wc2)) = pl2;
            __syncthreads();              // W(tap+1) visible
        }
    }

    // epilogue: bias + leaky relu, then 9 tap-dot projections (quad reduce)
    const float* bs = (const float*)(smem + BS);
    const float* w2 = (const float*)(smem + W2);
    int g = lane >> 2, c0 = (lane & 3) * 2;
    int y = y0 + w;
#pragma unroll
    for (int mt = 0; mt < 2; mt++) {
#pragma unroll
        for (int half = 0; half < 2; half++) {
            int x = x0 + mt*16 + g + half*8;
            float part[9];
#pragma unroll
            for (int t = 0; t < 9; t++) part[t] = 0.f;
#pragma unroll
            for (int nt = 0; nt < 8; nt++) {
                int oc = nt*8 + c0;
                float v0 = acc[mt][nt][half*2 + 0] + bs[oc];
                float v1 = acc[mt][nt][half*2 + 1] + bs[oc + 1];
                v0 = (v0 >= 0.f) ? v0 : 0.2f * v0;
                v1 = (v1 >= 0.f) ? v1 : 0.2f * v1;
#pragma unroll
                for (int t = 0; t < 9; t++)
                    part[t] += v0 * w2[t*64 + oc] + v1 * w2[t*64 + oc + 1];
            }
#pragma unroll
            for (int t = 0; t < 9; t++) {
                part[t] += __shfl_xor_sync(0xFFFFFFFFu, part[t], 1);
                part[t] += __shfl_xor_sync(0xFFFFFFFFu, part[t], 2);
            }
            if ((lane & 3) == 0) {
                int pix = y*256 + x;
#pragma unroll
                for (int t = 0; t < 9; t++)
                    g_u[t*262144 + b*65536 + pix] = part[t];
            }
        }
    }
}

// ---------------- pool (fused conv2 sum + tanh): per tile -> gram ----------
__global__ void pool_kernel(const float* __restrict__ rb2)
{
    __shared__ float win[66][67];
    int r = blockIdx.x;
    int b = r >> 4, t = r & 15;
    int ti = t >> 2, tj = t & 3;
    int tid = threadIdx.x;
    float b2 = rb2[0];
    for (int i = tid; i < 66*66; i += 256) {
        int h = i / 66, w = i % 66;
        int gy = ti*64 - 1 + h, gx = tj*64 - 1 + w;
        float v = 0.f;
        if ((unsigned)gy < 256u && (unsigned)gx < 256u) {
            float s = 0.f;
#pragma unroll
            for (int tp = 0; tp < 9; tp++) {
                int yy = gy + tp/3 - 1, xx = gx + tp%3 - 1;
                if ((unsigned)yy < 256u && (unsigned)xx < 256u)
                    s += g_u[tp*262144 + b*65536 + yy*256 + xx];
            }
            v = tanhf(s + b2);
        }
        win[h][w] = v;
    }
    __syncthreads();
    for (int i = tid; i < 1024; i += 256) {
        int p = i >> 5, q = i & 31;
        int sp = (p*66) >> 5, ep = ((p+1)*66 + 31) >> 5;
        int sq = (q*66) >> 5, eq = ((q+1)*66 + 31) >> 5;
        float s = 0.f;
        for (int h = sp; h < ep; h++)
            for (int w = sq; w < eq; w++)
                s += win[h][w];
        g_gram[r*1024 + i] = s / (float)((ep - sp) * (eq - sq));
    }
}

// ---------------- HMMA split-K FC GEMM: part[s] = A(64xKC) @ B(KCxN64) -----
__global__ __launch_bounds__(256) void gemm_hmma_kernel(
    const float* __restrict__ Bm, int K, int N, int KC, int stage)
{
    const float* __restrict__ A = (stage == 0) ? g_gram : (stage == 1) ? g_fc1 : g_fc2;

    __shared__ __nv_bfloat16 Ah[64*24], Al[64*24];
    __shared__ __nv_bfloat16 Bh[64*24], Bl[64*24];

    int n0 = blockIdx.x * 64;
    int k0 = blockIdx.y * KC;
    int tid = threadIdx.x, w = tid >> 5, lane = tid & 31;
    int mt = w >> 1;
    int nh = (w & 1) * 4;

    float acc[4][4];
#pragma unroll
    for (int nt = 0; nt < 4; nt++)
#pragma unroll
        for (int e = 0; e < 4; e++) acc[nt][e] = 0.f;

    uint32_t a_row = lane & 15, a_k16 = (lane >> 4) * 16;
    uint32_t w_row = lane & 7,  w_k16 = ((lane >> 3) & 1) * 16;
    uint32_t sAh = smem_u32(Ah), sAl = smem_u32(Al);
    uint32_t sBh = smem_u32(Bh), sBl = smem_u32(Bl);

    int am = tid >> 2, ak = (tid & 3) * 4;
    int bk = tid >> 4, bn = (tid & 15) * 4;

    for (int kc = 0; kc < KC; kc += 16) {
        int kb = k0 + kc;
        __syncthreads();
        {
            float4 va = *(const float4*)&A[(size_t)am * K + kb + ak];
            __nv_bfloat16 h, l;
            const float* vp = (const float*)&va;
#pragma unroll
            for (int j = 0; j < 4; j++) {
                split_bf16(vp[j], h, l);
                Ah[am*24 + ak + j] = h;
                Al[am*24 + ak + j] = l;
            }
        }
        {
            int col = n0 + bn;
            float4 vb = make_float4(0.f, 0.f, 0.f, 0.f);
            if (col < N) vb = *(const float4*)&Bm[(size_t)(kb + bk) * N + col];
            __nv_bfloat16 h, l;
            const float* vp = (const float*)&vb;
#pragma unroll
            for (int j = 0; j < 4; j++) {
                split_bf16(vp[j], h, l);
                Bh[(bn + j)*24 + bk] = h;
                Bl[(bn + j)*24 + bk] = l;
            }
        }
        __syncthreads();

        uint32_t ah[4], al[4];
        uint32_t aoff = (uint32_t)(mt*16 + a_row)*48 + a_k16;
        ldm_x4(ah, sAh + aoff);
        ldm_x4(al, sAl + aoff);
#pragma unroll
        for (int nt = 0; nt < 4; nt++) {
            uint32_t bhf[2], blf[2];
            uint32_t woff = (uint32_t)((nh + nt)*8 + w_row)*48 + w_k16;
            ldm_x2(bhf, sBh + woff);
            ldm_x2(blf, sBl + woff);
            mma_bf16(acc[nt], ah, bhf);
            mma_bf16(acc[nt], al, bhf);
            mma_bf16(acc[nt], ah, blf);
        }
    }

    int s = blockIdx.y;
    int g = lane >> 2, c0 = (lane & 3) * 2;
#pragma unroll
    for (int nt = 0; nt < 4; nt++) {
#pragma unroll
        for (int half = 0; half < 2; half++) {
            int row = mt*16 + g + half*8;
            int col = n0 + (nh + nt)*8 + c0;
            if (col < N) {
                float* p = &g_part[((size_t)(s*64 + row)) * N + col];
                p[0] = acc[nt][half*2 + 0];
                p[1] = acc[nt][half*2 + 1];
            }
        }
    }
}

// ---------------- split-K reduce + bias + activation -----------------------
__global__ void gemm_reduce_kernel(const float* __restrict__ bias,
                                   int N, int nsplit, int relu, int stage)
{
    float* out = (stage == 0) ? g_fc1 : (stage == 1) ? g_fc2 : g_wb;
    int nv = N >> 2;
    int idx = blockIdx.x * 256 + threadIdx.x;
    if (idx >= 64 * nv) return;
    int m = idx / nv, f = idx - m * nv;
    float4 s = make_float4(0.f, 0.f, 0.f, 0.f);
    for (int sp = 0; sp < nsplit; sp++) {
        const float4* p = (const float4*)&g_part[(size_t)(sp*64 + m) * N];
        float4 v = p[f];
        s.x += v.x; s.y += v.y; s.z += v.z; s.w += v.w;
    }
    float4 bv = ((const float4*)bias)[f];
    s.x += bv.x; s.y += bv.y; s.z += bv.z; s.w += bv.w;
    if (relu) {
        s.x = fmaxf(s.x, 0.f); s.y = fmaxf(s.y, 0.f);
        s.z = fmaxf(s.z, 0.f); s.w = fmaxf(s.w, 0.f);
    }
    ((float4*)out)[(size_t)m * nv + f] = s;
}

// ---------------- dynamic per-tile conv via mma.sync, swizzled halo-A ------
// grid (2,8,64). block 256, 2 blocks/SM.
// smem: AH @0 (43520), AL @43520, WH @87040 (4096), WL @91136 (4096),
//       bias @95232 (128). Total 95360.
__global__ __launch_bounds__(256, 2) void dynconv_hmma_kernel(float* __restrict__ out)
{
    extern __shared__ char smem[];
    const uint32_t AH = 0, AL = 43520, WH = 87040, WL = 91136, BS = 95232;
    uint32_t sb = smem_u32(smem);
    int r = blockIdx.z;
    int b = r >> 4, t = r & 15;
    int ti = t >> 2, tj = t & 3;
    int y0 = ti*64 + blockIdx.y * 8;
    int x0 = tj*64 + blockIdx.x * 32;
    int tid = threadIdx.x, w = tid >> 5, lane = tid & 31;

    const float* wrow = g_wb + (size_t)r * 18464;
    if (tid < 32) *(float*)(smem + BS + tid*4) = wrow[18432 + tid];

    // build swizzled halo A once
    for (int i = tid; i < 2720; i += 256) {
        int hp = i >> 3, ch8 = i & 7;
        int hy = hp / 34, hx = hp - hy*34;
        int gy = y0 - 1 + hy, gx = x0 - 1 + hx;
        uint4 vh = {0,0,0,0}, vl = {0,0,0,0};
        if ((unsigned)gy < 256u && (unsigned)gx < 256u) {
            size_t g = ((size_t)(b*256 + gy)*256 + gx)*64 + ch8*8;
            vh = *(const uint4*)(g_fh + g);
            vl = *(const uint4*)(g_fl + g);
        }
        uint32_t off = SWZ(hp, ch8);
        *(uint4*)(smem + AH + off) = vh;
        *(uint4*)(smem + AL + off) = vl;
    }
    // preload W tap 0: thread -> (oc = tid>>3, chunk c = tid&7, 8 scalars)
    int pr_oc = tid >> 3, pr_c = tid & 7;
    {
#pragma unroll
        for (int j = 0; j < 8; j++) {
            __nv_bfloat16 hi, lo;
            split_bf16(wrow[(pr_oc*64 + pr_c*8 + j)*9 + 0], hi, lo);
            uint32_t off = SWZ(pr_oc, pr_c) + j*2;
            *(__nv_bfloat16*)(smem + WH + off) = hi;
            *(__nv_bfloat16*)(smem + WL + off) = lo;
        }
    }
    __syncthreads();

    float acc[2][4][4];
#pragma unroll
    for (int mt = 0; mt < 2; mt++)
#pragma unroll
        for (int nt = 0; nt < 4; nt++)
#pragma unroll
            for (int e = 0; e < 4; e++) acc[mt][nt][e] = 0.f;

    int a_row = lane & 15, a_cs = lane >> 4;
    int w_row = lane & 7,  w_cs = (lane >> 3) & 1;

    for (int tap = 0; tap < 9; tap++) {
        int dy = tap / 3 - 1, dx = tap % 3 - 1;

        float pre[8];
        if (tap < 8) {
#pragma unroll
            for (int j = 0; j < 8; j++)
                pre[j] = wrow[(pr_oc*64 + pr_c*8 + j)*9 + tap + 1];
        }

        int rb = (w + dy + 1)*34 + dx + 1;
#pragma unroll
        for (int ks = 0; ks < 4; ks++) {
            uint32_t ah[2][4], al[2][4];
#pragma unroll
            for (int mt = 0; mt < 2; mt++) {
                int ar = rb + mt*16 + a_row;
                uint32_t aoff = SWZ(ar, ks*2 + a_cs);
                ldm_x4(ah[mt], sb + AH + aoff);
                ldm_x4(al[mt], sb + AL + aoff);
            }
#pragma unroll
            for (int nt = 0; nt < 4; nt++) {
                uint32_t wh[2], wl[2];
                uint32_t woff = SWZ(nt*8 + w_row, ks*2 + w_cs);
                ldm_x2(wh, sb + WH + woff);
                ldm_x2(wl, sb + WL + woff);
                mma_bf16(acc[0][nt], ah[0], wh);
                mma_bf16(acc[1][nt], ah[1], wh);
                mma_bf16(acc[0][nt], al[0], wh);
                mma_bf16(acc[1][nt], al[1], wh);
                mma_bf16(acc[0][nt], ah[0], wl);
                mma_bf16(acc[1][nt], ah[1], wl);
            }
        }
        __syncthreads();
        if (tap < 8) {
#pragma unroll
            for (int j = 0; j < 8; j++) {
                __nv_bfloat16 hi, lo;
                split_bf16(pre[j], hi, lo);
                uint32_t off = SWZ(pr_oc, pr_c) + j*2;
                *(__nv_bfloat16*)(smem + WH + off) = hi;
                *(__nv_bfloat16*)(smem + WL + off) = lo;
            }
            __syncthreads();
        }
    }

    const float* bsm = (const float*)(smem + BS);
    int g = lane >> 2, c0 = (lane & 3) * 2;
    int y = y0 + w;
#pragma unroll
    for (int mt = 0; mt < 2; mt++) {
#pragma unroll
        for (int half = 0; half < 2; half++) {
            int x = x0 + mt*16 + g + half*8;
            int pix = y*256 + x;
#pragma unroll
            for (int nt = 0; nt < 4; nt++) {
                int oc = nt*8 + c0;
                float v0 = acc[mt][nt][half*2 + 0] + bsm[oc];
                float v1 = acc[mt][nt][half*2 + 1] + bsm[oc + 1];
                out[(((size_t)(b*96 + 64 + oc)) << 16) + pix] = v0;
                out[(((size_t)(b*96 + 64 + oc + 1)) << 16) + pix] = v1;
            }
        }
    }
}

// ---------------- launch ---------------------------------------------------
extern "C" void kernel_launch(void* const* d_in, const int* in_sizes, int n_in,
                              void* d_out, int out_size)
{
    const float* feature = (const float*)d_in[0];
    const float* rw1 = (const float*)d_in[1];
    const float* rb1 = (const float*)d_in[2];
    const float* rw2 = (const float*)d_in[3];
    const float* rb2 = (const float*)d_in[4];
    const float* fw1 = (const float*)d_in[5];
    const float* fb1 = (const float*)d_in[6];
    const float* fw2 = (const float*)d_in[7];
    const float* fb2 = (const float*)d_in[8];
    const float* fw3 = (const float*)d_in[9];
    const float* fb3 = (const float*)d_in[10];
    float* out = (float*)d_out;

    const int CONV1_SMEM = 105984;
    const int DYN_SMEM = 95360;
    cudaFuncSetAttribute(conv1_hmma_kernel,
                         cudaFuncAttributeMaxDynamicSharedMemorySize, CONV1_SMEM);
    cudaFuncSetAttribute(dynconv_hmma_kernel,
                         cudaFuncAttributeMaxDynamicSharedMemorySize, DYN_SMEM);

    tohwc_kernel<<<4096, 256>>>(feature, out);
    wprep_kernel<<<144, 256>>>(rw1);
    conv1_hmma_kernel<<<dim3(8, 32, 4), 256, CONV1_SMEM>>>(rb1, rw2);
    pool_kernel<<<64, 256>>>(rb2);

    // FC1: 64x1024 @ 1024x2048, split-K 16 (HMMA)
    gemm_hmma_kernel<<<dim3(32, 16), 256>>>(fw1, 1024, 2048, 64, 0);
    gemm_reduce_kernel<<<(64*512 + 255)/256, 256>>>(fb1, 2048, 16, 1, 0);
    // FC2: 64x2048 @ 2048x2048, split-K 16 (HMMA)
    gemm_hmma_kernel<<<dim3(32, 16), 256>>>(fw2, 2048, 2048, 128, 1);
    gemm_reduce_kernel<<<(64*512 + 255)/256, 256>>>(fb2, 2048, 16, 1, 1);
    // FC3: 64x2048 @ 2048x18464, split-K 8 (HMMA)
    gemm_hmma_kernel<<<dim3(289, 8), 256>>>(fw3, 2048, 18464, 256, 2);
    gemm_reduce_kernel<<<(64*4616 + 255)/256, 256>>>(fb3, 18464, 8, 0, 2);

    dynconv_hmma_kernel<<<dim3(2, 8, 64), 256, DYN_SMEM>>>(out);
}

// round 11
// speedup vs baseline: 2.6403x; 1.0965x over previous
#include <cuda_runtime.h>
#include <cuda_bf16.h>
#include <cstdint>
#include <math.h>

// Problem constants
// B=4, C=64, H=W=256, N_SPLIT=4 (T=16), RED_FC=32, OUT_NC=32, K=3, FMN1=FMN2=2048
// wsize = 32*64*9 = 18432, wb row = 18464

typedef unsigned long long ull;

// ---------------- scratch (device globals; no runtime allocation) ----------
__device__ float g_u[9*4*65536];               // conv2 tap projections
__device__ float g_adap[4*65536];              // tanh(conv2)
__device__ float g_gram[64*1024];              // pooled grams
__device__ float g_fc1[64*2048];
__device__ float g_fc2[64*2048];
__device__ float g_wb[64*18464];               // dynamic weights + bias
__device__ float g_part[9453568];              // split-K partials
__device__ __nv_bfloat16 g_fh[4*256*256*64];   // feature NHWC bf16 hi
__device__ __nv_bfloat16 g_fl[4*256*256*64];   // feature NHWC bf16 lo
__device__ __nv_bfloat16 g_w1h[9*64*64];       // rw1 [tap][oc][ic] hi
__device__ __nv_bfloat16 g_w1l[9*64*64];       // rw1 [tap][oc][ic] lo
__device__ __nv_bfloat16 g_dwh[64*9*32*64];    // dyn W [r][tap][oc][ic] hi
__device__ __nv_bfloat16 g_dwl[64*9*32*64];    // dyn W [r][tap][oc][ic] lo

// row-major 128B rows with XOR-16B swizzle (bank-conflict-free ldmatrix)
#define SWZ(row, chunk) ((uint32_t)(row)*128u + (((uint32_t)((chunk) ^ ((row) & 7))) * 16u))

// ---------------- mma.sync helpers (sm_80+ path, works on plain sm_103) ----
__device__ __forceinline__ uint32_t smem_u32(const void* p) {
    uint32_t a;
    asm("{ .reg .u64 t; cvta.to.shared.u64 t, %1; cvt.u32.u64 %0, t; }" : "=r"(a) : "l"(p));
    return a;
}
__device__ __forceinline__ void ldm_x4(uint32_t* r, uint32_t addr) {
    asm volatile("ldmatrix.sync.aligned.m8n8.x4.shared.b16 {%0,%1,%2,%3}, [%4];"
        : "=r"(r[0]), "=r"(r[1]), "=r"(r[2]), "=r"(r[3]) : "r"(addr));
}
__device__ __forceinline__ void ldm_x2(uint32_t* r, uint32_t addr) {
    asm volatile("ldmatrix.sync.aligned.m8n8.x2.shared.b16 {%0,%1}, [%2];"
        : "=r"(r[0]), "=r"(r[1]) : "r"(addr));
}
__device__ __forceinline__ void mma_bf16(float* d, const uint32_t* a, const uint32_t* b) {
    asm volatile(
        "mma.sync.aligned.m16n8k16.row.col.f32.bf16.bf16.f32 "
        "{%0,%1,%2,%3}, {%4,%5,%6,%7}, {%8,%9}, {%0,%1,%2,%3};"
        : "+f"(d[0]), "+f"(d[1]), "+f"(d[2]), "+f"(d[3])
        : "r"(a[0]), "r"(a[1]), "r"(a[2]), "r"(a[3]), "r"(b[0]), "r"(b[1]));
}
__device__ __forceinline__ void split_bf16(float v, __nv_bfloat16& hi, __nv_bfloat16& lo) {
    hi = __float2bfloat16_rn(v);
    lo = __float2bfloat16_rn(v - __bfloat162float(hi));
}

// ---------------- NCHW fp32 -> NHWC bf16 hi/lo  (+ fused feature copy) -----
__global__ __launch_bounds__(256) void tohwc_kernel(const float* __restrict__ feat,
                                                    float* __restrict__ out)
{
    __shared__ float s[64][65];
    int bx = blockIdx.x;
    int b = bx >> 10, grp = bx & 1023;
    int pix0 = grp * 64;
    int tid = threadIdx.x;
#pragma unroll
    for (int i = 0; i < 16; i++) {
        int idx = i * 256 + tid;
        int ic = idx >> 6, px = idx & 63;
        float v = feat[(((size_t)(b*64 + ic)) << 16) + pix0 + px];
        s[ic][px] = v;
        out[(((size_t)(b*96 + ic)) << 16) + pix0 + px] = v;   // fused passthrough
    }
    __syncthreads();
#pragma unroll
    for (int i = 0; i < 16; i++) {
        int idx = i * 256 + tid;
        int px = idx >> 6, ic = idx & 63;
        __nv_bfloat16 hi, lo;
        split_bf16(s[ic][px], hi, lo);
        size_t o = ((size_t)b*65536 + pix0 + px) * 64 + ic;
        g_fh[o] = hi; g_fl[o] = lo;
    }
}

// ---------------- rw1 -> [tap][oc][ic] bf16 hi/lo --------------------------
__global__ void wprep_kernel(const float* __restrict__ rw1)
{
    int idx = blockIdx.x * 256 + threadIdx.x;
    if (idx >= 9*64*64) return;
    int tap = idx >> 12, rem = idx & 4095;
    int oc = rem >> 6, ic = rem & 63;
    __nv_bfloat16 hi, lo;
    split_bf16(rw1[(oc*64 + ic)*9 + tap], hi, lo);
    g_w1h[idx] = hi; g_w1l[idx] = lo;
}

// ---------------- g_wb -> [r][tap][oc][ic] bf16 hi/lo ----------------------
__global__ void dynwprep_kernel()
{
    int idx = blockIdx.x * 256 + threadIdx.x;   // 64 * 2048
    if (idx >= 64*2048) return;
    int r = idx >> 11, rem = idx & 2047;        // rem = oc*64+ic
    const float* src = g_wb + (size_t)r*18464 + rem*9;
#pragma unroll
    for (int tap = 0; tap < 9; tap++) {
        __nv_bfloat16 h, l;
        split_bf16(src[tap], h, l);
        size_t o = ((size_t)(r*9 + tap))*2048 + rem;
        g_dwh[o] = h; g_dwl[o] = l;
    }
}

// ---------------- conv1 via mma.sync, swizzled halo-A + fused conv2 proj ---
// grid (8,32,4). block 256 (8 warps), 2 blocks/SM.
// smem: AH @0 (43520), AL @43520, WH @87040 (8192), WL @95232 (8192),
//       bias @103424 (256), w2 @103680 (2304). Total 105984.
__global__ __launch_bounds__(256, 2) void conv1_hmma_kernel(
    const float* __restrict__ rb1, const float* __restrict__ rw2)
{
    extern __shared__ char smem[];
    const uint32_t AH = 0, AL = 43520, WH = 87040, WL = 95232, BS = 103424, W2 = 103680;
    uint32_t sb = smem_u32(smem);
    int b = blockIdx.z;
    int y0 = blockIdx.y * 8, x0 = blockIdx.x * 32;
    int tid = threadIdx.x, w = tid >> 5, lane = tid & 31;

    if (tid < 64) *(float*)(smem + BS + tid*4) = rb1[tid];
    for (int i = tid; i < 576; i += 256) {
        int tap = i >> 6, ic = i & 63;
        *(float*)(smem + W2 + i*4) = rw2[ic*9 + tap];
    }

    // build swizzled halo A once: 340 rows (10x34 px) x 64 ic, hi+lo
    for (int i = tid; i < 2720; i += 256) {
        int hp = i >> 3, ch8 = i & 7;
        int hy = hp / 34, hx = hp - hy*34;
        int gy = y0 - 1 + hy, gx = x0 - 1 + hx;
        uint4 vh = {0,0,0,0}, vl = {0,0,0,0};
        if ((unsigned)gy < 256u && (unsigned)gx < 256u) {
            size_t g = ((size_t)(b*256 + gy)*256 + gx)*64 + ch8*8;
            vh = *(const uint4*)(g_fh + g);
            vl = *(const uint4*)(g_fl + g);
        }
        uint32_t off = SWZ(hp, ch8);
        *(uint4*)(smem + AH + off) = vh;
        *(uint4*)(smem + AL + off) = vl;
    }
    // preload W tap 0
    int wr1 = tid >> 3, wc1 = tid & 7;
    int wr2 = (256 + tid) >> 3, wc2 = (256 + tid) & 7;
    {
        uint4 h1 = *(const uint4*)(g_w1h + wr1*64 + wc1*8);
        uint4 l1 = *(const uint4*)(g_w1l + wr1*64 + wc1*8);
        uint4 h2 = *(const uint4*)(g_w1h + wr2*64 + wc2*8);
        uint4 l2 = *(const uint4*)(g_w1l + wr2*64 + wc2*8);
        *(uint4*)(smem + WH + SWZ(wr1, wc1)) = h1;
        *(uint4*)(smem + WL + SWZ(wr1, wc1)) = l1;
        *(uint4*)(smem + WH + SWZ(wr2, wc2)) = h2;
        *(uint4*)(smem + WL + SWZ(wr2, wc2)) = l2;
    }
    __syncthreads();

    float acc[2][8][4];
#pragma unroll
    for (int mt = 0; mt < 2; mt++)
#pragma unroll
        for (int nt = 0; nt < 8; nt++)
#pragma unroll
            for (int e = 0; e < 4; e++) acc[mt][nt][e] = 0.f;

    int a_row = lane & 15, a_cs = lane >> 4;
    int w_row = lane & 7,  w_cs = (lane >> 3) & 1;

    for (int tap = 0; tap < 9; tap++) {
        int dy = tap / 3 - 1, dx = tap % 3 - 1;

        // prefetch next tap's W into regs (hidden under this tap's mma)
        uint4 ph1, pl1, ph2, pl2;
        if (tap < 8) {
            size_t gb = (size_t)(tap + 1)*4096;
            ph1 = *(const uint4*)(g_w1h + gb + wr1*64 + wc1*8);
            pl1 = *(const uint4*)(g_w1l + gb + wr1*64 + wc1*8);
            ph2 = *(const uint4*)(g_w1h + gb + wr2*64 + wc2*8);
            pl2 = *(const uint4*)(g_w1l + gb + wr2*64 + wc2*8);
        }

        int rb = (w + dy + 1)*34 + dx + 1;
#pragma unroll
        for (int ks = 0; ks < 4; ks++) {
            uint32_t ah[2][4], al[2][4];
#pragma unroll
            for (int mt = 0; mt < 2; mt++) {
                int ar = rb + mt*16 + a_row;
                uint32_t aoff = SWZ(ar, ks*2 + a_cs);
                ldm_x4(ah[mt], sb + AH + aoff);
                ldm_x4(al[mt], sb + AL + aoff);
            }
#pragma unroll
            for (int nt = 0; nt < 8; nt++) {
                uint32_t wh[2], wl[2];
                uint32_t woff = SWZ(nt*8 + w_row, ks*2 + w_cs);
                ldm_x2(wh, sb + WH + woff);
                ldm_x2(wl, sb + WL + woff);
                mma_bf16(acc[0][nt], ah[0], wh);
                mma_bf16(acc[1][nt], ah[1], wh);
                mma_bf16(acc[0][nt], al[0], wh);
                mma_bf16(acc[1][nt], al[1], wh);
                mma_bf16(acc[0][nt], ah[0], wl);
                mma_bf16(acc[1][nt], ah[1], wl);
            }
        }
        __syncthreads();                  // everyone done reading W(tap)
        if (tap < 8) {
            *(uint4*)(smem + WH + SWZ(wr1, wc1)) = ph1;
            *(uint4*)(smem + WL + SWZ(wr1, wc1)) = pl1;
            *(uint4*)(smem + WH + SWZ(wr2, wc2)) = ph2;
            *(uint4*)(smem + WL + SWZ(wr2, wc2)) = pl2;
            __syncthreads();              // W(tap+1) visible
        }
    }

    // epilogue: bias + leaky relu, then 9 tap-dot projections (quad reduce)
    const float* bs = (const float*)(smem + BS);
    const float* w2 = (const float*)(smem + W2);
    int g = lane >> 2, c0 = (lane & 3) * 2;
    int y = y0 + w;
#pragma unroll
    for (int mt = 0; mt < 2; mt++) {
#pragma unroll
        for (int half = 0; half < 2; half++) {
            int x = x0 + mt*16 + g + half*8;
            float part[9];
#pragma unroll
            for (int t = 0; t < 9; t++) part[t] = 0.f;
#pragma unroll
            for (int nt = 0; nt < 8; nt++) {
                int oc = nt*8 + c0;
                float v0 = acc[mt][nt][half*2 + 0] + bs[oc];
                float v1 = acc[mt][nt][half*2 + 1] + bs[oc + 1];
                v0 = (v0 >= 0.f) ? v0 : 0.2f * v0;
                v1 = (v1 >= 0.f) ? v1 : 0.2f * v1;
#pragma unroll
                for (int t = 0; t < 9; t++)
                    part[t] += v0 * w2[t*64 + oc] + v1 * w2[t*64 + oc + 1];
            }
#pragma unroll
            for (int t = 0; t < 9; t++) {
                part[t] += __shfl_xor_sync(0xFFFFFFFFu, part[t], 1);
                part[t] += __shfl_xor_sync(0xFFFFFFFFu, part[t], 2);
            }
            if ((lane & 3) == 0) {
                int pix = y*256 + x;
#pragma unroll
                for (int t = 0; t < 9; t++)
                    g_u[t*262144 + b*65536 + pix] = part[t];
            }
        }
    }
}

// ---------------- conv2 sum: adap = tanh(sum of shifted taps + bias) -------
__global__ __launch_bounds__(256) void conv2_sum_kernel(const float* __restrict__ rb2)
{
    int P = blockIdx.x * 256 + threadIdx.x;
    int b = P >> 16, pix = P & 65535;
    int y = pix >> 8, x = pix & 255;
    float s = 0.f;
#pragma unroll
    for (int t = 0; t < 9; t++) {
        int yy = y + t/3 - 1, xx = x + t%3 - 1;
        if ((unsigned)yy < 256u && (unsigned)xx < 256u)
            s += g_u[t*262144 + b*65536 + yy*256 + xx];
    }
    g_adap[(size_t)b*65536 + pix] = tanhf(s + rb2[0]);
}

// ---------------- adaptive pool per tile -> gram ---------------------------
__global__ void pool_kernel()
{
    __shared__ float win[66][67];
    int r = blockIdx.x;
    int b = r >> 4, t = r & 15;
    int ti = t >> 2, tj = t & 3;
    int tid = threadIdx.x;
    for (int i = tid; i < 66*66; i += 256) {
        int h = i / 66, w = i % 66;
        int gy = ti*64 - 1 + h, gx = tj*64 - 1 + w;
        float v = 0.f;
        if ((unsigned)gy < 256u && (unsigned)gx < 256u)
            v = g_adap[((size_t)b*256 + gy) * 256 + gx];
        win[h][w] = v;
    }
    __syncthreads();
    for (int i = tid; i < 1024; i += 256) {
        int p = i >> 5, q = i & 31;
        int sp = (p*66) >> 5, ep = ((p+1)*66 + 31) >> 5;
        int sq = (q*66) >> 5, eq = ((q+1)*66 + 31) >> 5;
        float s = 0.f;
        for (int h = sp; h < ep; h++)
            for (int w = sq; w < eq; w++)
                s += win[h][w];
        g_gram[r*1024 + i] = s / (float)((ep - sp) * (eq - sq));
    }
}

// ---------------- HMMA split-K FC GEMM: part[s] = A(64xKC) @ B(KCxN64) -----
__global__ __launch_bounds__(256) void gemm_hmma_kernel(
    const float* __restrict__ Bm, int K, int N, int KC, int stage)
{
    const float* __restrict__ A = (stage == 0) ? g_gram : (stage == 1) ? g_fc1 : g_fc2;

    __shared__ __nv_bfloat16 Ah[64*24], Al[64*24];
    __shared__ __nv_bfloat16 Bh[64*24], Bl[64*24];

    int n0 = blockIdx.x * 64;
    int k0 = blockIdx.y * KC;
    int tid = threadIdx.x, w = tid >> 5, lane = tid & 31;
    int mt = w >> 1;
    int nh = (w & 1) * 4;

    float acc[4][4];
#pragma unroll
    for (int nt = 0; nt < 4; nt++)
#pragma unroll
        for (int e = 0; e < 4; e++) acc[nt][e] = 0.f;

    uint32_t a_row = lane & 15, a_k16 = (lane >> 4) * 16;
    uint32_t w_row = lane & 7,  w_k16 = ((lane >> 3) & 1) * 16;
    uint32_t sAh = smem_u32(Ah), sAl = smem_u32(Al);
    uint32_t sBh = smem_u32(Bh), sBl = smem_u32(Bl);

    int am = tid >> 2, ak = (tid & 3) * 4;
    int bk = tid >> 4, bn = (tid & 15) * 4;

    for (int kc = 0; kc < KC; kc += 16) {
        int kb = k0 + kc;
        __syncthreads();
        {
            float4 va = *(const float4*)&A[(size_t)am * K + kb + ak];
            __nv_bfloat16 h, l;
            const float* vp = (const float*)&va;
#pragma unroll
            for (int j = 0; j < 4; j++) {
                split_bf16(vp[j], h, l);
                Ah[am*24 + ak + j] = h;
                Al[am*24 + ak + j] = l;
            }
        }
        {
            int col = n0 + bn;
            float4 vb = make_float4(0.f, 0.f, 0.f, 0.f);
            if (col < N) vb = *(const float4*)&Bm[(size_t)(kb + bk) * N + col];
            __nv_bfloat16 h, l;
            const float* vp = (const float*)&vb;
#pragma unroll
            for (int j = 0; j < 4; j++) {
                split_bf16(vp[j], h, l);
                Bh[(bn + j)*24 + bk] = h;
                Bl[(bn + j)*24 + bk] = l;
            }
        }
        __syncthreads();

        uint32_t ah[4], al[4];
        uint32_t aoff = (uint32_t)(mt*16 + a_row)*48 + a_k16;
        ldm_x4(ah, sAh + aoff);
        ldm_x4(al, sAl + aoff);
#pragma unroll
        for (int nt = 0; nt < 4; nt++) {
            uint32_t bhf[2], blf[2];
            uint32_t woff = (uint32_t)((nh + nt)*8 + w_row)*48 + w_k16;
            ldm_x2(bhf, sBh + woff);
            ldm_x2(blf, sBl + woff);
            mma_bf16(acc[nt], ah, bhf);
            mma_bf16(acc[nt], al, bhf);
            mma_bf16(acc[nt], ah, blf);
        }
    }

    int s = blockIdx.y;
    int g = lane >> 2, c0 = (lane & 3) * 2;
#pragma unroll
    for (int nt = 0; nt < 4; nt++) {
#pragma unroll
        for (int half = 0; half < 2; half++) {
            int row = mt*16 + g + half*8;
            int col = n0 + (nh + nt)*8 + c0;
            if (col < N) {
                float* p = &g_part[((size_t)(s*64 + row)) * N + col];
                p[0] = acc[nt][half*2 + 0];
                p[1] = acc[nt][half*2 + 1];
            }
        }
    }
}

// ---------------- split-K reduce + bias + activation -----------------------
__global__ void gemm_reduce_kernel(const float* __restrict__ bias,
                                   int N, int nsplit, int relu, int stage)
{
    float* out = (stage == 0) ? g_fc1 : (stage == 1) ? g_fc2 : g_wb;
    int nv = N >> 2;
    int idx = blockIdx.x * 256 + threadIdx.x;
    if (idx >= 64 * nv) return;
    int m = idx / nv, f = idx - m * nv;
    float4 s = make_float4(0.f, 0.f, 0.f, 0.f);
    for (int sp = 0; sp < nsplit; sp++) {
        const float4* p = (const float4*)&g_part[(size_t)(sp*64 + m) * N];
        float4 v = p[f];
        s.x += v.x; s.y += v.y; s.z += v.z; s.w += v.w;
    }
    float4 bv = ((const float4*)bias)[f];
    s.x += bv.x; s.y += bv.y; s.z += bv.z; s.w += bv.w;
    if (relu) {
        s.x = fmaxf(s.x, 0.f); s.y = fmaxf(s.y, 0.f);
        s.z = fmaxf(s.z, 0.f); s.w = fmaxf(s.w, 0.f);
    }
    ((float4*)out)[(size_t)m * nv + f] = s;
}

// ---------------- dynamic per-tile conv via mma.sync, swizzled halo-A ------
// grid (2,8,64). block 256, 2 blocks/SM.
// smem: AH @0 (43520), AL @43520, WH @87040 (4096), WL @91136 (4096),
//       bias @95232 (128). Total 95360.
__global__ __launch_bounds__(256, 2) void dynconv_hmma_kernel(float* __restrict__ out)
{
    extern __shared__ char smem[];
    const uint32_t AH = 0, AL = 43520, WH = 87040, WL = 91136, BS = 95232;
    uint32_t sb = smem_u32(smem);
    int r = blockIdx.z;
    int b = r >> 4, t = r & 15;
    int ti = t >> 2, tj = t & 3;
    int y0 = ti*64 + blockIdx.y * 8;
    int x0 = tj*64 + blockIdx.x * 32;
    int tid = threadIdx.x, w = tid >> 5, lane = tid & 31;

    if (tid < 32) *(float*)(smem + BS + tid*4) = g_wb[(size_t)r*18464 + 18432 + tid];

    // build swizzled halo A once
    for (int i = tid; i < 2720; i += 256) {
        int hp = i >> 3, ch8 = i & 7;
        int hy = hp / 34, hx = hp - hy*34;
        int gy = y0 - 1 + hy, gx = x0 - 1 + hx;
        uint4 vh = {0,0,0,0}, vl = {0,0,0,0};
        if ((unsigned)gy < 256u && (unsigned)gx < 256u) {
            size_t g = ((size_t)(b*256 + gy)*256 + gx)*64 + ch8*8;
            vh = *(const uint4*)(g_fh + g);
            vl = *(const uint4*)(g_fl + g);
        }
        uint32_t off = SWZ(hp, ch8);
        *(uint4*)(smem + AH + off) = vh;
        *(uint4*)(smem + AL + off) = vl;
    }
    // preload W tap 0 (prepped bf16, coalesced uint4: 32 oc x 8 chunks)
    const __nv_bfloat16* dwh = g_dwh + (size_t)r*9*2048;
    const __nv_bfloat16* dwl = g_dwl + (size_t)r*9*2048;
    int wr = tid >> 3, wc = tid & 7;
    {
        *(uint4*)(smem + WH + SWZ(wr, wc)) = *(const uint4*)(dwh + wr*64 + wc*8);
        *(uint4*)(smem + WL + SWZ(wr, wc)) = *(const uint4*)(dwl + wr*64 + wc*8);
    }
    __syncthreads();

    float acc[2][4][4];
#pragma unroll
    for (int mt = 0; mt < 2; mt++)
#pragma unroll
        for (int nt = 0; nt < 4; nt++)
#pragma unroll
            for (int e = 0; e < 4; e++) acc[mt][nt][e] = 0.f;

    int a_row = lane & 15, a_cs = lane >> 4;
    int w_row = lane & 7,  w_cs = (lane >> 3) & 1;

    for (int tap = 0; tap < 9; tap++) {
        int dy = tap / 3 - 1, dx = tap % 3 - 1;

        uint4 ph, pl;
        if (tap < 8) {
            ph = *(const uint4*)(dwh + (tap + 1)*2048 + wr*64 + wc*8);
            pl = *(const uint4*)(dwl + (tap + 1)*2048 + wr*64 + wc*8);
        }

        int rb = (w + dy + 1)*34 + dx + 1;
#pragma unroll
        for (int ks = 0; ks < 4; ks++) {
            uint32_t ah[2][4], al[2][4];
#pragma unroll
            for (int mt = 0; mt < 2; mt++) {
                int ar = rb + mt*16 + a_row;
                uint32_t aoff = SWZ(ar, ks*2 + a_cs);
                ldm_x4(ah[mt], sb + AH + aoff);
                ldm_x4(al[mt], sb + AL + aoff);
            }
#pragma unroll
            for (int nt = 0; nt < 4; nt++) {
                uint32_t wh[2], wl[2];
                uint32_t woff = SWZ(nt*8 + w_row, ks*2 + w_cs);
                ldm_x2(wh, sb + WH + woff);
                ldm_x2(wl, sb + WL + woff);
                mma_bf16(acc[0][nt], ah[0], wh);
                mma_bf16(acc[1][nt], ah[1], wh);
                mma_bf16(acc[0][nt], al[0], wh);
                mma_bf16(acc[1][nt], al[1], wh);
                mma_bf16(acc[0][nt], ah[0], wl);
                mma_bf16(acc[1][nt], ah[1], wl);
            }
        }
        __syncthreads();
        if (tap < 8) {
            *(uint4*)(smem + WH + SWZ(wr, wc)) = ph;
            *(uint4*)(smem + WL + SWZ(wr, wc)) = pl;
            __syncthreads();
        }
    }

    const float* bsm = (const float*)(smem + BS);
    int g = lane >> 2, c0 = (lane & 3) * 2;
    int y = y0 + w;
#pragma unroll
    for (int mt = 0; mt < 2; mt++) {
#pragma unroll
        for (int half = 0; half < 2; half++) {
            int x = x0 + mt*16 + g + half*8;
            int pix = y*256 + x;
#pragma unroll
            for (int nt = 0; nt < 4; nt++) {
                int oc = nt*8 + c0;
                float v0 = acc[mt][nt][half*2 + 0] + bsm[oc];
                float v1 = acc[mt][nt][half*2 + 1] + bsm[oc + 1];
                out[(((size_t)(b*96 + 64 + oc)) << 16) + pix] = v0;
                out[(((size_t)(b*96 + 64 + oc + 1)) << 16) + pix] = v1;
            }
        }
    }
}

// ---------------- launch ---------------------------------------------------
extern "C" void kernel_launch(void* const* d_in, const int* in_sizes, int n_in,
                              void* d_out, int out_size)
{
    const float* feature = (const float*)d_in[0];
    const float* rw1 = (const float*)d_in[1];
    const float* rb1 = (const float*)d_in[2];
    const float* rw2 = (const float*)d_in[3];
    const float* rb2 = (const float*)d_in[4];
    const float* fw1 = (const float*)d_in[5];
    const float* fb1 = (const float*)d_in[6];
    const float* fw2 = (const float*)d_in[7];
    const float* fb2 = (const float*)d_in[8];
    const float* fw3 = (const float*)d_in[9];
    const float* fb3 = (const float*)d_in[10];
    float* out = (float*)d_out;

    const int CONV1_SMEM = 105984;
    const int DYN_SMEM = 95360;
    cudaFuncSetAttribute(conv1_hmma_kernel,
                         cudaFuncAttributeMaxDynamicSharedMemorySize, CONV1_SMEM);
    cudaFuncSetAttribute(dynconv_hmma_kernel,
                         cudaFuncAttributeMaxDynamicSharedMemorySize, DYN_SMEM);

    tohwc_kernel<<<4096, 256>>>(feature, out);
    wprep_kernel<<<144, 256>>>(rw1);
    conv1_hmma_kernel<<<dim3(8, 32, 4), 256, CONV1_SMEM>>>(rb1, rw2);
    conv2_sum_kernel<<<1024, 256>>>(rb2);
    pool_kernel<<<64, 256>>>();

    // FC1: 64x1024 @ 1024x2048, split-K 16 (HMMA)
    gemm_hmma_kernel<<<dim3(32, 16), 256>>>(fw1, 1024, 2048, 64, 0);
    gemm_reduce_kernel<<<(64*512 + 255)/256, 256>>>(fb1, 2048, 16, 1, 0);
    // FC2: 64x2048 @ 2048x2048, split-K 16 (HMMA)
    gemm_hmma_kernel<<<dim3(32, 16), 256>>>(fw2, 2048, 2048, 128, 1);
    gemm_reduce_kernel<<<(64*512 + 255)/256, 256>>>(fb2, 2048, 16, 1, 1);
    // FC3: 64x2048 @ 2048x18464, split-K 8 (HMMA)
    gemm_hmma_kernel<<<dim3(289, 8), 256>>>(fw3, 2048, 18464, 256, 2);
    gemm_reduce_kernel<<<(64*4616 + 255)/256, 256>>>(fb3, 18464, 8, 0, 2);

    dynwprep_kernel<<<512, 256>>>();
    dynconv_hmma_kernel<<<dim3(2, 8, 64), 256, DYN_SMEM>>>(out);
}

// round 12
// speedup vs baseline: 2.7976x; 1.0596x over previous
#include <cuda_runtime.h>
#include <cuda_bf16.h>
#include <cstdint>
#include <math.h>

// Problem constants
// B=4, C=64, H=W=256, N_SPLIT=4 (T=16), RED_FC=32, OUT_NC=32, K=3, FMN1=FMN2=2048
// wsize = 32*64*9 = 18432, wb row = 18464

typedef unsigned long long ull;

// ---------------- scratch (device globals; no runtime allocation) ----------
__device__ float g_u[9*4*65536];               // conv2 tap projections
__device__ float g_adap[4*65536];              // tanh(conv2)
__device__ float g_gram[64*1024];              // pooled grams
__device__ float g_fc1[64*2048];
__device__ float g_fc2[64*2048];
__device__ float g_wb[64*18464];               // dynamic weights + bias
__device__ float g_part[9453568];              // split-K partials
__device__ __nv_bfloat16 g_fh[4*256*256*64];   // feature NHWC bf16 hi
__device__ __nv_bfloat16 g_fl[4*256*256*64];   // feature NHWC bf16 lo
__device__ __nv_bfloat16 g_w1h[9*64*64];       // rw1 [tap][oc][ic] hi
__device__ __nv_bfloat16 g_w1l[9*64*64];       // rw1 [tap][oc][ic] lo
__device__ __nv_bfloat16 g_dwh[64*9*32*64];    // dyn W [r][tap][oc][ic] hi
__device__ __nv_bfloat16 g_dwl[64*9*32*64];    // dyn W [r][tap][oc][ic] lo

// row-major 128B rows with XOR-16B swizzle (bank-conflict-free ldmatrix)
#define SWZ(row, chunk) ((uint32_t)(row)*128u + (((uint32_t)((chunk) ^ ((row) & 7))) * 16u))

// ---------------- mma.sync helpers (sm_80+ path, works on plain sm_103) ----
__device__ __forceinline__ uint32_t smem_u32(const void* p) {
    uint32_t a;
    asm("{ .reg .u64 t; cvta.to.shared.u64 t, %1; cvt.u32.u64 %0, t; }" : "=r"(a) : "l"(p));
    return a;
}
__device__ __forceinline__ void ldm_x4(uint32_t* r, uint32_t addr) {
    asm volatile("ldmatrix.sync.aligned.m8n8.x4.shared.b16 {%0,%1,%2,%3}, [%4];"
        : "=r"(r[0]), "=r"(r[1]), "=r"(r[2]), "=r"(r[3]) : "r"(addr));
}
__device__ __forceinline__ void ldm_x2(uint32_t* r, uint32_t addr) {
    asm volatile("ldmatrix.sync.aligned.m8n8.x2.shared.b16 {%0,%1}, [%2];"
        : "=r"(r[0]), "=r"(r[1]) : "r"(addr));
}
__device__ __forceinline__ void mma_bf16(float* d, const uint32_t* a, const uint32_t* b) {
    asm volatile(
        "mma.sync.aligned.m16n8k16.row.col.f32.bf16.bf16.f32 "
        "{%0,%1,%2,%3}, {%4,%5,%6,%7}, {%8,%9}, {%0,%1,%2,%3};"
        : "+f"(d[0]), "+f"(d[1]), "+f"(d[2]), "+f"(d[3])
        : "r"(a[0]), "r"(a[1]), "r"(a[2]), "r"(a[3]), "r"(b[0]), "r"(b[1]));
}
__device__ __forceinline__ void split_bf16(float v, __nv_bfloat16& hi, __nv_bfloat16& lo) {
    hi = __float2bfloat16_rn(v);
    lo = __float2bfloat16_rn(v - __bfloat162float(hi));
}

// ---------------- NCHW fp32 -> NHWC bf16 hi/lo  (+ fused feature copy) -----
__global__ __launch_bounds__(256) void tohwc_kernel(const float* __restrict__ feat,
                                                    float* __restrict__ out)
{
    __shared__ float s[64][65];
    int bx = blockIdx.x;
    int b = bx >> 10, grp = bx & 1023;
    int pix0 = grp * 64;
    int tid = threadIdx.x;
#pragma unroll
    for (int i = 0; i < 16; i++) {
        int idx = i * 256 + tid;
        int ic = idx >> 6, px = idx & 63;
        float v = feat[(((size_t)(b*64 + ic)) << 16) + pix0 + px];
        s[ic][px] = v;
        out[(((size_t)(b*96 + ic)) << 16) + pix0 + px] = v;   // fused passthrough
    }
    __syncthreads();
#pragma unroll
    for (int i = 0; i < 16; i++) {
        int idx = i * 256 + tid;
        int px = idx >> 6, ic = idx & 63;
        __nv_bfloat16 hi, lo;
        split_bf16(s[ic][px], hi, lo);
        size_t o = ((size_t)b*65536 + pix0 + px) * 64 + ic;
        g_fh[o] = hi; g_fl[o] = lo;
    }
}

// ---------------- rw1 -> [tap][oc][ic] bf16 hi/lo --------------------------
__global__ void wprep_kernel(const float* __restrict__ rw1)
{
    int idx = blockIdx.x * 256 + threadIdx.x;
    if (idx >= 9*64*64) return;
    int tap = idx >> 12, rem = idx & 4095;
    int oc = rem >> 6, ic = rem & 63;
    __nv_bfloat16 hi, lo;
    split_bf16(rw1[(oc*64 + ic)*9 + tap], hi, lo);
    g_w1h[idx] = hi; g_w1l[idx] = lo;
}

// ---------------- g_wb -> [r][tap][oc][ic] bf16 hi/lo ----------------------
__global__ void dynwprep_kernel()
{
    int idx = blockIdx.x * 256 + threadIdx.x;   // 64 * 2048
    if (idx >= 64*2048) return;
    int r = idx >> 11, rem = idx & 2047;        // rem = oc*64+ic
    const float* src = g_wb + (size_t)r*18464 + rem*9;
#pragma unroll
    for (int tap = 0; tap < 9; tap++) {
        __nv_bfloat16 h, l;
        split_bf16(src[tap], h, l);
        size_t o = ((size_t)(r*9 + tap))*2048 + rem;
        g_dwh[o] = h; g_dwl[o] = l;
    }
}

// ---------------- conv1 via mma.sync, swizzled halo-A + fused conv2 proj ---
// grid (8,32,4). block 256 (8 warps), 2 blocks/SM.
// smem: AH @0 (43520), AL @43520, WH @87040 (8192), WL @95232 (8192),
//       bias @103424 (256), w2 @103680 (2304). Total 105984.
__global__ __launch_bounds__(256, 2) void conv1_hmma_kernel(
    const float* __restrict__ rb1, const float* __restrict__ rw2)
{
    extern __shared__ char smem[];
    const uint32_t AH = 0, AL = 43520, WH = 87040, WL = 95232, BS = 103424, W2 = 103680;
    uint32_t sb = smem_u32(smem);
    int b = blockIdx.z;
    int y0 = blockIdx.y * 8, x0 = blockIdx.x * 32;
    int tid = threadIdx.x, w = tid >> 5, lane = tid & 31;

    if (tid < 64) *(float*)(smem + BS + tid*4) = rb1[tid];
    for (int i = tid; i < 576; i += 256) {
        int tap = i >> 6, ic = i & 63;
        *(float*)(smem + W2 + i*4) = rw2[ic*9 + tap];
    }

    // build swizzled halo A once: 340 rows (10x34 px) x 64 ic, hi+lo
    for (int i = tid; i < 2720; i += 256) {
        int hp = i >> 3, ch8 = i & 7;
        int hy = hp / 34, hx = hp - hy*34;
        int gy = y0 - 1 + hy, gx = x0 - 1 + hx;
        uint4 vh = {0,0,0,0}, vl = {0,0,0,0};
        if ((unsigned)gy < 256u && (unsigned)gx < 256u) {
            size_t g = ((size_t)(b*256 + gy)*256 + gx)*64 + ch8*8;
            vh = *(const uint4*)(g_fh + g);
            vl = *(const uint4*)(g_fl + g);
        }
        uint32_t off = SWZ(hp, ch8);
        *(uint4*)(smem + AH + off) = vh;
        *(uint4*)(smem + AL + off) = vl;
    }
    // preload W tap 0
    int wr1 = tid >> 3, wc1 = tid & 7;
    int wr2 = (256 + tid) >> 3, wc2 = (256 + tid) & 7;
    {
        uint4 h1 = *(const uint4*)(g_w1h + wr1*64 + wc1*8);
        uint4 l1 = *(const uint4*)(g_w1l + wr1*64 + wc1*8);
        uint4 h2 = *(const uint4*)(g_w1h + wr2*64 + wc2*8);
        uint4 l2 = *(const uint4*)(g_w1l + wr2*64 + wc2*8);
        *(uint4*)(smem + WH + SWZ(wr1, wc1)) = h1;
        *(uint4*)(smem + WL + SWZ(wr1, wc1)) = l1;
        *(uint4*)(smem + WH + SWZ(wr2, wc2)) = h2;
        *(uint4*)(smem + WL + SWZ(wr2, wc2)) = l2;
    }
    __syncthreads();

    float acc[2][8][4];
#pragma unroll
    for (int mt = 0; mt < 2; mt++)
#pragma unroll
        for (int nt = 0; nt < 8; nt++)
#pragma unroll
            for (int e = 0; e < 4; e++) acc[mt][nt][e] = 0.f;

    int a_row = lane & 15, a_cs = lane >> 4;
    int w_row = lane & 7,  w_cs = (lane >> 3) & 1;

    for (int tap = 0; tap < 9; tap++) {
        int dy = tap / 3 - 1, dx = tap % 3 - 1;

        // prefetch next tap's W into regs (hidden under this tap's mma)
        uint4 ph1, pl1, ph2, pl2;
        if (tap < 8) {
            size_t gb = (size_t)(tap + 1)*4096;
            ph1 = *(const uint4*)(g_w1h + gb + wr1*64 + wc1*8);
            pl1 = *(const uint4*)(g_w1l + gb + wr1*64 + wc1*8);
            ph2 = *(const uint4*)(g_w1h + gb + wr2*64 + wc2*8);
            pl2 = *(const uint4*)(g_w1l + gb + wr2*64 + wc2*8);
        }

        int rb = (w + dy + 1)*34 + dx + 1;
#pragma unroll
        for (int ks = 0; ks < 4; ks++) {
            uint32_t ah[2][4], al[2][4];
#pragma unroll
            for (int mt = 0; mt < 2; mt++) {
                int ar = rb + mt*16 + a_row;
                uint32_t aoff = SWZ(ar, ks*2 + a_cs);
                ldm_x4(ah[mt], sb + AH + aoff);
                ldm_x4(al[mt], sb + AL + aoff);
            }
#pragma unroll
            for (int nt = 0; nt < 8; nt++) {
                uint32_t wh[2], wl[2];
                uint32_t woff = SWZ(nt*8 + w_row, ks*2 + w_cs);
                ldm_x2(wh, sb + WH + woff);
                ldm_x2(wl, sb + WL + woff);
                mma_bf16(acc[0][nt], ah[0], wh);
                mma_bf16(acc[1][nt], ah[1], wh);
                mma_bf16(acc[0][nt], al[0], wh);
                mma_bf16(acc[1][nt], al[1], wh);
                mma_bf16(acc[0][nt], ah[0], wl);
                mma_bf16(acc[1][nt], ah[1], wl);
            }
        }
        __syncthreads();                  // everyone done reading W(tap)
        if (tap < 8) {
            *(uint4*)(smem + WH + SWZ(wr1, wc1)) = ph1;
            *(uint4*)(smem + WL + SWZ(wr1, wc1)) = pl1;
            *(uint4*)(smem + WH + SWZ(wr2, wc2)) = ph2;
            *(uint4*)(smem + WL + SWZ(wr2, wc2)) = pl2;
            __syncthreads();              // W(tap+1) visible
        }
    }

    // epilogue: bias + leaky relu, then 9 tap-dot projections (quad reduce)
    const float* bs = (const float*)(smem + BS);
    const float* w2 = (const float*)(smem + W2);
    int g = lane >> 2, c0 = (lane & 3) * 2;
    int y = y0 + w;
#pragma unroll
    for (int mt = 0; mt < 2; mt++) {
#pragma unroll
        for (int half = 0; half < 2; half++) {
            int x = x0 + mt*16 + g + half*8;
            float part[9];
#pragma unroll
            for (int t = 0; t < 9; t++) part[t] = 0.f;
#pragma unroll
            for (int nt = 0; nt < 8; nt++) {
                int oc = nt*8 + c0;
                float v0 = acc[mt][nt][half*2 + 0] + bs[oc];
                float v1 = acc[mt][nt][half*2 + 1] + bs[oc + 1];
                v0 = (v0 >= 0.f) ? v0 : 0.2f * v0;
                v1 = (v1 >= 0.f) ? v1 : 0.2f * v1;
#pragma unroll
                for (int t = 0; t < 9; t++)
                    part[t] += v0 * w2[t*64 + oc] + v1 * w2[t*64 + oc + 1];
            }
#pragma unroll
            for (int t = 0; t < 9; t++) {
                part[t] += __shfl_xor_sync(0xFFFFFFFFu, part[t], 1);
                part[t] += __shfl_xor_sync(0xFFFFFFFFu, part[t], 2);
            }
            if ((lane & 3) == 0) {
                int pix = y*256 + x;
#pragma unroll
                for (int t = 0; t < 9; t++)
                    g_u[t*262144 + b*65536 + pix] = part[t];
            }
        }
    }
}

// ---------------- conv2 sum: adap = tanh(sum of shifted taps + bias) -------
__global__ __launch_bounds__(256) void conv2_sum_kernel(const float* __restrict__ rb2)
{
    int P = blockIdx.x * 256 + threadIdx.x;
    int b = P >> 16, pix = P & 65535;
    int y = pix >> 8, x = pix & 255;
    float s = 0.f;
#pragma unroll
    for (int t = 0; t < 9; t++) {
        int yy = y + t/3 - 1, xx = x + t%3 - 1;
        if ((unsigned)yy < 256u && (unsigned)xx < 256u)
            s += g_u[t*262144 + b*65536 + yy*256 + xx];
    }
    g_adap[(size_t)b*65536 + pix] = tanhf(s + rb2[0]);
}

// ---------------- adaptive pool per tile -> gram ---------------------------
__global__ void pool_kernel()
{
    __shared__ float win[66][67];
    int r = blockIdx.x;
    int b = r >> 4, t = r & 15;
    int ti = t >> 2, tj = t & 3;
    int tid = threadIdx.x;
    for (int i = tid; i < 66*66; i += 256) {
        int h = i / 66, w = i % 66;
        int gy = ti*64 - 1 + h, gx = tj*64 - 1 + w;
        float v = 0.f;
        if ((unsigned)gy < 256u && (unsigned)gx < 256u)
            v = g_adap[((size_t)b*256 + gy) * 256 + gx];
        win[h][w] = v;
    }
    __syncthreads();
    for (int i = tid; i < 1024; i += 256) {
        int p = i >> 5, q = i & 31;
        int sp = (p*66) >> 5, ep = ((p+1)*66 + 31) >> 5;
        int sq = (q*66) >> 5, eq = ((q+1)*66 + 31) >> 5;
        float s = 0.f;
        for (int h = sp; h < ep; h++)
            for (int w = sq; w < eq; w++)
                s += win[h][w];
        g_gram[r*1024 + i] = s / (float)((ep - sp) * (eq - sq));
    }
}

// ---------------- HMMA split-K FC GEMM (ping-pong): part[s] = A @ B --------
// grid (ceil(N/64), nsplit), block 256 (8 warps). 1 barrier per k16-step;
// fp32 global loads for step s+1 issued before the MMAs of step s.
__global__ __launch_bounds__(256) void gemm_hmma_kernel(
    const float* __restrict__ Bm, int K, int N, int KC, int stage)
{
    const float* __restrict__ A = (stage == 0) ? g_gram : (stage == 1) ? g_fc1 : g_fc2;

    __shared__ __nv_bfloat16 Ah[2][1536], Al[2][1536];   // [buf][m*24 + k]
    __shared__ __nv_bfloat16 Bh[2][1536], Bl[2][1536];   // [buf][n*24 + k]

    int n0 = blockIdx.x * 64;
    int k0 = blockIdx.y * KC;
    int tid = threadIdx.x, w = tid >> 5, lane = tid & 31;
    int mt = w >> 1;
    int nh = (w & 1) * 4;

    float acc[4][4];
#pragma unroll
    for (int nt = 0; nt < 4; nt++)
#pragma unroll
        for (int e = 0; e < 4; e++) acc[nt][e] = 0.f;

    uint32_t a_row = lane & 15, a_k16 = (lane >> 4) * 16;
    uint32_t w_row = lane & 7,  w_k16 = ((lane >> 3) & 1) * 16;
    uint32_t sAh = smem_u32(Ah), sAl = smem_u32(Al);
    uint32_t sBh = smem_u32(Bh), sBl = smem_u32(Bl);

    int am = tid >> 2, ak = (tid & 3) * 4;
    int bk = tid >> 4, bn = (tid & 15) * 4;
    int col = n0 + bn;
    int nsteps = KC >> 4;

    // load + store step 0 into buf 0
    float4 va = *(const float4*)&A[(size_t)am * K + k0 + ak];
    float4 vb = make_float4(0.f, 0.f, 0.f, 0.f);
    if (col < N) vb = *(const float4*)&Bm[(size_t)(k0 + bk) * N + col];
    {
        const float* vp = (const float*)&va;
        const float* wp = (const float*)&vb;
        __nv_bfloat16 h, l;
#pragma unroll
        for (int j = 0; j < 4; j++) {
            split_bf16(vp[j], h, l);
            Ah[0][am*24 + ak + j] = h;
            Al[0][am*24 + ak + j] = l;
            split_bf16(wp[j], h, l);
            Bh[0][(bn + j)*24 + bk] = h;
            Bl[0][(bn + j)*24 + bk] = l;
        }
    }
    __syncthreads();

    for (int s = 0; s < nsteps; s++) {
        int cur = s & 1;
        if (s + 1 < nsteps) {
            int kb = k0 + (s + 1)*16;
            va = *(const float4*)&A[(size_t)am * K + kb + ak];
            vb = make_float4(0.f, 0.f, 0.f, 0.f);
            if (col < N) vb = *(const float4*)&Bm[(size_t)(kb + bk) * N + col];
        }

        uint32_t cb = cur * 3072;   // byte offset of buffer
        uint32_t ah[4], al[4];
        uint32_t aoff = cb + (uint32_t)(mt*16 + a_row)*48 + a_k16;
        ldm_x4(ah, sAh + aoff);
        ldm_x4(al, sAl + aoff);
#pragma unroll
        for (int nt = 0; nt < 4; nt++) {
            uint32_t bhf[2], blf[2];
            uint32_t woff = cb + (uint32_t)((nh + nt)*8 + w_row)*48 + w_k16;
            ldm_x2(bhf, sBh + woff);
            ldm_x2(blf, sBl + woff);
            mma_bf16(acc[nt], ah, bhf);
            mma_bf16(acc[nt], al, bhf);
            mma_bf16(acc[nt], ah, blf);
        }

        if (s + 1 < nsteps) {
            int nx = cur ^ 1;
            const float* vp = (const float*)&va;
            const float* wp = (const float*)&vb;
            __nv_bfloat16 h, l;
#pragma unroll
            for (int j = 0; j < 4; j++) {
                split_bf16(vp[j], h, l);
                Ah[nx][am*24 + ak + j] = h;
                Al[nx][am*24 + ak + j] = l;
                split_bf16(wp[j], h, l);
                Bh[nx][(bn + j)*24 + bk] = h;
                Bl[nx][(bn + j)*24 + bk] = l;
            }
        }
        __syncthreads();
    }

    int s = blockIdx.y;
    int g = lane >> 2, c0 = (lane & 3) * 2;
#pragma unroll
    for (int nt = 0; nt < 4; nt++) {
#pragma unroll
        for (int half = 0; half < 2; half++) {
            int row = mt*16 + g + half*8;
            int ocol = n0 + (nh + nt)*8 + c0;
            if (ocol < N) {
                float* p = &g_part[((size_t)(s*64 + row)) * N + ocol];
                p[0] = acc[nt][half*2 + 0];
                p[1] = acc[nt][half*2 + 1];
            }
        }
    }
}

// ---------------- split-K reduce + bias + activation -----------------------
__global__ void gemm_reduce_kernel(const float* __restrict__ bias,
                                   int N, int nsplit, int relu, int stage)
{
    float* out = (stage == 0) ? g_fc1 : (stage == 1) ? g_fc2 : g_wb;
    int nv = N >> 2;
    int idx = blockIdx.x * 256 + threadIdx.x;
    if (idx >= 64 * nv) return;
    int m = idx / nv, f = idx - m * nv;
    float4 s = make_float4(0.f, 0.f, 0.f, 0.f);
    for (int sp = 0; sp < nsplit; sp++) {
        const float4* p = (const float4*)&g_part[(size_t)(sp*64 + m) * N];
        float4 v = p[f];
        s.x += v.x; s.y += v.y; s.z += v.z; s.w += v.w;
    }
    float4 bv = ((const float4*)bias)[f];
    s.x += bv.x; s.y += bv.y; s.z += bv.z; s.w += bv.w;
    if (relu) {
        s.x = fmaxf(s.x, 0.f); s.y = fmaxf(s.y, 0.f);
        s.z = fmaxf(s.z, 0.f); s.w = fmaxf(s.w, 0.f);
    }
    ((float4*)out)[(size_t)m * nv + f] = s;
}

// ---------------- dynamic per-tile conv via mma.sync, halo-A, W ping-pong --
// grid (2,8,64). block 256, 2 blocks/SM.
// smem: AH @0 (43520), AL @43520, W bufs @87040 (2 x (4096 hi + 4096 lo)),
//       bias @103424 (128). Total 103552.
__global__ __launch_bounds__(256, 2) void dynconv_hmma_kernel(float* __restrict__ out)
{
    extern __shared__ char smem[];
    const uint32_t AH = 0, AL = 43520, WB = 87040, BS = 103424;
    uint32_t sb = smem_u32(smem);
    int r = blockIdx.z;
    int b = r >> 4, t = r & 15;
    int ti = t >> 2, tj = t & 3;
    int y0 = ti*64 + blockIdx.y * 8;
    int x0 = tj*64 + blockIdx.x * 32;
    int tid = threadIdx.x, w = tid >> 5, lane = tid & 31;

    if (tid < 32) *(float*)(smem + BS + tid*4) = g_wb[(size_t)r*18464 + 18432 + tid];

    // build swizzled halo A once
    for (int i = tid; i < 2720; i += 256) {
        int hp = i >> 3, ch8 = i & 7;
        int hy = hp / 34, hx = hp - hy*34;
        int gy = y0 - 1 + hy, gx = x0 - 1 + hx;
        uint4 vh = {0,0,0,0}, vl = {0,0,0,0};
        if ((unsigned)gy < 256u && (unsigned)gx < 256u) {
            size_t g = ((size_t)(b*256 + gy)*256 + gx)*64 + ch8*8;
            vh = *(const uint4*)(g_fh + g);
            vl = *(const uint4*)(g_fl + g);
        }
        uint32_t off = SWZ(hp, ch8);
        *(uint4*)(smem + AH + off) = vh;
        *(uint4*)(smem + AL + off) = vl;
    }
    // preload W tap 0 into buf 0 (prepped bf16, coalesced uint4)
    const __nv_bfloat16* dwh = g_dwh + (size_t)r*9*2048;
    const __nv_bfloat16* dwl = g_dwl + (size_t)r*9*2048;
    int wr = tid >> 3, wc = tid & 7;
    {
        *(uint4*)(smem + WB + SWZ(wr, wc)) = *(const uint4*)(dwh + wr*64 + wc*8);
        *(uint4*)(smem + WB + 4096 + SWZ(wr, wc)) = *(const uint4*)(dwl + wr*64 + wc*8);
    }
    __syncthreads();

    float acc[2][4][4];
#pragma unroll
    for (int mt = 0; mt < 2; mt++)
#pragma unroll
        for (int nt = 0; nt < 4; nt++)
#pragma unroll
            for (int e = 0; e < 4; e++) acc[mt][nt][e] = 0.f;

    int a_row = lane & 15, a_cs = lane >> 4;
    int w_row = lane & 7,  w_cs = (lane >> 3) & 1;

    for (int tap = 0; tap < 9; tap++) {
        int dy = tap / 3 - 1, dx = tap % 3 - 1;
        int buf = tap & 1;
        uint32_t wb = WB + buf*8192;

        uint4 ph, pl;
        if (tap < 8) {
            ph = *(const uint4*)(dwh + (tap + 1)*2048 + wr*64 + wc*8);
            pl = *(const uint4*)(dwl + (tap + 1)*2048 + wr*64 + wc*8);
        }

        int rb = (w + dy + 1)*34 + dx + 1;
#pragma unroll
        for (int ks = 0; ks < 4; ks++) {
            uint32_t ah[2][4], al[2][4];
#pragma unroll
            for (int mt = 0; mt < 2; mt++) {
                int ar = rb + mt*16 + a_row;
                uint32_t aoff = SWZ(ar, ks*2 + a_cs);
                ldm_x4(ah[mt], sb + AH + aoff);
                ldm_x4(al[mt], sb + AL + aoff);
            }
#pragma unroll
            for (int nt = 0; nt < 4; nt++) {
                uint32_t wh[2], wl[2];
                uint32_t woff = SWZ(nt*8 + w_row, ks*2 + w_cs);
                ldm_x2(wh, sb + wb + woff);
                ldm_x2(wl, sb + wb + 4096 + woff);
                mma_bf16(acc[0][nt], ah[0], wh);
                mma_bf16(acc[1][nt], ah[1], wh);
                mma_bf16(acc[0][nt], al[0], wh);
                mma_bf16(acc[1][nt], al[1], wh);
                mma_bf16(acc[0][nt], ah[0], wl);
                mma_bf16(acc[1][nt], ah[1], wl);
            }
        }
        if (tap < 8) {
            uint32_t nb = WB + (buf ^ 1)*8192;
            *(uint4*)(smem + nb + SWZ(wr, wc)) = ph;
            *(uint4*)(smem + nb + 4096 + SWZ(wr, wc)) = pl;
        }
        __syncthreads();
    }

    const float* bsm = (const float*)(smem + BS);
    int g = lane >> 2, c0 = (lane & 3) * 2;
    int y = y0 + w;
#pragma unroll
    for (int mt = 0; mt < 2; mt++) {
#pragma unroll
        for (int half = 0; half < 2; half++) {
            int x = x0 + mt*16 + g + half*8;
            int pix = y*256 + x;
#pragma unroll
            for (int nt = 0; nt < 4; nt++) {
                int oc = nt*8 + c0;
                float v0 = acc[mt][nt][half*2 + 0] + bsm[oc];
                float v1 = acc[mt][nt][half*2 + 1] + bsm[oc + 1];
                out[(((size_t)(b*96 + 64 + oc)) << 16) + pix] = v0;
                out[(((size_t)(b*96 + 64 + oc + 1)) << 16) + pix] = v1;
            }
        }
    }
}

// ---------------- launch ---------------------------------------------------
extern "C" void kernel_launch(void* const* d_in, const int* in_sizes, int n_in,
                              void* d_out, int out_size)
{
    const float* feature = (const float*)d_in[0];
    const float* rw1 = (const float*)d_in[1];
    const float* rb1 = (const float*)d_in[2];
    const float* rw2 = (const float*)d_in[3];
    const float* rb2 = (const float*)d_in[4];
    const float* fw1 = (const float*)d_in[5];
    const float* fb1 = (const float*)d_in[6];
    const float* fw2 = (const float*)d_in[7];
    const float* fb2 = (const float*)d_in[8];
    const float* fw3 = (const float*)d_in[9];
    const float* fb3 = (const float*)d_in[10];
    float* out = (float*)d_out;

    const int CONV1_SMEM = 105984;
    const int DYN_SMEM = 103552;
    cudaFuncSetAttribute(conv1_hmma_kernel,
                         cudaFuncAttributeMaxDynamicSharedMemorySize, CONV1_SMEM);
    cudaFuncSetAttribute(dynconv_hmma_kernel,
                         cudaFuncAttributeMaxDynamicSharedMemorySize, DYN_SMEM);

    tohwc_kernel<<<4096, 256>>>(feature, out);
    wprep_kernel<<<144, 256>>>(rw1);
    conv1_hmma_kernel<<<dim3(8, 32, 4), 256, CONV1_SMEM>>>(rb1, rw2);
    conv2_sum_kernel<<<1024, 256>>>(rb2);
    pool_kernel<<<64, 256>>>();

    // FC1: 64x1024 @ 1024x2048, split-K 16 (HMMA ping-pong)
    gemm_hmma_kernel<<<dim3(32, 16), 256>>>(fw1, 1024, 2048, 64, 0);
    gemm_reduce_kernel<<<(64*512 + 255)/256, 256>>>(fb1, 2048, 16, 1, 0);
    // FC2: 64x2048 @ 2048x2048, split-K 16 (HMMA ping-pong)
    gemm_hmma_kernel<<<dim3(32, 16), 256>>>(fw2, 2048, 2048, 128, 1);
    gemm_reduce_kernel<<<(64*512 + 255)/256, 256>>>(fb2, 2048, 16, 1, 1);
    // FC3: 64x2048 @ 2048x18464, split-K 4 (HMMA ping-pong)
    gemm_hmma_kernel<<<dim3(289, 4), 256>>>(fw3, 2048, 18464, 512, 2);
    gemm_reduce_kernel<<<(64*4616 + 255)/256, 256>>>(fb3, 18464, 4, 0, 2);

    dynwprep_kernel<<<512, 256>>>();
    dynconv_hmma_kernel<<<dim3(2, 8, 64), 256, DYN_SMEM>>>(out);
}

// round 13
// speedup vs baseline: 3.2434x; 1.1594x over previous
#include <cuda_runtime.h>
#include <cuda_fp16.h>
#include <cstdint>
#include <math.h>

// Problem constants
// B=4, C=64, H=W=256, N_SPLIT=4 (T=16), RED_FC=32, OUT_NC=32, K=3, FMN1=FMN2=2048
// wsize = 32*64*9 = 18432, wb row = 18464

// ---------------- scratch (device globals; no runtime allocation) ----------
__device__ float g_u[9*4*65536];               // conv2 tap projections
__device__ float g_adap[4*65536];              // tanh(conv2)
__device__ float g_gram[64*1024];              // pooled grams
__device__ float g_fc1[64*2048];
__device__ float g_fc2[64*2048];
__device__ float g_wb[64*18464];               // dynamic weights + bias
__device__ float g_part[9453568];              // split-K partials
__device__ __half g_fh[4*256*256*64];          // feature NHWC fp16
__device__ __half g_w1h[9*64*64];              // rw1 [tap][oc][ic] hi
__device__ __half g_w1l[9*64*64];              // rw1 [tap][oc][ic] lo
__device__ __half g_dwh[64*9*32*64];           // dyn W [r][tap][oc][ic] hi
__device__ __half g_dwl[64*9*32*64];           // dyn W [r][tap][oc][ic] lo

// row-major 128B rows with XOR-16B swizzle (bank-conflict-free ldmatrix)
#define SWZ(row, chunk) ((uint32_t)(row)*128u + (((uint32_t)((chunk) ^ ((row) & 7))) * 16u))

// ---------------- mma.sync helpers (sm_80+ path, works on plain sm_103) ----
__device__ __forceinline__ uint32_t smem_u32(const void* p) {
    uint32_t a;
    asm("{ .reg .u64 t; cvta.to.shared.u64 t, %1; cvt.u32.u64 %0, t; }" : "=r"(a) : "l"(p));
    return a;
}
__device__ __forceinline__ void ldm_x4(uint32_t* r, uint32_t addr) {
    asm volatile("ldmatrix.sync.aligned.m8n8.x4.shared.b16 {%0,%1,%2,%3}, [%4];"
        : "=r"(r[0]), "=r"(r[1]), "=r"(r[2]), "=r"(r[3]) : "r"(addr));
}
__device__ __forceinline__ void ldm_x2(uint32_t* r, uint32_t addr) {
    asm volatile("ldmatrix.sync.aligned.m8n8.x2.shared.b16 {%0,%1}, [%2];"
        : "=r"(r[0]), "=r"(r[1]) : "r"(addr));
}
__device__ __forceinline__ void mma_f16(float* d, const uint32_t* a, const uint32_t* b) {
    asm volatile(
        "mma.sync.aligned.m16n8k16.row.col.f32.f16.f16.f32 "
        "{%0,%1,%2,%3}, {%4,%5,%6,%7}, {%8,%9}, {%0,%1,%2,%3};"
        : "+f"(d[0]), "+f"(d[1]), "+f"(d[2]), "+f"(d[3])
        : "r"(a[0]), "r"(a[1]), "r"(a[2]), "r"(a[3]), "r"(b[0]), "r"(b[1]));
}
__device__ __forceinline__ void split_f16(float v, __half& hi, __half& lo) {
    hi = __float2half_rn(v);
    lo = __float2half_rn(v - __half2float(hi));
}

// ---------------- NCHW fp32 -> NHWC fp16 (+ fused feature copy) ------------
__global__ __launch_bounds__(256) void tohwc_kernel(const float* __restrict__ feat,
                                                    float* __restrict__ out)
{
    __shared__ float s[64][65];
    int bx = blockIdx.x;
    int b = bx >> 10, grp = bx & 1023;
    int pix0 = grp * 64;
    int tid = threadIdx.x;
#pragma unroll
    for (int i = 0; i < 16; i++) {
        int idx = i * 256 + tid;
        int ic = idx >> 6, px = idx & 63;
        float v = feat[(((size_t)(b*64 + ic)) << 16) + pix0 + px];
        s[ic][px] = v;
        out[(((size_t)(b*96 + ic)) << 16) + pix0 + px] = v;   // fused passthrough
    }
    __syncthreads();
#pragma unroll
    for (int i = 0; i < 16; i++) {
        int idx = i * 256 + tid;
        int px = idx >> 6, ic = idx & 63;
        g_fh[((size_t)b*65536 + pix0 + px) * 64 + ic] = __float2half_rn(s[ic][px]);
    }
}

// ---------------- rw1 -> [tap][oc][ic] fp16 hi/lo --------------------------
__global__ void wprep_kernel(const float* __restrict__ rw1)
{
    int idx = blockIdx.x * 256 + threadIdx.x;
    if (idx >= 9*64*64) return;
    int tap = idx >> 12, rem = idx & 4095;
    int oc = rem >> 6, ic = rem & 63;
    __half hi, lo;
    split_f16(rw1[(oc*64 + ic)*9 + tap], hi, lo);
    g_w1h[idx] = hi; g_w1l[idx] = lo;
}

// ---------------- g_wb -> [r][tap][oc][ic] fp16 hi/lo ----------------------
__global__ void dynwprep_kernel()
{
    int idx = blockIdx.x * 256 + threadIdx.x;   // 64 * 2048
    if (idx >= 64*2048) return;
    int r = idx >> 11, rem = idx & 2047;        // rem = oc*64+ic
    const float* src = g_wb + (size_t)r*18464 + rem*9;
#pragma unroll
    for (int tap = 0; tap < 9; tap++) {
        __half h, l;
        split_f16(src[tap], h, l);
        size_t o = ((size_t)(r*9 + tap))*2048 + rem;
        g_dwh[o] = h; g_dwl[o] = l;
    }
}

// ---------------- conv1 via fp16 mma, halo-A, W ping-pong, conv2 proj ------
// grid (8,32,4). block 256 (8 warps), 2 blocks/SM. 1 sync per tap.
// smem: A @0 (43520), W bufs @43520 (2 x (8192 hi + 8192 lo) = 32768),
//       bias @76288 (256), w2 @76544 (2304). Total 78848.
__global__ __launch_bounds__(256, 2) void conv1_hmma_kernel(
    const float* __restrict__ rb1, const float* __restrict__ rw2)
{
    extern __shared__ char smem[];
    const uint32_t AS = 0, WB = 43520, BS = 76288, W2 = 76544;
    uint32_t sb = smem_u32(smem);
    int b = blockIdx.z;
    int y0 = blockIdx.y * 8, x0 = blockIdx.x * 32;
    int tid = threadIdx.x, w = tid >> 5, lane = tid & 31;

    if (tid < 64) *(float*)(smem + BS + tid*4) = rb1[tid];
    for (int i = tid; i < 576; i += 256) {
        int tap = i >> 6, ic = i & 63;
        *(float*)(smem + W2 + i*4) = rw2[ic*9 + tap];
    }

    // build swizzled halo A once: 340 rows (10x34 px) x 64 ic fp16
    for (int i = tid; i < 2720; i += 256) {
        int hp = i >> 3, ch8 = i & 7;
        int hy = hp / 34, hx = hp - hy*34;
        int gy = y0 - 1 + hy, gx = x0 - 1 + hx;
        uint4 vh = {0,0,0,0};
        if ((unsigned)gy < 256u && (unsigned)gx < 256u)
            vh = *(const uint4*)(g_fh + ((size_t)(b*256 + gy)*256 + gx)*64 + ch8*8);
        *(uint4*)(smem + AS + SWZ(hp, ch8)) = vh;
    }
    // preload W tap 0 into buf 0 (hi @+0, lo @+8192)
    int wr1 = tid >> 3, wc1 = tid & 7;        // rows 0..31
    int wr2 = wr1 + 32, wc2 = wc1;            // rows 32..63
    {
        *(uint4*)(smem + WB + SWZ(wr1, wc1)) = *(const uint4*)(g_w1h + wr1*64 + wc1*8);
        *(uint4*)(smem + WB + SWZ(wr2, wc2)) = *(const uint4*)(g_w1h + wr2*64 + wc2*8);
        *(uint4*)(smem + WB + 8192 + SWZ(wr1, wc1)) = *(const uint4*)(g_w1l + wr1*64 + wc1*8);
        *(uint4*)(smem + WB + 8192 + SWZ(wr2, wc2)) = *(const uint4*)(g_w1l + wr2*64 + wc2*8);
    }
    __syncthreads();

    float acc[2][8][4];
#pragma unroll
    for (int mt = 0; mt < 2; mt++)
#pragma unroll
        for (int nt = 0; nt < 8; nt++)
#pragma unroll
            for (int e = 0; e < 4; e++) acc[mt][nt][e] = 0.f;

    int a_row = lane & 15, a_cs = lane >> 4;
    int w_row = lane & 7,  w_cs = (lane >> 3) & 1;

    for (int tap = 0; tap < 9; tap++) {
        int dy = tap / 3 - 1, dx = tap % 3 - 1;
        int buf = tap & 1;
        uint32_t wb = WB + buf*16384;

        uint4 ph1, ph2, pl1, pl2;
        if (tap < 8) {
            size_t gb = (size_t)(tap + 1)*4096;
            ph1 = *(const uint4*)(g_w1h + gb + wr1*64 + wc1*8);
            ph2 = *(const uint4*)(g_w1h + gb + wr2*64 + wc2*8);
            pl1 = *(const uint4*)(g_w1l + gb + wr1*64 + wc1*8);
            pl2 = *(const uint4*)(g_w1l + gb + wr2*64 + wc2*8);
        }

        int rb = (w + dy + 1)*34 + dx + 1;
#pragma unroll
        for (int ks = 0; ks < 4; ks++) {
            uint32_t a[2][4];
#pragma unroll
            for (int mt = 0; mt < 2; mt++) {
                int ar = rb + mt*16 + a_row;
                ldm_x4(a[mt], sb + AS + SWZ(ar, ks*2 + a_cs));
            }
#pragma unroll
            for (int nt = 0; nt < 8; nt++) {
                uint32_t wh[2], wl[2];
                uint32_t woff = SWZ(nt*8 + w_row, ks*2 + w_cs);
                ldm_x2(wh, sb + wb + woff);
                ldm_x2(wl, sb + wb + 8192 + woff);
                mma_f16(acc[0][nt], a[0], wh);
                mma_f16(acc[1][nt], a[1], wh);
                mma_f16(acc[0][nt], a[0], wl);
                mma_f16(acc[1][nt], a[1], wl);
            }
        }
        if (tap < 8) {
            uint32_t nb = WB + (buf ^ 1)*16384;
            *(uint4*)(smem + nb + SWZ(wr1, wc1)) = ph1;
            *(uint4*)(smem + nb + SWZ(wr2, wc2)) = ph2;
            *(uint4*)(smem + nb + 8192 + SWZ(wr1, wc1)) = pl1;
            *(uint4*)(smem + nb + 8192 + SWZ(wr2, wc2)) = pl2;
        }
        __syncthreads();
    }

    // epilogue: bias + leaky relu, then 9 tap-dot projections (quad reduce)
    const float* bs = (const float*)(smem + BS);
    const float* w2 = (const float*)(smem + W2);
    int g = lane >> 2, c0 = (lane & 3) * 2;
    int y = y0 + w;
#pragma unroll
    for (int mt = 0; mt < 2; mt++) {
#pragma unroll
        for (int half = 0; half < 2; half++) {
            int x = x0 + mt*16 + g + half*8;
            float part[9];
#pragma unroll
            for (int t = 0; t < 9; t++) part[t] = 0.f;
#pragma unroll
            for (int nt = 0; nt < 8; nt++) {
                int oc = nt*8 + c0;
                float v0 = acc[mt][nt][half*2 + 0] + bs[oc];
                float v1 = acc[mt][nt][half*2 + 1] + bs[oc + 1];
                v0 = (v0 >= 0.f) ? v0 : 0.2f * v0;
                v1 = (v1 >= 0.f) ? v1 : 0.2f * v1;
#pragma unroll
                for (int t = 0; t < 9; t++)
                    part[t] += v0 * w2[t*64 + oc] + v1 * w2[t*64 + oc + 1];
            }
#pragma unroll
            for (int t = 0; t < 9; t++) {
                part[t] += __shfl_xor_sync(0xFFFFFFFFu, part[t], 1);
                part[t] += __shfl_xor_sync(0xFFFFFFFFu, part[t], 2);
            }
            if ((lane & 3) == 0) {
                int pix = y*256 + x;
#pragma unroll
                for (int t = 0; t < 9; t++)
                    g_u[t*262144 + b*65536 + pix] = part[t];
            }
        }
    }
}

// ---------------- conv2 sum: adap = tanh(sum of shifted taps + bias) -------
__global__ __launch_bounds__(256) void conv2_sum_kernel(const float* __restrict__ rb2)
{
    int P = blockIdx.x * 256 + threadIdx.x;
    int b = P >> 16, pix = P & 65535;
    int y = pix >> 8, x = pix & 255;
    float s = 0.f;
#pragma unroll
    for (int t = 0; t < 9; t++) {
        int yy = y + t/3 - 1, xx = x + t%3 - 1;
        if ((unsigned)yy < 256u && (unsigned)xx < 256u)
            s += g_u[t*262144 + b*65536 + yy*256 + xx];
    }
    g_adap[(size_t)b*65536 + pix] = tanhf(s + rb2[0]);
}

// ---------------- adaptive pool per tile -> gram ---------------------------
__global__ void pool_kernel()
{
    __shared__ float win[66][67];
    int r = blockIdx.x;
    int b = r >> 4, t = r & 15;
    int ti = t >> 2, tj = t & 3;
    int tid = threadIdx.x;
    for (int i = tid; i < 66*66; i += 256) {
        int h = i / 66, w = i % 66;
        int gy = ti*64 - 1 + h, gx = tj*64 - 1 + w;
        float v = 0.f;
        if ((unsigned)gy < 256u && (unsigned)gx < 256u)
            v = g_adap[((size_t)b*256 + gy) * 256 + gx];
        win[h][w] = v;
    }
    __syncthreads();
    for (int i = tid; i < 1024; i += 256) {
        int p = i >> 5, q = i & 31;
        int sp = (p*66) >> 5, ep = ((p+1)*66 + 31) >> 5;
        int sq = (q*66) >> 5, eq = ((q+1)*66 + 31) >> 5;
        float s = 0.f;
        for (int h = sp; h < ep; h++)
            for (int w = sq; w < eq; w++)
                s += win[h][w];
        g_gram[r*1024 + i] = s / (float)((ep - sp) * (eq - sq));
    }
}

// ---------------- fp16 split-K FC GEMM (ping-pong): part[s] = A @ B --------
// A fp16 single, B (weights) fp16 hi/lo -> 2 products. 1 barrier per step.
__global__ __launch_bounds__(256) void gemm_hmma_kernel(
    const float* __restrict__ Bm, int K, int N, int KC, int stage)
{
    const float* __restrict__ A = (stage == 0) ? g_gram : (stage == 1) ? g_fc1 : g_fc2;

    __shared__ __half Ah[2][1536];               // [buf][m*24 + k]
    __shared__ __half Bh[2][1536], Bl[2][1536];  // [buf][n*24 + k]

    int n0 = blockIdx.x * 64;
    int k0 = blockIdx.y * KC;
    int tid = threadIdx.x, w = tid >> 5, lane = tid & 31;
    int mt = w >> 1;
    int nh = (w & 1) * 4;

    float acc[4][4];
#pragma unroll
    for (int nt = 0; nt < 4; nt++)
#pragma unroll
        for (int e = 0; e < 4; e++) acc[nt][e] = 0.f;

    uint32_t a_row = lane & 15, a_k16 = (lane >> 4) * 16;
    uint32_t w_row = lane & 7,  w_k16 = ((lane >> 3) & 1) * 16;
    uint32_t sAh = smem_u32(Ah);
    uint32_t sBh = smem_u32(Bh), sBl = smem_u32(Bl);

    int am = tid >> 2, ak = (tid & 3) * 4;
    int bk = tid >> 4, bn = (tid & 15) * 4;
    int col = n0 + bn;
    int nsteps = KC >> 4;

    float4 va = *(const float4*)&A[(size_t)am * K + k0 + ak];
    float4 vb = make_float4(0.f, 0.f, 0.f, 0.f);
    if (col < N) vb = *(const float4*)&Bm[(size_t)(k0 + bk) * N + col];
    {
        const float* vp = (const float*)&va;
        const float* wp = (const float*)&vb;
        __half h, l;
#pragma unroll
        for (int j = 0; j < 4; j++) {
            Ah[0][am*24 + ak + j] = __float2half_rn(vp[j]);
            split_f16(wp[j], h, l);
            Bh[0][(bn + j)*24 + bk] = h;
            Bl[0][(bn + j)*24 + bk] = l;
        }
    }
    __syncthreads();

    for (int s = 0; s < nsteps; s++) {
        int cur = s & 1;
        if (s + 1 < nsteps) {
            int kb = k0 + (s + 1)*16;
            va = *(const float4*)&A[(size_t)am * K + kb + ak];
            vb = make_float4(0.f, 0.f, 0.f, 0.f);
            if (col < N) vb = *(const float4*)&Bm[(size_t)(kb + bk) * N + col];
        }

        uint32_t cb = cur * 3072;
        uint32_t a[4];
        ldm_x4(a, sAh + cb + (uint32_t)(mt*16 + a_row)*48 + a_k16);
#pragma unroll
        for (int nt = 0; nt < 4; nt++) {
            uint32_t bhf[2], blf[2];
            uint32_t woff = cb + (uint32_t)((nh + nt)*8 + w_row)*48 + w_k16;
            ldm_x2(bhf, sBh + woff);
            ldm_x2(blf, sBl + woff);
            mma_f16(acc[nt], a, bhf);
            mma_f16(acc[nt], a, blf);
        }

        if (s + 1 < nsteps) {
            int nx = cur ^ 1;
            const float* vp = (const float*)&va;
            const float* wp = (const float*)&vb;
            __half h, l;
#pragma unroll
            for (int j = 0; j < 4; j++) {
                Ah[nx][am*24 + ak + j] = __float2half_rn(vp[j]);
                split_f16(wp[j], h, l);
                Bh[nx][(bn + j)*24 + bk] = h;
                Bl[nx][(bn + j)*24 + bk] = l;
            }
        }
        __syncthreads();
    }

    int s = blockIdx.y;
    int g = lane >> 2, c0 = (lane & 3) * 2;
#pragma unroll
    for (int nt = 0; nt < 4; nt++) {
#pragma unroll
        for (int half = 0; half < 2; half++) {
            int row = mt*16 + g + half*8;
            int ocol = n0 + (nh + nt)*8 + c0;
            if (ocol < N) {
                float* p = &g_part[((size_t)(s*64 + row)) * N + ocol];
                p[0] = acc[nt][half*2 + 0];
                p[1] = acc[nt][half*2 + 1];
            }
        }
    }
}

// ---------------- split-K reduce + bias + activation -----------------------
__global__ void gemm_reduce_kernel(const float* __restrict__ bias,
                                   int N, int nsplit, int relu, int stage)
{
    float* out = (stage == 0) ? g_fc1 : (stage == 1) ? g_fc2 : g_wb;
    int nv = N >> 2;
    int idx = blockIdx.x * 256 + threadIdx.x;
    if (idx >= 64 * nv) return;
    int m = idx / nv, f = idx - m * nv;
    float4 s = make_float4(0.f, 0.f, 0.f, 0.f);
    for (int sp = 0; sp < nsplit; sp++) {
        const float4* p = (const float4*)&g_part[(size_t)(sp*64 + m) * N];
        float4 v = p[f];
        s.x += v.x; s.y += v.y; s.z += v.z; s.w += v.w;
    }
    float4 bv = ((const float4*)bias)[f];
    s.x += bv.x; s.y += bv.y; s.z += bv.z; s.w += bv.w;
    if (relu) {
        s.x = fmaxf(s.x, 0.f); s.y = fmaxf(s.y, 0.f);
        s.z = fmaxf(s.z, 0.f); s.w = fmaxf(s.w, 0.f);
    }
    ((float4*)out)[(size_t)m * nv + f] = s;
}

// ---------------- dynamic per-tile conv via fp16 mma, halo-A, W ping-pong --
// grid (2,8,64). block 256, 2 blocks/SM.
// smem: A @0 (43520), W bufs @43520 (2 x (4096 hi + 4096 lo) = 16384),
//       bias @59904 (128). Total 60032.
__global__ __launch_bounds__(256, 2) void dynconv_hmma_kernel(float* __restrict__ out)
{
    extern __shared__ char smem[];
    const uint32_t AS = 0, WB = 43520, BS = 59904;
    uint32_t sb = smem_u32(smem);
    int r = blockIdx.z;
    int b = r >> 4, t = r & 15;
    int ti = t >> 2, tj = t & 3;
    int y0 = ti*64 + blockIdx.y * 8;
    int x0 = tj*64 + blockIdx.x * 32;
    int tid = threadIdx.x, w = tid >> 5, lane = tid & 31;

    if (tid < 32) *(float*)(smem + BS + tid*4) = g_wb[(size_t)r*18464 + 18432 + tid];

    // build swizzled halo A once (fp16)
    for (int i = tid; i < 2720; i += 256) {
        int hp = i >> 3, ch8 = i & 7;
        int hy = hp / 34, hx = hp - hy*34;
        int gy = y0 - 1 + hy, gx = x0 - 1 + hx;
        uint4 vh = {0,0,0,0};
        if ((unsigned)gy < 256u && (unsigned)gx < 256u)
            vh = *(const uint4*)(g_fh + ((size_t)(b*256 + gy)*256 + gx)*64 + ch8*8);
        *(uint4*)(smem + AS + SWZ(hp, ch8)) = vh;
    }
    // preload W tap 0 into buf 0
    const __half* dwh = g_dwh + (size_t)r*9*2048;
    const __half* dwl = g_dwl + (size_t)r*9*2048;
    int wr = tid >> 3, wc = tid & 7;
    {
        *(uint4*)(smem + WB + SWZ(wr, wc)) = *(const uint4*)(dwh + wr*64 + wc*8);
        *(uint4*)(smem + WB + 4096 + SWZ(wr, wc)) = *(const uint4*)(dwl + wr*64 + wc*8);
    }
    __syncthreads();

    float acc[2][4][4];
#pragma unroll
    for (int mt = 0; mt < 2; mt++)
#pragma unroll
        for (int nt = 0; nt < 4; nt++)
#pragma unroll
            for (int e = 0; e < 4; e++) acc[mt][nt][e] = 0.f;

    int a_row = lane & 15, a_cs = lane >> 4;
    int w_row = lane & 7,  w_cs = (lane >> 3) & 1;

    for (int tap = 0; tap < 9; tap++) {
        int dy = tap / 3 - 1, dx = tap % 3 - 1;
        int buf = tap & 1;
        uint32_t wb = WB + buf*8192;

        uint4 ph, pl;
        if (tap < 8) {
            ph = *(const uint4*)(dwh + (tap + 1)*2048 + wr*64 + wc*8);
            pl = *(const uint4*)(dwl + (tap + 1)*2048 + wr*64 + wc*8);
        }

        int rb = (w + dy + 1)*34 + dx + 1;
#pragma unroll
        for (int ks = 0; ks < 4; ks++) {
            uint32_t a[2][4];
#pragma unroll
            for (int mt = 0; mt < 2; mt++) {
                int ar = rb + mt*16 + a_row;
                ldm_x4(a[mt], sb + AS + SWZ(ar, ks*2 + a_cs));
            }
#pragma unroll
            for (int nt = 0; nt < 4; nt++) {
                uint32_t wh[2], wl[2];
                uint32_t woff = SWZ(nt*8 + w_row, ks*2 + w_cs);
                ldm_x2(wh, sb + wb + woff);
                ldm_x2(wl, sb + wb + 4096 + woff);
                mma_f16(acc[0][nt], a[0], wh);
                mma_f16(acc[1][nt], a[1], wh);
                mma_f16(acc[0][nt], a[0], wl);
                mma_f16(acc[1][nt], a[1], wl);
            }
        }
        if (tap < 8) {
            uint32_t nb = WB + (buf ^ 1)*8192;
            *(uint4*)(smem + nb + SWZ(wr, wc)) = ph;
            *(uint4*)(smem + nb + 4096 + SWZ(wr, wc)) = pl;
        }
        __syncthreads();
    }

    const float* bsm = (const float*)(smem + BS);
    int g = lane >> 2, c0 = (lane & 3) * 2;
    int y = y0 + w;
#pragma unroll
    for (int mt = 0; mt < 2; mt++) {
#pragma unroll
        for (int half = 0; half < 2; half++) {
            int x = x0 + mt*16 + g + half*8;
            int pix = y*256 + x;
#pragma unroll
            for (int nt = 0; nt < 4; nt++) {
                int oc = nt*8 + c0;
                float v0 = acc[mt][nt][half*2 + 0] + bsm[oc];
                float v1 = acc[mt][nt][half*2 + 1] + bsm[oc + 1];
                out[(((size_t)(b*96 + 64 + oc)) << 16) + pix] = v0;
                out[(((size_t)(b*96 + 64 + oc + 1)) << 16) + pix] = v1;
            }
        }
    }
}

// ---------------- launch ---------------------------------------------------
extern "C" void kernel_launch(void* const* d_in, const int* in_sizes, int n_in,
                              void* d_out, int out_size)
{
    const float* feature = (const float*)d_in[0];
    const float* rw1 = (const float*)d_in[1];
    const float* rb1 = (const float*)d_in[2];
    const float* rw2 = (const float*)d_in[3];
    const float* rb2 = (const float*)d_in[4];
    const float* fw1 = (const float*)d_in[5];
    const float* fb1 = (const float*)d_in[6];
    const float* fw2 = (const float*)d_in[7];
    const float* fb2 = (const float*)d_in[8];
    const float* fw3 = (const float*)d_in[9];
    const float* fb3 = (const float*)d_in[10];
    float* out = (float*)d_out;

    const int CONV1_SMEM = 78848;
    const int DYN_SMEM = 60032;
    cudaFuncSetAttribute(conv1_hmma_kernel,
                         cudaFuncAttributeMaxDynamicSharedMemorySize, CONV1_SMEM);
    cudaFuncSetAttribute(dynconv_hmma_kernel,
                         cudaFuncAttributeMaxDynamicSharedMemorySize, DYN_SMEM);

    tohwc_kernel<<<4096, 256>>>(feature, out);
    wprep_kernel<<<144, 256>>>(rw1);
    conv1_hmma_kernel<<<dim3(8, 32, 4), 256, CONV1_SMEM>>>(rb1, rw2);
    conv2_sum_kernel<<<1024, 256>>>(rb2);
    pool_kernel<<<64, 256>>>();

    // FC1: 64x1024 @ 1024x2048, split-K 16 (fp16 ping-pong)
    gemm_hmma_kernel<<<dim3(32, 16), 256>>>(fw1, 1024, 2048, 64, 0);
    gemm_reduce_kernel<<<(64*512 + 255)/256, 256>>>(fb1, 2048, 16, 1, 0);
    // FC2: 64x2048 @ 2048x2048, split-K 16 (fp16 ping-pong)
    gemm_hmma_kernel<<<dim3(32, 16), 256>>>(fw2, 2048, 2048, 128, 1);
    gemm_reduce_kernel<<<(64*512 + 255)/256, 256>>>(fb2, 2048, 16, 1, 1);
    // FC3: 64x2048 @ 2048x18464, split-K 4 (fp16 ping-pong)
    gemm_hmma_kernel<<<dim3(289, 4), 256>>>(fw3, 2048, 18464, 512, 2);
    gemm_reduce_kernel<<<(64*4616 + 255)/256, 256>>>(fb3, 18464, 4, 0, 2);

    dynwprep_kernel<<<512, 256>>>();
    dynconv_hmma_kernel<<<dim3(2, 8, 64), 256, DYN_SMEM>>>(out);
}

// round 14
// speedup vs baseline: 4.2711x; 1.3168x over previous
#include <cuda_runtime.h>
#include <cuda_fp16.h>
#include <cstdint>
#include <math.h>

// Problem constants
// B=4, C=64, H=W=256, N_SPLIT=4 (T=16), RED_FC=32, OUT_NC=32, K=3, FMN1=FMN2=2048
// wsize = 32*64*9 = 18432, wb row = 18464

// ---------------- scratch (device globals; no runtime allocation) ----------
__device__ float g_u[9*4*65536];               // conv2 tap projections
__device__ float g_adap[4*65536];              // tanh(conv2)
__device__ float g_gram[64*1024];              // pooled grams
__device__ float g_fc1[64*2048];
__device__ float g_fc2[64*2048];
__device__ float g_wb[64*18464];               // dynamic weights + bias
__device__ float g_part[9453568];              // split-K partials
__device__ __half g_fh[4*256*256*64];          // feature NHWC fp16
__device__ __half g_w1h[9*64*64];              // rw1 [tap][oc][ic] fp16
__device__ __half g_dwh[64*9*32*64];           // dyn W [r][tap][oc][ic] fp16

// row-major 128B rows with XOR-16B swizzle (bank-conflict-free ldmatrix)
#define SWZ(row, chunk) ((uint32_t)(row)*128u + (((uint32_t)((chunk) ^ ((row) & 7))) * 16u))

// ---------------- mma.sync helpers (sm_80+ path, works on plain sm_103) ----
__device__ __forceinline__ uint32_t smem_u32(const void* p) {
    uint32_t a;
    asm("{ .reg .u64 t; cvta.to.shared.u64 t, %1; cvt.u32.u64 %0, t; }" : "=r"(a) : "l"(p));
    return a;
}
__device__ __forceinline__ void ldm_x4(uint32_t* r, uint32_t addr) {
    asm volatile("ldmatrix.sync.aligned.m8n8.x4.shared.b16 {%0,%1,%2,%3}, [%4];"
        : "=r"(r[0]), "=r"(r[1]), "=r"(r[2]), "=r"(r[3]) : "r"(addr));
}
__device__ __forceinline__ void ldm_x2(uint32_t* r, uint32_t addr) {
    asm volatile("ldmatrix.sync.aligned.m8n8.x2.shared.b16 {%0,%1}, [%2];"
        : "=r"(r[0]), "=r"(r[1]) : "r"(addr));
}
__device__ __forceinline__ void mma_f16(float* d, const uint32_t* a, const uint32_t* b) {
    asm volatile(
        "mma.sync.aligned.m16n8k16.row.col.f32.f16.f16.f32 "
        "{%0,%1,%2,%3}, {%4,%5,%6,%7}, {%8,%9}, {%0,%1,%2,%3};"
        : "+f"(d[0]), "+f"(d[1]), "+f"(d[2]), "+f"(d[3])
        : "r"(a[0]), "r"(a[1]), "r"(a[2]), "r"(a[3]), "r"(b[0]), "r"(b[1]));
}

// ---------------- NCHW fp32 -> NHWC fp16 (+ fused feature copy) ------------
__global__ __launch_bounds__(256) void tohwc_kernel(const float* __restrict__ feat,
                                                    float* __restrict__ out)
{
    __shared__ float s[64][65];
    int bx = blockIdx.x;
    int b = bx >> 10, grp = bx & 1023;
    int pix0 = grp * 64;
    int tid = threadIdx.x;
#pragma unroll
    for (int i = 0; i < 16; i++) {
        int idx = i * 256 + tid;
        int ic = idx >> 6, px = idx & 63;
        float v = feat[(((size_t)(b*64 + ic)) << 16) + pix0 + px];
        s[ic][px] = v;
        out[(((size_t)(b*96 + ic)) << 16) + pix0 + px] = v;   // fused passthrough
    }
    __syncthreads();
#pragma unroll
    for (int i = 0; i < 16; i++) {
        int idx = i * 256 + tid;
        int px = idx >> 6, ic = idx & 63;
        g_fh[((size_t)b*65536 + pix0 + px) * 64 + ic] = __float2half_rn(s[ic][px]);
    }
}

// ---------------- rw1 -> [tap][oc][ic] fp16 --------------------------------
__global__ void wprep_kernel(const float* __restrict__ rw1)
{
    int idx = blockIdx.x * 256 + threadIdx.x;
    if (idx >= 9*64*64) return;
    int tap = idx >> 12, rem = idx & 4095;
    int oc = rem >> 6, ic = rem & 63;
    g_w1h[idx] = __float2half_rn(rw1[(oc*64 + ic)*9 + tap]);
}

// ---------------- g_wb -> [r][tap][oc][ic] fp16 ----------------------------
__global__ void dynwprep_kernel()
{
    int idx = blockIdx.x * 256 + threadIdx.x;   // 64 * 2048
    if (idx >= 64*2048) return;
    int r = idx >> 11, rem = idx & 2047;        // rem = oc*64+ic
    const float* src = g_wb + (size_t)r*18464 + rem*9;
#pragma unroll
    for (int tap = 0; tap < 9; tap++)
        g_dwh[((size_t)(r*9 + tap))*2048 + rem] = __float2half_rn(src[tap]);
}

// ---------------- conv1 via fp16 mma, halo-A, W ping-pong, conv2 proj ------
// grid (8,32,4). block 256 (8 warps), 2 blocks/SM. 1 sync per tap.
// smem: A @0 (43520), W bufs @43520 (2 x 8192 = 16384),
//       bias @59904 (256), w2 @60160 (2304). Total 62464.
__global__ __launch_bounds__(256, 2) void conv1_hmma_kernel(
    const float* __restrict__ rb1, const float* __restrict__ rw2)
{
    extern __shared__ char smem[];
    const uint32_t AS = 0, WB = 43520, BS = 59904, W2 = 60160;
    uint32_t sb = smem_u32(smem);
    int b = blockIdx.z;
    int y0 = blockIdx.y * 8, x0 = blockIdx.x * 32;
    int tid = threadIdx.x, w = tid >> 5, lane = tid & 31;

    if (tid < 64) *(float*)(smem + BS + tid*4) = rb1[tid];
    for (int i = tid; i < 576; i += 256) {
        int tap = i >> 6, ic = i & 63;
        *(float*)(smem + W2 + i*4) = rw2[ic*9 + tap];
    }

    // build swizzled halo A once: 340 rows (10x34 px) x 64 ic fp16
    for (int i = tid; i < 2720; i += 256) {
        int hp = i >> 3, ch8 = i & 7;
        int hy = hp / 34, hx = hp - hy*34;
        int gy = y0 - 1 + hy, gx = x0 - 1 + hx;
        uint4 vh = {0,0,0,0};
        if ((unsigned)gy < 256u && (unsigned)gx < 256u)
            vh = *(const uint4*)(g_fh + ((size_t)(b*256 + gy)*256 + gx)*64 + ch8*8);
        *(uint4*)(smem + AS + SWZ(hp, ch8)) = vh;
    }
    // preload W tap 0 into buf 0
    int wr1 = tid >> 3, wc1 = tid & 7;        // rows 0..31
    int wr2 = wr1 + 32, wc2 = wc1;            // rows 32..63
    {
        *(uint4*)(smem + WB + SWZ(wr1, wc1)) = *(const uint4*)(g_w1h + wr1*64 + wc1*8);
        *(uint4*)(smem + WB + SWZ(wr2, wc2)) = *(const uint4*)(g_w1h + wr2*64 + wc2*8);
    }
    __syncthreads();

    float acc[2][8][4];
#pragma unroll
    for (int mt = 0; mt < 2; mt++)
#pragma unroll
        for (int nt = 0; nt < 8; nt++)
#pragma unroll
            for (int e = 0; e < 4; e++) acc[mt][nt][e] = 0.f;

    int a_row = lane & 15, a_cs = lane >> 4;
    int w_row = lane & 7,  w_cs = (lane >> 3) & 1;

    for (int tap = 0; tap < 9; tap++) {
        int dy = tap / 3 - 1, dx = tap % 3 - 1;
        int buf = tap & 1;
        uint32_t wb = WB + buf*8192;

        uint4 ph1, ph2;
        if (tap < 8) {
            size_t gb = (size_t)(tap + 1)*4096;
            ph1 = *(const uint4*)(g_w1h + gb + wr1*64 + wc1*8);
            ph2 = *(const uint4*)(g_w1h + gb + wr2*64 + wc2*8);
        }

        int rb = (w + dy + 1)*34 + dx + 1;
#pragma unroll
        for (int ks = 0; ks < 4; ks++) {
            uint32_t a[2][4];
#pragma unroll
            for (int mt = 0; mt < 2; mt++) {
                int ar = rb + mt*16 + a_row;
                ldm_x4(a[mt], sb + AS + SWZ(ar, ks*2 + a_cs));
            }
#pragma unroll
            for (int nt = 0; nt < 8; nt++) {
                uint32_t wh[2];
                ldm_x2(wh, sb + wb + SWZ(nt*8 + w_row, ks*2 + w_cs));
                mma_f16(acc[0][nt], a[0], wh);
                mma_f16(acc[1][nt], a[1], wh);
            }
        }
        if (tap < 8) {
            uint32_t nb = WB + (buf ^ 1)*8192;
            *(uint4*)(smem + nb + SWZ(wr1, wc1)) = ph1;
            *(uint4*)(smem + nb + SWZ(wr2, wc2)) = ph2;
        }
        __syncthreads();
    }

    // epilogue: bias + leaky relu, then 9 tap-dot projections (quad reduce)
    const float* bs = (const float*)(smem + BS);
    const float* w2 = (const float*)(smem + W2);
    int g = lane >> 2, c0 = (lane & 3) * 2;
    int y = y0 + w;
#pragma unroll
    for (int mt = 0; mt < 2; mt++) {
#pragma unroll
        for (int half = 0; half < 2; half++) {
            int x = x0 + mt*16 + g + half*8;
            float part[9];
#pragma unroll
            for (int t = 0; t < 9; t++) part[t] = 0.f;
#pragma unroll
            for (int nt = 0; nt < 8; nt++) {
                int oc = nt*8 + c0;
                float v0 = acc[mt][nt][half*2 + 0] + bs[oc];
                float v1 = acc[mt][nt][half*2 + 1] + bs[oc + 1];
                v0 = (v0 >= 0.f) ? v0 : 0.2f * v0;
                v1 = (v1 >= 0.f) ? v1 : 0.2f * v1;
#pragma unroll
                for (int t = 0; t < 9; t++)
                    part[t] += v0 * w2[t*64 + oc] + v1 * w2[t*64 + oc + 1];
            }
#pragma unroll
            for (int t = 0; t < 9; t++) {
                part[t] += __shfl_xor_sync(0xFFFFFFFFu, part[t], 1);
                part[t] += __shfl_xor_sync(0xFFFFFFFFu, part[t], 2);
            }
            if ((lane & 3) == 0) {
                int pix = y*256 + x;
#pragma unroll
                for (int t = 0; t < 9; t++)
                    g_u[t*262144 + b*65536 + pix] = part[t];
            }
        }
    }
}

// ---------------- conv2 sum: adap = tanh(sum of shifted taps + bias) -------
__global__ __launch_bounds__(256) void conv2_sum_kernel(const float* __restrict__ rb2)
{
    int P = blockIdx.x * 256 + threadIdx.x;
    int b = P >> 16, pix = P & 65535;
    int y = pix >> 8, x = pix & 255;
    float s = 0.f;
#pragma unroll
    for (int t = 0; t < 9; t++) {
        int yy = y + t/3 - 1, xx = x + t%3 - 1;
        if ((unsigned)yy < 256u && (unsigned)xx < 256u)
            s += g_u[t*262144 + b*65536 + yy*256 + xx];
    }
    g_adap[(size_t)b*65536 + pix] = tanhf(s + rb2[0]);
}

// ---------------- adaptive pool per tile -> gram ---------------------------
__global__ void pool_kernel()
{
    __shared__ float win[66][67];
    int r = blockIdx.x;
    int b = r >> 4, t = r & 15;
    int ti = t >> 2, tj = t & 3;
    int tid = threadIdx.x;
    for (int i = tid; i < 66*66; i += 256) {
        int h = i / 66, w = i % 66;
        int gy = ti*64 - 1 + h, gx = tj*64 - 1 + w;
        float v = 0.f;
        if ((unsigned)gy < 256u && (unsigned)gx < 256u)
            v = g_adap[((size_t)b*256 + gy) * 256 + gx];
        win[h][w] = v;
    }
    __syncthreads();
    for (int i = tid; i < 1024; i += 256) {
        int p = i >> 5, q = i & 31;
        int sp = (p*66) >> 5, ep = ((p+1)*66 + 31) >> 5;
        int sq = (q*66) >> 5, eq = ((q+1)*66 + 31) >> 5;
        float s = 0.f;
        for (int h = sp; h < ep; h++)
            for (int w = sq; w < eq; w++)
                s += win[h][w];
        g_gram[r*1024 + i] = s / (float)((ep - sp) * (eq - sq));
    }
}

// ---------------- fp16 split-K FC GEMM (ping-pong): part[s] = A @ B --------
// A fp16, B fp16 -> 1 product. 1 barrier per k16-step.
__global__ __launch_bounds__(256) void gemm_hmma_kernel(
    const float* __restrict__ Bm, int K, int N, int KC, int stage)
{
    const float* __restrict__ A = (stage == 0) ? g_gram : (stage == 1) ? g_fc1 : g_fc2;

    __shared__ __half Ah[2][1536];   // [buf][m*24 + k]
    __shared__ __half Bh[2][1536];   // [buf][n*24 + k]

    int n0 = blockIdx.x * 64;
    int k0 = blockIdx.y * KC;
    int tid = threadIdx.x, w = tid >> 5, lane = tid & 31;
    int mt = w >> 1;
    int nh = (w & 1) * 4;

    float acc[4][4];
#pragma unroll
    for (int nt = 0; nt < 4; nt++)
#pragma unroll
        for (int e = 0; e < 4; e++) acc[nt][e] = 0.f;

    uint32_t a_row = lane & 15, a_k16 = (lane >> 4) * 16;
    uint32_t w_row = lane & 7,  w_k16 = ((lane >> 3) & 1) * 16;
    uint32_t sAh = smem_u32(Ah);
    uint32_t sBh = smem_u32(Bh);

    int am = tid >> 2, ak = (tid & 3) * 4;
    int bk = tid >> 4, bn = (tid & 15) * 4;
    int col = n0 + bn;
    int nsteps = KC >> 4;

    float4 va = *(const float4*)&A[(size_t)am * K + k0 + ak];
    float4 vb = make_float4(0.f, 0.f, 0.f, 0.f);
    if (col < N) vb = *(const float4*)&Bm[(size_t)(k0 + bk) * N + col];
    {
        const float* vp = (const float*)&va;
        const float* wp = (const float*)&vb;
#pragma unroll
        for (int j = 0; j < 4; j++) {
            Ah[0][am*24 + ak + j] = __float2half_rn(vp[j]);
            Bh[0][(bn + j)*24 + bk] = __float2half_rn(wp[j]);
        }
    }
    __syncthreads();

    for (int s = 0; s < nsteps; s++) {
        int cur = s & 1;
        if (s + 1 < nsteps) {
            int kb = k0 + (s + 1)*16;
            va = *(const float4*)&A[(size_t)am * K + kb + ak];
            vb = make_float4(0.f, 0.f, 0.f, 0.f);
            if (col < N) vb = *(const float4*)&Bm[(size_t)(kb + bk) * N + col];
        }

        uint32_t cb = cur * 3072;
        uint32_t a[4];
        ldm_x4(a, sAh + cb + (uint32_t)(mt*16 + a_row)*48 + a_k16);
#pragma unroll
        for (int nt = 0; nt < 4; nt++) {
            uint32_t bhf[2];
            ldm_x2(bhf, sBh + cb + (uint32_t)((nh + nt)*8 + w_row)*48 + w_k16);
            mma_f16(acc[nt], a, bhf);
        }

        if (s + 1 < nsteps) {
            int nx = cur ^ 1;
            const float* vp = (const float*)&va;
            const float* wp = (const float*)&vb;
#pragma unroll
            for (int j = 0; j < 4; j++) {
                Ah[nx][am*24 + ak + j] = __float2half_rn(vp[j]);
                Bh[nx][(bn + j)*24 + bk] = __float2half_rn(wp[j]);
            }
        }
        __syncthreads();
    }

    int s = blockIdx.y;
    int g = lane >> 2, c0 = (lane & 3) * 2;
#pragma unroll
    for (int nt = 0; nt < 4; nt++) {
#pragma unroll
        for (int half = 0; half < 2; half++) {
            int row = mt*16 + g + half*8;
            int ocol = n0 + (nh + nt)*8 + c0;
            if (ocol < N) {
                float* p = &g_part[((size_t)(s*64 + row)) * N + ocol];
                p[0] = acc[nt][half*2 + 0];
                p[1] = acc[nt][half*2 + 1];
            }
        }
    }
}

// ---------------- split-K reduce + bias + activation -----------------------
__global__ void gemm_reduce_kernel(const float* __restrict__ bias,
                                   int N, int nsplit, int relu, int stage)
{
    float* out = (stage == 0) ? g_fc1 : (stage == 1) ? g_fc2 : g_wb;
    int nv = N >> 2;
    int idx = blockIdx.x * 256 + threadIdx.x;
    if (idx >= 64 * nv) return;
    int m = idx / nv, f = idx - m * nv;
    float4 s = make_float4(0.f, 0.f, 0.f, 0.f);
    for (int sp = 0; sp < nsplit; sp++) {
        const float4* p = (const float4*)&g_part[(size_t)(sp*64 + m) * N];
        float4 v = p[f];
        s.x += v.x; s.y += v.y; s.z += v.z; s.w += v.w;
    }
    float4 bv = ((const float4*)bias)[f];
    s.x += bv.x; s.y += bv.y; s.z += bv.z; s.w += bv.w;
    if (relu) {
        s.x = fmaxf(s.x, 0.f); s.y = fmaxf(s.y, 0.f);
        s.z = fmaxf(s.z, 0.f); s.w = fmaxf(s.w, 0.f);
    }
    ((float4*)out)[(size_t)m * nv + f] = s;
}

// ---------------- dynamic per-tile conv via fp16 mma, halo-A, W ping-pong --
// grid (2,8,64). block 256, 2 blocks/SM.
// smem: A @0 (43520), W bufs @43520 (2 x 4096 = 8192), bias @51712 (128).
// Total 51840.
__global__ __launch_bounds__(256, 2) void dynconv_hmma_kernel(float* __restrict__ out)
{
    extern __shared__ char smem[];
    const uint32_t AS = 0, WB = 43520, BS = 51712;
    uint32_t sb = smem_u32(smem);
    int r = blockIdx.z;
    int b = r >> 4, t = r & 15;
    int ti = t >> 2, tj = t & 3;
    int y0 = ti*64 + blockIdx.y * 8;
    int x0 = tj*64 + blockIdx.x * 32;
    int tid = threadIdx.x, w = tid >> 5, lane = tid & 31;

    if (tid < 32) *(float*)(smem + BS + tid*4) = g_wb[(size_t)r*18464 + 18432 + tid];

    // build swizzled halo A once (fp16)
    for (int i = tid; i < 2720; i += 256) {
        int hp = i >> 3, ch8 = i & 7;
        int hy = hp / 34, hx = hp - hy*34;
        int gy = y0 - 1 + hy, gx = x0 - 1 + hx;
        uint4 vh = {0,0,0,0};
        if ((unsigned)gy < 256u && (unsigned)gx < 256u)
            vh = *(const uint4*)(g_fh + ((size_t)(b*256 + gy)*256 + gx)*64 + ch8*8);
        *(uint4*)(smem + AS + SWZ(hp, ch8)) = vh;
    }
    // preload W tap 0 into buf 0
    const __half* dwh = g_dwh + (size_t)r*9*2048;
    int wr = tid >> 3, wc = tid & 7;
    *(uint4*)(smem + WB + SWZ(wr, wc)) = *(const uint4*)(dwh + wr*64 + wc*8);
    __syncthreads();

    float acc[2][4][4];
#pragma unroll
    for (int mt = 0; mt < 2; mt++)
#pragma unroll
        for (int nt = 0; nt < 4; nt++)
#pragma unroll
            for (int e = 0; e < 4; e++) acc[mt][nt][e] = 0.f;

    int a_row = lane & 15, a_cs = lane >> 4;
    int w_row = lane & 7,  w_cs = (lane >> 3) & 1;

    for (int tap = 0; tap < 9; tap++) {
        int dy = tap / 3 - 1, dx = tap % 3 - 1;
        int buf = tap & 1;
        uint32_t wb = WB + buf*4096;

        uint4 ph;
        if (tap < 8)
            ph = *(const uint4*)(dwh + (tap + 1)*2048 + wr*64 + wc*8);

        int rb = (w + dy + 1)*34 + dx + 1;
#pragma unroll
        for (int ks = 0; ks < 4; ks++) {
            uint32_t a[2][4];
#pragma unroll
            for (int mt = 0; mt < 2; mt++) {
                int ar = rb + mt*16 + a_row;
                ldm_x4(a[mt], sb + AS + SWZ(ar, ks*2 + a_cs));
            }
#pragma unroll
            for (int nt = 0; nt < 4; nt++) {
                uint32_t wh[2];
                ldm_x2(wh, sb + wb + SWZ(nt*8 + w_row, ks*2 + w_cs));
                mma_f16(acc[0][nt], a[0], wh);
                mma_f16(acc[1][nt], a[1], wh);
            }
        }
        if (tap < 8) {
            uint32_t nb = WB + (buf ^ 1)*4096;
            *(uint4*)(smem + nb + SWZ(wr, wc)) = ph;
        }
        __syncthreads();
    }

    const float* bsm = (const float*)(smem + BS);
    int g = lane >> 2, c0 = (lane & 3) * 2;
    int y = y0 + w;
#pragma unroll
    for (int mt = 0; mt < 2; mt++) {
#pragma unroll
        for (int half = 0; half < 2; half++) {
            int x = x0 + mt*16 + g + half*8;
            int pix = y*256 + x;
#pragma unroll
            for (int nt = 0; nt < 4; nt++) {
                int oc = nt*8 + c0;
                float v0 = acc[mt][nt][half*2 + 0] + bsm[oc];
                float v1 = acc[mt][nt][half*2 + 1] + bsm[oc + 1];
                out[(((size_t)(b*96 + 64 + oc)) << 16) + pix] = v0;
                out[(((size_t)(b*96 + 64 + oc + 1)) << 16) + pix] = v1;
            }
        }
    }
}

// ---------------- launch ---------------------------------------------------
extern "C" void kernel_launch(void* const* d_in, const int* in_sizes, int n_in,
                              void* d_out, int out_size)
{
    const float* feature = (const float*)d_in[0];
    const float* rw1 = (const float*)d_in[1];
    const float* rb1 = (const float*)d_in[2];
    const float* rw2 = (const float*)d_in[3];
    const float* rb2 = (const float*)d_in[4];
    const float* fw1 = (const float*)d_in[5];
    const float* fb1 = (const float*)d_in[6];
    const float* fw2 = (const float*)d_in[7];
    const float* fb2 = (const float*)d_in[8];
    const float* fw3 = (const float*)d_in[9];
    const float* fb3 = (const float*)d_in[10];
    float* out = (float*)d_out;

    const int CONV1_SMEM = 62464;
    const int DYN_SMEM = 51840;
    cudaFuncSetAttribute(conv1_hmma_kernel,
                         cudaFuncAttributeMaxDynamicSharedMemorySize, CONV1_SMEM);
    cudaFuncSetAttribute(dynconv_hmma_kernel,
                         cudaFuncAttributeMaxDynamicSharedMemorySize, DYN_SMEM);

    tohwc_kernel<<<4096, 256>>>(feature, out);
    wprep_kernel<<<144, 256>>>(rw1);
    conv1_hmma_kernel<<<dim3(8, 32, 4), 256, CONV1_SMEM>>>(rb1, rw2);
    conv2_sum_kernel<<<1024, 256>>>(rb2);
    pool_kernel<<<64, 256>>>();

    // FC1: 64x1024 @ 1024x2048, split-K 16 (fp16 ping-pong)
    gemm_hmma_kernel<<<dim3(32, 16), 256>>>(fw1, 1024, 2048, 64, 0);
    gemm_reduce_kernel<<<(64*512 + 255)/256, 256>>>(fb1, 2048, 16, 1, 0);
    // FC2: 64x2048 @ 2048x2048, split-K 16 (fp16 ping-pong)
    gemm_hmma_kernel<<<dim3(32, 16), 256>>>(fw2, 2048, 2048, 128, 1);
    gemm_reduce_kernel<<<(64*512 + 255)/256, 256>>>(fb2, 2048, 16, 1, 1);
    // FC3: 64x2048 @ 2048x18464, split-K 4 (fp16 ping-pong)
    gemm_hmma_kernel<<<dim3(289, 4), 256>>>(fw3, 2048, 18464, 512, 2);
    gemm_reduce_kernel<<<(64*4616 + 255)/256, 256>>>(fb3, 18464, 4, 0, 2);

    dynwprep_kernel<<<512, 256>>>();
    dynconv_hmma_kernel<<<dim3(2, 8, 64), 256, DYN_SMEM>>>(out);
}

// round 15
// speedup vs baseline: 4.3047x; 1.0079x over previous
#include <cuda_runtime.h>
#include <cuda_fp16.h>
#include <cstdint>
#include <math.h>

// Problem constants
// B=4, C=64, H=W=256, N_SPLIT=4 (T=16), RED_FC=32, OUT_NC=32, K=3, FMN1=FMN2=2048
// wsize = 32*64*9 = 18432, wb row = 18464

// ---------------- scratch (device globals; no runtime allocation) ----------
__device__ float g_u[9*4*65536];               // conv2 tap projections
__device__ float g_adap[4*65536];              // tanh(conv2)
__device__ float g_gram[64*1024];              // pooled grams
__device__ float g_fc1[64*2048];
__device__ float g_fc2[64*2048];
__device__ float g_wb[64*18464];               // dynamic weights + bias
__device__ float g_part[9453568];              // split-K partials
__device__ __half g_fh[4*256*256*64];          // feature NHWC fp16
__device__ __half g_w1h[9*64*64];              // rw1 [tap][oc][ic] fp16
__device__ __half g_dwh[64*9*32*64];           // dyn W [r][tap][oc][ic] fp16

// row-major 128B rows with XOR-16B swizzle (bank-conflict-free ldmatrix)
#define SWZ(row, chunk) ((uint32_t)(row)*128u + (((uint32_t)((chunk) ^ ((row) & 7))) * 16u))

// ---------------- mma.sync helpers (sm_80+ path, works on plain sm_103) ----
__device__ __forceinline__ uint32_t smem_u32(const void* p) {
    uint32_t a;
    asm("{ .reg .u64 t; cvta.to.shared.u64 t, %1; cvt.u32.u64 %0, t; }" : "=r"(a) : "l"(p));
    return a;
}
__device__ __forceinline__ void ldm_x4(uint32_t* r, uint32_t addr) {
    asm volatile("ldmatrix.sync.aligned.m8n8.x4.shared.b16 {%0,%1,%2,%3}, [%4];"
        : "=r"(r[0]), "=r"(r[1]), "=r"(r[2]), "=r"(r[3]) : "r"(addr));
}
__device__ __forceinline__ void mma_f16_p(float* d, const uint32_t* a,
                                          uint32_t b0, uint32_t b1) {
    asm volatile(
        "mma.sync.aligned.m16n8k16.row.col.f32.f16.f16.f32 "
        "{%0,%1,%2,%3}, {%4,%5,%6,%7}, {%8,%9}, {%0,%1,%2,%3};"
        : "+f"(d[0]), "+f"(d[1]), "+f"(d[2]), "+f"(d[3])
        : "r"(a[0]), "r"(a[1]), "r"(a[2]), "r"(a[3]), "r"(b0), "r"(b1));
}

// ---------------- NCHW fp32 -> NHWC fp16 (+ fused feature copy) ------------
__global__ __launch_bounds__(256) void tohwc_kernel(const float* __restrict__ feat,
                                                    float* __restrict__ out)
{
    __shared__ float s[64][65];
    int bx = blockIdx.x;
    int b = bx >> 10, grp = bx & 1023;
    int pix0 = grp * 64;
    int tid = threadIdx.x;
#pragma unroll
    for (int i = 0; i < 16; i++) {
        int idx = i * 256 + tid;
        int ic = idx >> 6, px = idx & 63;
        float v = feat[(((size_t)(b*64 + ic)) << 16) + pix0 + px];
        s[ic][px] = v;
        out[(((size_t)(b*96 + ic)) << 16) + pix0 + px] = v;   // fused passthrough
    }
    __syncthreads();
#pragma unroll
    for (int i = 0; i < 16; i++) {
        int idx = i * 256 + tid;
        int px = idx >> 6, ic = idx & 63;
        g_fh[((size_t)b*65536 + pix0 + px) * 64 + ic] = __float2half_rn(s[ic][px]);
    }
}

// ---------------- rw1 -> [tap][oc][ic] fp16 --------------------------------
__global__ void wprep_kernel(const float* __restrict__ rw1)
{
    int idx = blockIdx.x * 256 + threadIdx.x;
    if (idx >= 9*64*64) return;
    int tap = idx >> 12, rem = idx & 4095;
    int oc = rem >> 6, ic = rem & 63;
    g_w1h[idx] = __float2half_rn(rw1[(oc*64 + ic)*9 + tap]);
}

// ---------------- g_wb -> [r][tap][oc][ic] fp16 ----------------------------
__global__ void dynwprep_kernel()
{
    int idx = blockIdx.x * 256 + threadIdx.x;   // 64 * 2048
    if (idx >= 64*2048) return;
    int r = idx >> 11, rem = idx & 2047;        // rem = oc*64+ic
    const float* src = g_wb + (size_t)r*18464 + rem*9;
#pragma unroll
    for (int tap = 0; tap < 9; tap++)
        g_dwh[((size_t)(r*9 + tap))*2048 + rem] = __float2half_rn(src[tap]);
}

// ---------------- conv1 via fp16 mma, halo-A, W ping-pong, conv2 proj ------
// grid (8,32,4). block 256 (8 warps), 2 blocks/SM. 1 sync per tap.
// smem: A @0 (43520), W bufs @43520 (2 x 8192 = 16384),
//       bias @59904 (256), w2 @60160 (2304). Total 62464.
__global__ __launch_bounds__(256, 2) void conv1_hmma_kernel(
    const float* __restrict__ rb1, const float* __restrict__ rw2)
{
    extern __shared__ char smem[];
    const uint32_t AS = 0, WB = 43520, BS = 59904, W2 = 60160;
    uint32_t sb = smem_u32(smem);
    int b = blockIdx.z;
    int y0 = blockIdx.y * 8, x0 = blockIdx.x * 32;
    int tid = threadIdx.x, w = tid >> 5, lane = tid & 31;

    if (tid < 64) *(float*)(smem + BS + tid*4) = rb1[tid];
    for (int i = tid; i < 576; i += 256) {
        int tap = i >> 6, ic = i & 63;
        *(float*)(smem + W2 + i*4) = rw2[ic*9 + tap];
    }

    // build swizzled halo A once: 340 rows (10x34 px) x 64 ic fp16
    for (int i = tid; i < 2720; i += 256) {
        int hp = i >> 3, ch8 = i & 7;
        int hy = hp / 34, hx = hp - hy*34;
        int gy = y0 - 1 + hy, gx = x0 - 1 + hx;
        uint4 vh = {0,0,0,0};
        if ((unsigned)gy < 256u && (unsigned)gx < 256u)
            vh = *(const uint4*)(g_fh + ((size_t)(b*256 + gy)*256 + gx)*64 + ch8*8);
        *(uint4*)(smem + AS + SWZ(hp, ch8)) = vh;
    }
    // preload W tap 0 into buf 0
    int wr1 = tid >> 3, wc1 = tid & 7;        // rows 0..31
    int wr2 = wr1 + 32, wc2 = wc1;            // rows 32..63
    {
        *(uint4*)(smem + WB + SWZ(wr1, wc1)) = *(const uint4*)(g_w1h + wr1*64 + wc1*8);
        *(uint4*)(smem + WB + SWZ(wr2, wc2)) = *(const uint4*)(g_w1h + wr2*64 + wc2*8);
    }
    __syncthreads();

    float acc[2][8][4];
#pragma unroll
    for (int mt = 0; mt < 2; mt++)
#pragma unroll
        for (int nt = 0; nt < 8; nt++)
#pragma unroll
            for (int e = 0; e < 4; e++) acc[mt][nt][e] = 0.f;

    int a_row = lane & 15, a_cs = lane >> 4;
    int w_row16 = lane & 15, w_cs16 = lane >> 4;   // 16-row x4 W fragments

    for (int tap = 0; tap < 9; tap++) {
        int dy = tap / 3 - 1, dx = tap % 3 - 1;
        int buf = tap & 1;
        uint32_t wb = WB + buf*8192;

        uint4 ph1, ph2;
        if (tap < 8) {
            size_t gb = (size_t)(tap + 1)*4096;
            ph1 = *(const uint4*)(g_w1h + gb + wr1*64 + wc1*8);
            ph2 = *(const uint4*)(g_w1h + gb + wr2*64 + wc2*8);
        }

        int rb = (w + dy + 1)*34 + dx + 1;
#pragma unroll
        for (int ks = 0; ks < 4; ks++) {
            uint32_t a[2][4];
#pragma unroll
            for (int mt = 0; mt < 2; mt++) {
                int ar = rb + mt*16 + a_row;
                ldm_x4(a[mt], sb + AS + SWZ(ar, ks*2 + a_cs));
            }
#pragma unroll
            for (int p = 0; p < 4; p++) {        // pairs of n8 tiles
                uint32_t wf[4];
                ldm_x4(wf, sb + wb + SWZ(p*16 + w_row16, ks*2 + w_cs16));
                mma_f16_p(acc[0][2*p],     a[0], wf[0], wf[2]);
                mma_f16_p(acc[1][2*p],     a[1], wf[0], wf[2]);
                mma_f16_p(acc[0][2*p + 1], a[0], wf[1], wf[3]);
                mma_f16_p(acc[1][2*p + 1], a[1], wf[1], wf[3]);
            }
        }
        if (tap < 8) {
            uint32_t nb = WB + (buf ^ 1)*8192;
            *(uint4*)(smem + nb + SWZ(wr1, wc1)) = ph1;
            *(uint4*)(smem + nb + SWZ(wr2, wc2)) = ph2;
        }
        __syncthreads();
    }

    // epilogue: bias + leaky relu, then 9 tap-dot projections (quad reduce)
    const float* bs = (const float*)(smem + BS);
    const float* w2 = (const float*)(smem + W2);
    int g = lane >> 2, c0 = (lane & 3) * 2;
    int y = y0 + w;
#pragma unroll
    for (int mt = 0; mt < 2; mt++) {
#pragma unroll
        for (int half = 0; half < 2; half++) {
            int x = x0 + mt*16 + g + half*8;
            float part[9];
#pragma unroll
            for (int t = 0; t < 9; t++) part[t] = 0.f;
#pragma unroll
            for (int nt = 0; nt < 8; nt++) {
                int oc = nt*8 + c0;
                float v0 = acc[mt][nt][half*2 + 0] + bs[oc];
                float v1 = acc[mt][nt][half*2 + 1] + bs[oc + 1];
                v0 = (v0 >= 0.f) ? v0 : 0.2f * v0;
                v1 = (v1 >= 0.f) ? v1 : 0.2f * v1;
#pragma unroll
                for (int t = 0; t < 9; t++)
                    part[t] += v0 * w2[t*64 + oc] + v1 * w2[t*64 + oc + 1];
            }
#pragma unroll
            for (int t = 0; t < 9; t++) {
                part[t] += __shfl_xor_sync(0xFFFFFFFFu, part[t], 1);
                part[t] += __shfl_xor_sync(0xFFFFFFFFu, part[t], 2);
            }
            if ((lane & 3) == 0) {
                int pix = y*256 + x;
#pragma unroll
                for (int t = 0; t < 9; t++)
                    g_u[t*262144 + b*65536 + pix] = part[t];
            }
        }
    }
}

// ---------------- conv2 sum: adap = tanh(sum of shifted taps + bias) -------
__global__ __launch_bounds__(256) void conv2_sum_kernel(const float* __restrict__ rb2)
{
    int P = blockIdx.x * 256 + threadIdx.x;
    int b = P >> 16, pix = P & 65535;
    int y = pix >> 8, x = pix & 255;
    float s = 0.f;
#pragma unroll
    for (int t = 0; t < 9; t++) {
        int yy = y + t/3 - 1, xx = x + t%3 - 1;
        if ((unsigned)yy < 256u && (unsigned)xx < 256u)
            s += g_u[t*262144 + b*65536 + yy*256 + xx];
    }
    g_adap[(size_t)b*65536 + pix] = tanhf(s + rb2[0]);
}

// ---------------- adaptive pool per tile -> gram ---------------------------
__global__ void pool_kernel()
{
    __shared__ float win[66][67];
    int r = blockIdx.x;
    int b = r >> 4, t = r & 15;
    int ti = t >> 2, tj = t & 3;
    int tid = threadIdx.x;
    for (int i = tid; i < 66*66; i += 256) {
        int h = i / 66, w = i % 66;
        int gy = ti*64 - 1 + h, gx = tj*64 - 1 + w;
        float v = 0.f;
        if ((unsigned)gy < 256u && (unsigned)gx < 256u)
            v = g_adap[((size_t)b*256 + gy) * 256 + gx];
        win[h][w] = v;
    }
    __syncthreads();
    for (int i = tid; i < 1024; i += 256) {
        int p = i >> 5, q = i & 31;
        int sp = (p*66) >> 5, ep = ((p+1)*66 + 31) >> 5;
        int sq = (q*66) >> 5, eq = ((q+1)*66 + 31) >> 5;
        float s = 0.f;
        for (int h = sp; h < ep; h++)
            for (int w = sq; w < eq; w++)
                s += win[h][w];
        g_gram[r*1024 + i] = s / (float)((ep - sp) * (eq - sq));
    }
}

// ---------------- fp16 split-K FC GEMM (ping-pong): part[s] = A @ B --------
// A fp16, B fp16. 1 barrier per k16-step. B fragments via paired ldm_x4.
__global__ __launch_bounds__(256) void gemm_hmma_kernel(
    const float* __restrict__ Bm, int K, int N, int KC, int stage)
{
    const float* __restrict__ A = (stage == 0) ? g_gram : (stage == 1) ? g_fc1 : g_fc2;

    __shared__ __half Ah[2][1536];   // [buf][m*24 + k]
    __shared__ __half Bh[2][1536];   // [buf][n*24 + k]

    int n0 = blockIdx.x * 64;
    int k0 = blockIdx.y * KC;
    int tid = threadIdx.x, w = tid >> 5, lane = tid & 31;
    int mt = w >> 1;
    int nh = (w & 1) * 4;            // n8-tile base: 0 or 4

    float acc[4][4];
#pragma unroll
    for (int nt = 0; nt < 4; nt++)
#pragma unroll
        for (int e = 0; e < 4; e++) acc[nt][e] = 0.f;

    uint32_t a_row = lane & 15, a_k16 = (lane >> 4) * 16;
    uint32_t w_row16 = lane & 15, w_k16 = (lane >> 4) * 16;
    uint32_t sAh = smem_u32(Ah);
    uint32_t sBh = smem_u32(Bh);

    int am = tid >> 2, ak = (tid & 3) * 4;
    int bk = tid >> 4, bn = (tid & 15) * 4;
    int col = n0 + bn;
    int nsteps = KC >> 4;

    float4 va = *(const float4*)&A[(size_t)am * K + k0 + ak];
    float4 vb = make_float4(0.f, 0.f, 0.f, 0.f);
    if (col < N) vb = *(const float4*)&Bm[(size_t)(k0 + bk) * N + col];
    {
        const float* vp = (const float*)&va;
        const float* wp = (const float*)&vb;
#pragma unroll
        for (int j = 0; j < 4; j++) {
            Ah[0][am*24 + ak + j] = __float2half_rn(vp[j]);
            Bh[0][(bn + j)*24 + bk] = __float2half_rn(wp[j]);
        }
    }
    __syncthreads();

    for (int s = 0; s < nsteps; s++) {
        int cur = s & 1;
        if (s + 1 < nsteps) {
            int kb = k0 + (s + 1)*16;
            va = *(const float4*)&A[(size_t)am * K + kb + ak];
            vb = make_float4(0.f, 0.f, 0.f, 0.f);
            if (col < N) vb = *(const float4*)&Bm[(size_t)(kb + bk) * N + col];
        }

        uint32_t cb = cur * 3072;
        uint32_t a[4];
        ldm_x4(a, sAh + cb + (uint32_t)(mt*16 + a_row)*48 + a_k16);
#pragma unroll
        for (int p = 0; p < 2; p++) {           // pairs of n8 tiles
            uint32_t wf[4];
            uint32_t base_row = (nh + 2*p)*8 + w_row16;
            ldm_x4(wf, sBh + cb + base_row*48 + w_k16);
            mma_f16_p(acc[2*p],     a, wf[0], wf[2]);
            mma_f16_p(acc[2*p + 1], a, wf[1], wf[3]);
        }

        if (s + 1 < nsteps) {
            int nx = cur ^ 1;
            const float* vp = (const float*)&va;
            const float* wp = (const float*)&vb;
#pragma unroll
            for (int j = 0; j < 4; j++) {
                Ah[nx][am*24 + ak + j] = __float2half_rn(vp[j]);
                Bh[nx][(bn + j)*24 + bk] = __float2half_rn(wp[j]);
            }
        }
        __syncthreads();
    }

    int s = blockIdx.y;
    int g = lane >> 2, c0 = (lane & 3) * 2;
#pragma unroll
    for (int nt = 0; nt < 4; nt++) {
#pragma unroll
        for (int half = 0; half < 2; half++) {
            int row = mt*16 + g + half*8;
            int ocol = n0 + (nh + nt)*8 + c0;
            if (ocol < N) {
                float* p = &g_part[((size_t)(s*64 + row)) * N + ocol];
                p[0] = acc[nt][half*2 + 0];
                p[1] = acc[nt][half*2 + 1];
            }
        }
    }
}

// ---------------- split-K reduce + bias + activation -----------------------
__global__ void gemm_reduce_kernel(const float* __restrict__ bias,
                                   int N, int nsplit, int relu, int stage)
{
    float* out = (stage == 0) ? g_fc1 : (stage == 1) ? g_fc2 : g_wb;
    int nv = N >> 2;
    int idx = blockIdx.x * 256 + threadIdx.x;
    if (idx >= 64 * nv) return;
    int m = idx / nv, f = idx - m * nv;
    float4 s = make_float4(0.f, 0.f, 0.f, 0.f);
    for (int sp = 0; sp < nsplit; sp++) {
        const float4* p = (const float4*)&g_part[(size_t)(sp*64 + m) * N];
        float4 v = p[f];
        s.x += v.x; s.y += v.y; s.z += v.z; s.w += v.w;
    }
    float4 bv = ((const float4*)bias)[f];
    s.x += bv.x; s.y += bv.y; s.z += bv.z; s.w += bv.w;
    if (relu) {
        s.x = fmaxf(s.x, 0.f); s.y = fmaxf(s.y, 0.f);
        s.z = fmaxf(s.z, 0.f); s.w = fmaxf(s.w, 0.f);
    }
    ((float4*)out)[(size_t)m * nv + f] = s;
}

// ---------------- dynamic per-tile conv via fp16 mma, halo-A, W ping-pong --
// grid (2,8,64). block 256, 2 blocks/SM.
// smem: A @0 (43520), W bufs @43520 (2 x 4096 = 8192), bias @51712 (128).
// Total 51840.
__global__ __launch_bounds__(256, 2) void dynconv_hmma_kernel(float* __restrict__ out)
{
    extern __shared__ char smem[];
    const uint32_t AS = 0, WB = 43520, BS = 51712;
    uint32_t sb = smem_u32(smem);
    int r = blockIdx.z;
    int b = r >> 4, t = r & 15;
    int ti = t >> 2, tj = t & 3;
    int y0 = ti*64 + blockIdx.y * 8;
    int x0 = tj*64 + blockIdx.x * 32;
    int tid = threadIdx.x, w = tid >> 5, lane = tid & 31;

    if (tid < 32) *(float*)(smem + BS + tid*4) = g_wb[(size_t)r*18464 + 18432 + tid];

    // build swizzled halo A once (fp16)
    for (int i = tid; i < 2720; i += 256) {
        int hp = i >> 3, ch8 = i & 7;
        int hy = hp / 34, hx = hp - hy*34;
        int gy = y0 - 1 + hy, gx = x0 - 1 + hx;
        uint4 vh = {0,0,0,0};
        if ((unsigned)gy < 256u && (unsigned)gx < 256u)
            vh = *(const uint4*)(g_fh + ((size_t)(b*256 + gy)*256 + gx)*64 + ch8*8);
        *(uint4*)(smem + AS + SWZ(hp, ch8)) = vh;
    }
    // preload W tap 0 into buf 0
    const __half* dwh = g_dwh + (size_t)r*9*2048;
    int wr = tid >> 3, wc = tid & 7;
    *(uint4*)(smem + WB + SWZ(wr, wc)) = *(const uint4*)(dwh + wr*64 + wc*8);
    __syncthreads();

    float acc[2][4][4];
#pragma unroll
    for (int mt = 0; mt < 2; mt++)
#pragma unroll
        for (int nt = 0; nt < 4; nt++)
#pragma unroll
            for (int e = 0; e < 4; e++) acc[mt][nt][e] = 0.f;

    int a_row = lane & 15, a_cs = lane >> 4;
    int w_row16 = lane & 15, w_cs16 = lane >> 4;

    for (int tap = 0; tap < 9; tap++) {
        int dy = tap / 3 - 1, dx = tap % 3 - 1;
        int buf = tap & 1;
        uint32_t wb = WB + buf*4096;

        uint4 ph;
        if (tap < 8)
            ph = *(const uint4*)(dwh + (tap + 1)*2048 + wr*64 + wc*8);

        int rb = (w + dy + 1)*34 + dx + 1;
#pragma unroll
        for (int ks = 0; ks < 4; ks++) {
            uint32_t a[2][4];
#pragma unroll
            for (int mt = 0; mt < 2; mt++) {
                int ar = rb + mt*16 + a_row;
                ldm_x4(a[mt], sb + AS + SWZ(ar, ks*2 + a_cs));
            }
#pragma unroll
            for (int p = 0; p < 2; p++) {        // pairs of n8 tiles
                uint32_t wf[4];
                ldm_x4(wf, sb + wb + SWZ(p*16 + w_row16, ks*2 + w_cs16));
                mma_f16_p(acc[0][2*p],     a[0], wf[0], wf[2]);
                mma_f16_p(acc[1][2*p],     a[1], wf[0], wf[2]);
                mma_f16_p(acc[0][2*p + 1], a[0], wf[1], wf[3]);
                mma_f16_p(acc[1][2*p + 1], a[1], wf[1], wf[3]);
            }
        }
        if (tap < 8) {
            uint32_t nb = WB + (buf ^ 1)*4096;
            *(uint4*)(smem + nb + SWZ(wr, wc)) = ph;
        }
        __syncthreads();
    }

    const float* bsm = (const float*)(smem + BS);
    int g = lane >> 2, c0 = (lane & 3) * 2;
    int y = y0 + w;
#pragma unroll
    for (int mt = 0; mt < 2; mt++) {
#pragma unroll
        for (int half = 0; half < 2; half++) {
            int x = x0 + mt*16 + g + half*8;
            int pix = y*256 + x;
#pragma unroll
            for (int nt = 0; nt < 4; nt++) {
                int oc = nt*8 + c0;
                float v0 = acc[mt][nt][half*2 + 0] + bsm[oc];
                float v1 = acc[mt][nt][half*2 + 1] + bsm[oc + 1];
                out[(((size_t)(b*96 + 64 + oc)) << 16) + pix] = v0;
                out[(((size_t)(b*96 + 64 + oc + 1)) << 16) + pix] = v1;
            }
        }
    }
}

// ---------------- launch ---------------------------------------------------
extern "C" void kernel_launch(void* const* d_in, const int* in_sizes, int n_in,
                              void* d_out, int out_size)
{
    const float* feature = (const float*)d_in[0];
    const float* rw1 = (const float*)d_in[1];
    const float* rb1 = (const float*)d_in[2];
    const float* rw2 = (const float*)d_in[3];
    const float* rb2 = (const float*)d_in[4];
    const float* fw1 = (const float*)d_in[5];
    const float* fb1 = (const float*)d_in[6];
    const float* fw2 = (const float*)d_in[7];
    const float* fb2 = (const float*)d_in[8];
    const float* fw3 = (const float*)d_in[9];
    const float* fb3 = (const float*)d_in[10];
    float* out = (float*)d_out;

    const int CONV1_SMEM = 62464;
    const int DYN_SMEM = 51840;
    cudaFuncSetAttribute(conv1_hmma_kernel,
                         cudaFuncAttributeMaxDynamicSharedMemorySize, CONV1_SMEM);
    cudaFuncSetAttribute(dynconv_hmma_kernel,
                         cudaFuncAttributeMaxDynamicSharedMemorySize, DYN_SMEM);

    tohwc_kernel<<<4096, 256>>>(feature, out);
    wprep_kernel<<<144, 256>>>(rw1);
    conv1_hmma_kernel<<<dim3(8, 32, 4), 256, CONV1_SMEM>>>(rb1, rw2);
    conv2_sum_kernel<<<1024, 256>>>(rb2);
    pool_kernel<<<64, 256>>>();

    // FC1: 64x1024 @ 1024x2048, split-K 16 (fp16 ping-pong)
    gemm_hmma_kernel<<<dim3(32, 16), 256>>>(fw1, 1024, 2048, 64, 0);
    gemm_reduce_kernel<<<(64*512 + 255)/256, 256>>>(fb1, 2048, 16, 1, 0);
    // FC2: 64x2048 @ 2048x2048, split-K 16 (fp16 ping-pong)
    gemm_hmma_kernel<<<dim3(32, 16), 256>>>(fw2, 2048, 2048, 128, 1);
    gemm_reduce_kernel<<<(64*512 + 255)/256, 256>>>(fb2, 2048, 16, 1, 1);
    // FC3: 64x2048 @ 2048x18464, split-K 2 (fp16 ping-pong)
    gemm_hmma_kernel<<<dim3(289, 2), 256>>>(fw3, 2048, 18464, 1024, 2);
    gemm_reduce_kernel<<<(64*4616 + 255)/256, 256>>>(fb3, 18464, 2, 0, 2);

    dynwprep_kernel<<<512, 256>>>();
    dynconv_hmma_kernel<<<dim3(2, 8, 64), 256, DYN_SMEM>>>(out);
}